// round 5
// baseline (speedup 1.0000x reference)
#include <cuda_runtime.h>
#include <math.h>

// FFT size N = 2^25 = FA * FB * FC, position n = a + FA*b + AB*c
#define LN   25
#define NF   (1 << LN)
#define LA   11
#define FA   (1 << LA)          // 2048
#define LB   7
#define FB   (1 << LB)          // 128
#define LC   7
#define FC   (1 << LC)          // 128
#define AB   (FA * FB)          // 262144
#define GT   32                 // tile width (consecutive fast-dim elements)
#define NTHR 256

#define MTOT (1 << 24)          // problem size B*N = 2^24
#define NBLK (AB / GT)          // 8192 blocks for K1/K5

// 256 MB spectral work buffer + twiddle tables + partials (no runtime allocation)
__device__ float2 g_Z[NF];
__device__ float2 g_W16384[16384];  // W_16384^m
__device__ float2 g_W2048[1024];    // W_2048^m, m < 1024
__device__ float2 g_W128[64];       // W_128^m,  m < 64
__device__ float2 g_Wlo[4096];      // W_N^j,        j < 4096
__device__ float2 g_Whi[8192];      // W_N^{4096 j}, j < 8192
__device__ double g_data[NBLK];
__device__ double g_phys[NBLK];

__device__ __forceinline__ float2 cmul(float2 a, float2 b) {
    return make_float2(fmaf(a.x, b.x, -a.y * b.y), fmaf(a.x, b.y, a.y * b.x));
}

// ---------------------------------------------------------------- twiddle init
__global__ void k_tw() {
    int idx = blockIdx.x * 256 + threadIdx.x;   // 64 blocks * 256 = 16384
    const double P2 = 6.283185307179586476925286766559;
    if (idx < 16384) { double a = -P2 * idx / 16384.0;    g_W16384[idx] = make_float2((float)cos(a), (float)sin(a)); }
    if (idx < 8192)  { double a = -P2 * idx / 8192.0;     g_Whi[idx]    = make_float2((float)cos(a), (float)sin(a)); }
    if (idx < 4096)  { double a = -P2 * idx / (double)NF; g_Wlo[idx]    = make_float2((float)cos(a), (float)sin(a)); }
    if (idx < 1024)  { double a = -P2 * idx / 2048.0;     g_W2048[idx]  = make_float2((float)cos(a), (float)sin(a)); }
    if (idx < 64)    { double a = -P2 * idx / 128.0;      g_W128[idx]   = make_float2((float)cos(a), (float)sin(a)); }
}

// ------------------------------------------------- in-smem radix-2 DIF helper
// Row FFT of length F=1<<LF at element stride `stride`; NT threads (id tt) per
// row; all block threads must call this (uniform __syncthreads).
// sgn=+1: forward DFT; sgn=-1: unnormalized inverse. Natural-order output.
__device__ __forceinline__ void fft_sm(float2* d, int stride, int LF, int NT, int tt,
                                       const float2* __restrict__ tw, float sgn) {
    const int F = 1 << LF;
    for (int ls = LF - 1; ls >= 0; ls--) {
        const int s = 1 << ls;
#pragma unroll 4
        for (int q = tt; q < (F >> 1); q += NT) {
            int j  = q & (s - 1);
            int i0 = ((q >> ls) << (ls + 1)) + j;
            int i1 = i0 + s;
            float2 x0 = d[i0 * stride], x1 = d[i1 * stride];
            float2 lo = make_float2(x0.x + x1.x, x0.y + x1.y);
            float2 hi = make_float2(x0.x - x1.x, x0.y - x1.y);
            float2 w  = tw[j << (LF - 1 - ls)];
            w.y *= sgn;
            d[i0 * stride] = lo;
            d[i1 * stride] = cmul(hi, w);
        }
        __syncthreads();
    }
#pragma unroll 4
    for (int i = tt; i < F; i += NT) {
        int r = (int)(__brev((unsigned)i) >> (32 - LF));
        if (r > i) { float2 t0 = d[i * stride]; d[i * stride] = d[r * stride]; d[r * stride] = t0; }
    }
    __syncthreads();
}

// ------------------------------------- K1: pack Z = du + i*b, FFT over c, data loss
__global__ __launch_bounds__(NTHR)
void k1_pack_fft(const float* __restrict__ up, const float* __restrict__ utr) {
    __shared__ float2 tile[GT][FC + 1];
    __shared__ double red[NTHR];
    const int t   = threadIdx.x;
    const int ab0 = blockIdx.x * GT;

    float acc = 0.f;
    for (int i = t; i < GT * FC; i += NTHR) {
        int c = i >> 5;             // i / GT
        int g = i & (GT - 1);
        int n = ab0 + g + AB * c;
        float du = 0.f, bw = 0.f;
        if (n < MTOT) {
            float uv = __ldg(up + n);
            float d  = uv - __ldg(utr + n);
            acc = fmaf(d, d, acc);
            if (n < MTOT - 1) {
                du = __ldg(up + n + 1) - uv;
                // EXACT replica of the reference fp32 weights (incl. cancellation noise):
                // b[n] = fl(sqrt(n+1)) - fl(sqrt(n)), IEEE round-to-nearest
                bw = __fsqrt_rn((float)(n + 1)) - __fsqrt_rn((float)n);
            }
        }
        tile[g][c] = make_float2(du, bw);
    }
    __syncthreads();

    fft_sm(&tile[t >> 3][0], 1, LC, 8, t & 7, g_W128, 1.f);

    for (int i = t; i < GT * FC; i += NTHR) {
        int c = i >> 5;
        int g = i & (GT - 1);
        g_Z[ab0 + g + AB * c] = tile[g][c];
    }

    red[t] = (double)acc;
    __syncthreads();
    for (int s = NTHR / 2; s > 0; s >>= 1) { if (t < s) red[t] += red[t + s]; __syncthreads(); }
    if (t == 0) g_data[blockIdx.x] = red[0];
}

// ---------------------- K2/K4: FFT over b (stride FA), twiddle W_16384^{b c'}
template<int FWD>
__global__ __launch_bounds__(NTHR)
void k2_fftb() {
    __shared__ float2 tile[FB][GT + 1];
    const int t  = threadIdx.x;
    const int cp = blockIdx.x >> 6;             // c' ; FA/GT = 64
    const int a0 = (blockIdx.x & 63) * GT;

    for (int i = t; i < FB * GT; i += NTHR) {
        int b = i >> 5;
        int g = i & 31;
        float2 v = g_Z[a0 + g + FA * b + AB * cp];
        if (FWD) v = cmul(v, g_W16384[b * cp]);           // pre-twiddle (forward)
        tile[b][g] = v;
    }
    __syncthreads();

    fft_sm(&tile[0][t >> 3], GT + 1, LB, 8, t & 7, g_W128, FWD ? 1.f : -1.f);

    for (int i = t; i < FB * GT; i += NTHR) {
        int b = i >> 5;
        int g = i & 31;
        float2 v = tile[b][g];
        if (!FWD) {                                        // post-twiddle (inverse)
            float2 w = g_W16384[b * cp]; w.y = -w.y;
            v = cmul(v, w);
        }
        g_Z[a0 + g + FA * b + AB * cp] = v;
    }
}

// -------- block-wide FFT over up to 2 chunks of length FA (used by K3)
__device__ __forceinline__ void blockfft2(float2 (*sm)[FA], int nrow, int t, float sgn) {
    for (int ls = LA - 1; ls >= 0; ls--) {
        const int s = 1 << ls;
        const int tot = nrow << (LA - 1);
#pragma unroll 4
        for (int q = t; q < tot; q += NTHR) {
            int row = q >> (LA - 1);
            int qq  = q & ((FA >> 1) - 1);
            int j   = qq & (s - 1);
            int i0  = ((qq >> ls) << (ls + 1)) + j;
            float2* d = sm[row];
            float2 x0 = d[i0], x1 = d[i0 + s];
            float2 lo = make_float2(x0.x + x1.x, x0.y + x1.y);
            float2 hi = make_float2(x0.x - x1.x, x0.y - x1.y);
            float2 w  = g_W2048[j << (LA - 1 - ls)];
            w.y *= sgn;
            d[i0] = lo;
            d[i0 + s] = cmul(hi, w);
        }
        __syncthreads();
    }
#pragma unroll 4
    for (int i = t; i < (nrow << LA); i += NTHR) {
        int row = i >> LA;
        int ii  = i & (FA - 1);
        int r   = (int)(__brev((unsigned)ii) >> (32 - LA));
        if (r > ii) { float2 tmp = sm[row][ii]; sm[row][ii] = sm[row][r]; sm[row][r] = tmp; }
    }
    __syncthreads();
}

__device__ __forceinline__ float2 herm_P(float2 z1, float2 z2) {
    // DU = (z1 + conj z2)/2 ; B = -i/2 * (z1 - conj z2) ; P = DU*B
    float2 du = make_float2(0.5f * (z1.x + z2.x), 0.5f * (z1.y - z2.y));
    float2 bv = make_float2(0.5f * (z1.y + z2.y), -0.5f * (z1.x - z2.x));
    return cmul(du, bv);
}

// -------- K3: fwd FFT over a (+twiddle), Hermitian pairing P=DU*B, inv FFT over a
__global__ __launch_bounds__(NTHR)
void k3_core() {
    __shared__ float2 sm[2][FA];   // 32 KB
    const int t  = threadIdx.x;
    const int h1 = blockIdx.x;                 // chunk index = b' + FB*c'
    const int b1 = h1 & (FB - 1), c1 = h1 >> LB;
    int h2;
    if (c1 > 0)      h2 = (FB - 1 - b1) + ((FC - c1) << LB);
    else if (b1 > 0) h2 = FB - b1;
    else             h2 = 0;
    if (h1 > h2) return;                       // partner block handles the pair
    const bool self = (h1 == h2);
    const int  nrow = self ? 1 : 2;
    const int  b2 = h2 & (FB - 1), c2 = h2 >> LB;
    const int  hk1 = c1 + FC * b1;             // frequency weight c' + FC*b'
    const int  hk2 = c2 + FC * b2;

    // load chunk(s), contiguous
    for (int i = t; i < (nrow << LA); i += NTHR) {
        int row = i >> LA, a = i & (FA - 1);
        sm[row][a] = g_Z[(row ? h2 : h1) * FA + a];
    }
    __syncthreads();

    // forward pre-twiddle W_N^{a * hk} (e < N, no mod needed: 2047*16383 < 2^25)
    for (int i = t; i < (nrow << LA); i += NTHR) {
        int row = i >> LA, a = i & (FA - 1);
        int e = a * (row ? hk2 : hk1);
        float2 w = cmul(g_Whi[e >> 12], g_Wlo[e & 4095]);
        sm[row][a] = cmul(sm[row][a], w);
    }
    __syncthreads();

    blockfft2(sm, nrow, t, 1.f);               // forward FFT over a

    // Hermitian pairing + pointwise multiply, in smem
    if (!self) {
        for (int a1 = t; a1 < FA; a1 += NTHR) {
            float2 z1 = sm[0][a1];
            float2 z2 = sm[1][FA - 1 - a1];
            float2 P  = herm_P(z1, z2);
            sm[0][a1]          = P;
            sm[1][FA - 1 - a1] = make_float2(P.x, -P.y);
        }
    } else if (h1 != 0) {                      // h == 64: partner a2 = FA-1-a1 in-chunk
        for (int a1 = t; a1 < FA / 2; a1 += NTHR) {
            float2 z1 = sm[0][a1];
            float2 z2 = sm[0][FA - 1 - a1];
            float2 P  = herm_P(z1, z2);
            sm[0][a1]          = P;
            sm[0][FA - 1 - a1] = make_float2(P.x, -P.y);
        }
    } else {                                   // h == 0: partner a2 = (FA - a1) mod FA
        for (int a1 = t; a1 <= FA / 2; a1 += NTHR) {
            if (a1 == 0 || a1 == FA / 2) {
                float2 z = sm[0][a1];
                sm[0][a1] = make_float2(z.x * z.y, 0.f);   // DU=Re(z), B=Im(z)
            } else {
                float2 z1 = sm[0][a1];
                float2 z2 = sm[0][FA - a1];
                float2 P  = herm_P(z1, z2);
                sm[0][a1]      = P;
                sm[0][FA - a1] = make_float2(P.x, -P.y);
            }
        }
    }
    __syncthreads();

    blockfft2(sm, nrow, t, -1.f);              // inverse FFT over a'

    // inverse post-twiddle conj(W_N^{a*hk}), store
    for (int i = t; i < (nrow << LA); i += NTHR) {
        int row = i >> LA, a = i & (FA - 1);
        int e = a * (row ? hk2 : hk1);
        float2 w = cmul(g_Whi[e >> 12], g_Wlo[e & 4095]);
        w.y = -w.y;
        g_Z[(row ? h2 : h1) * FA + a] = cmul(sm[row][a], w);
    }
}

// -------- K5: inverse FFT over c' + fused physics-loss epilogue
__global__ __launch_bounds__(NTHR)
void k5_inv_epi(const float* __restrict__ up, float coefN) {
    __shared__ float2 tile[GT][FC + 1];
    __shared__ double red[NTHR];
    const int t   = threadIdx.x;
    const int ab0 = blockIdx.x * GT;

    for (int i = t; i < GT * FC; i += NTHR) {
        int c = i >> 5;
        int g = i & 31;
        tile[g][c] = g_Z[ab0 + g + AB * c];
    }
    __syncthreads();

    fft_sm(&tile[t >> 3][0], 1, LC, 8, t & 7, g_W128, -1.f);

    float acc = 0.f;
    for (int i = t; i < GT * FC; i += NTHR) {
        int c = i >> 5;
        int g = i & 31;
        int n = ab0 + g + AB * c;      // conv index
        int m = n + 1;                 // residual index (frac[m] = coef*conv[m-1])
        if (m < MTOT) {
            float um = __ldg(up + m);
            float ut = 0.f;
            if ((m & 16383) != 16383) ut = __ldg(up + m + 1) - um;  // last col: u_t = 0
            float r = ut - coefN * tile[g][c].x;
            acc = fmaf(r, r, acc);
        }
    }

    red[t] = (double)acc;
    __syncthreads();
    for (int s = NTHR / 2; s > 0; s >>= 1) { if (t < s) red[t] += red[t + s]; __syncthreads(); }
    if (t == 0) g_phys[blockIdx.x] = red[0];
}

// -------- finalize
__global__ void k_fin(const float* __restrict__ up, float* __restrict__ out) {
    __shared__ double rp[256], rd[256];
    int t = threadIdx.x;
    double sp = 0.0, sd = 0.0;
    for (int i = t; i < NBLK; i += 256) { sp += g_phys[i]; sd += g_data[i]; }
    rp[t] = sp; rd[t] = sd;
    __syncthreads();
    for (int s = 128; s > 0; s >>= 1) {
        if (t < s) { rp[t] += rp[t + s]; rd[t] += rd[t + s]; }
        __syncthreads();
    }
    if (t == 0) {
        double r0 = (double)up[1] - (double)up[0];    // m = 0 residual: u_t[0] - 0
        double phys = (rp[0] + r0 * r0) / (double)MTOT;
        double data = rd[0] / (double)MTOT;
        out[0] = (float)(data + 0.1 * phys);
        out[1] = (float)data;
        out[2] = (float)phys;
    }
}

extern "C" void kernel_launch(void* const* d_in, const int* in_sizes, int n_in,
                              void* d_out, int out_size)
{
    const float* up  = (const float*)d_in[0];  // u_pred
    const float* utr = (const float*)d_in[1];  // u_true
    (void)in_sizes; (void)n_in; (void)out_size;

    // coef = sqrt(M-1)/Gamma(1.5); fold the 1/N of the inverse FFT in here.
    double coefN = sqrt((double)(MTOT - 1)) / 0.886226925452758013649083741670572
                   / (double)NF;

    k_tw<<<64, 256>>>();
    k1_pack_fft<<<NBLK, NTHR>>>(up, utr);
    k2_fftb<1><<<NBLK, NTHR>>>();
    k3_core<<<FB * FC, NTHR>>>();
    k2_fftb<0><<<NBLK, NTHR>>>();
    k5_inv_epi<<<NBLK, NTHR>>>(up, (float)coefN);
    k_fin<<<1, 256>>>(up, (float*)d_out);
}

// round 6
// speedup vs baseline: 2.1267x; 2.1267x over previous
#include <cuda_runtime.h>
#include <math.h>

// FFT size N = 2^25 = FA * FB * FC, position n = a + FA*b + AB*c
#define LN   25
#define NF   (1 << LN)
#define LA   11
#define FA   (1 << LA)          // 2048
#define LB   7
#define FB   (1 << LB)          // 128
#define LC   7
#define FC   (1 << LC)          // 128
#define AB   (FA * FB)          // 262144
#define GT   32                 // tile width (consecutive fast-dim elements)
#define NTHR 256

#define MTOT (1 << 24)          // problem size B*N = 2^24
#define NBLK (AB / GT)          // 8192 blocks for K1/K5

#define FAP  (FA + (FA >> 5))   // padded row length for K3 smem
#define PH(p) ((p) + ((p) >> 5))

// 256 MB spectral work buffer + twiddle tables + partials (no runtime allocation)
__device__ float2 g_Z[NF];
__device__ float2 g_W16384[16384];  // W_16384^m (full)
__device__ float2 g_W2048[2048];    // W_2048^m  (full)
__device__ float2 g_W128[128];      // W_128^m   (full)
__device__ float2 g_Wlo[4096];      // W_N^j,        j < 4096
__device__ float2 g_Whi[8192];      // W_N^{4096 j}, j < 8192
__device__ double g_data[NBLK];
__device__ double g_phys[NBLK];

__device__ __forceinline__ float2 cadd(float2 a, float2 b) { return make_float2(a.x + b.x, a.y + b.y); }
__device__ __forceinline__ float2 csub(float2 a, float2 b) { return make_float2(a.x - b.x, a.y - b.y); }
__device__ __forceinline__ float2 cmul(float2 a, float2 b) {
    return make_float2(fmaf(a.x, b.x, -a.y * b.y), fmaf(a.x, b.y, a.y * b.x));
}
// multiply by -i (sgn=+1, forward) or +i (sgn=-1, inverse)
__device__ __forceinline__ float2 crot(float2 a, float sgn) { return make_float2(sgn * a.y, -sgn * a.x); }

// 8-point DFT in registers, natural-order outputs. sgn=+1 fwd, -1 inverse (unnormalized).
__device__ __forceinline__ void dft8(float2* u, float sgn) {
    const float C = 0.70710678118654752440f;
    float2 t0 = cadd(u[0], u[4]), t1 = cadd(u[1], u[5]);
    float2 t2 = cadd(u[2], u[6]), t3 = cadd(u[3], u[7]);
    float2 m4 = csub(u[0], u[4]), m5 = csub(u[1], u[5]);
    float2 m6 = csub(u[2], u[6]), m7 = csub(u[3], u[7]);
    float2 t4 = m4;
    float2 t5 = cmul(m5, make_float2(C, -sgn * C));    // W8^1
    float2 t6 = crot(m6, sgn);                         // W8^2
    float2 t7 = cmul(m7, make_float2(-C, -sgn * C));   // W8^3
    float2 s0 = cadd(t0, t2), s2 = csub(t0, t2);
    float2 s1 = cadd(t1, t3), s3 = crot(csub(t1, t3), sgn);
    float2 r0 = cadd(t4, t6), r2 = csub(t4, t6);
    float2 r1 = cadd(t5, t7), r3 = crot(csub(t5, t7), sgn);
    u[0] = cadd(s0, s1); u[4] = csub(s0, s1);
    u[2] = cadd(s2, s3); u[6] = csub(s2, s3);
    u[1] = cadd(r0, r1); u[5] = csub(r0, r1);
    u[3] = cadd(r2, r3); u[7] = csub(r2, r3);
}

// 4-point DFT in registers, natural order.
__device__ __forceinline__ void dft4(float2* u, float sgn) {
    float2 a0 = cadd(u[0], u[2]), b0 = csub(u[0], u[2]);
    float2 a1 = cadd(u[1], u[3]), b1 = crot(csub(u[1], u[3]), sgn);
    u[0] = cadd(a0, a1); u[2] = csub(a0, a1);
    u[1] = cadd(b0, b1); u[3] = csub(b0, b1);
}

// digit-reversal maps
// 128 = 8*8*2 DIF: position p -> natural frequency
__device__ __forceinline__ int f128(int p) {
    return (p >> 4) + (((p >> 1) & 7) << 3) + ((p & 1) << 6);
}
// 2048 = 8*8*8*4 DIF: natural frequency k -> scrambled position
__device__ __forceinline__ int pos2048(int k) {
    return ((k & 7) << 8) + (((k >> 3) & 7) << 5) + (((k >> 6) & 7) << 2) + (k >> 9);
}

// ---------------------------------------------------------------- twiddle init
__global__ void k_tw() {
    int idx = blockIdx.x * 256 + threadIdx.x;   // 64 blocks * 256 = 16384
    const double P2 = 6.283185307179586476925286766559;
    if (idx < 16384) { double a = -P2 * idx / 16384.0;    g_W16384[idx] = make_float2((float)cos(a), (float)sin(a)); }
    if (idx < 8192)  { double a = -P2 * idx / 8192.0;     g_Whi[idx]    = make_float2((float)cos(a), (float)sin(a)); }
    if (idx < 4096)  { double a = -P2 * idx / (double)NF; g_Wlo[idx]    = make_float2((float)cos(a), (float)sin(a)); }
    if (idx < 2048)  { double a = -P2 * idx / 2048.0;     g_W2048[idx]  = make_float2((float)cos(a), (float)sin(a)); }
    if (idx < 128)   { double a = -P2 * idx / 128.0;      g_W128[idx]   = make_float2((float)cos(a), (float)sin(a)); }
}

// -------------------------------------------------------------------------
// 128-point DIF FFT over the slow axis of tile[128][GT+1]; 32 independent
// transforms (one per column g). Input natural order; OUTPUT DIGIT-SCRAMBLED
// (digits 8,8,2; natural freq of position p is f128(p)).
// sgn=+1 forward DFT, sgn=-1 unnormalized inverse DFT.
// All NTHR threads participate; lane index g = q&31 -> conflict-free smem.
// -------------------------------------------------------------------------
__device__ __forceinline__ void fft128_cols(float2 (*tile)[GT + 1], int t, float sgn) {
    // stage 1: sub-len 128, span 16 (radix-8)
    for (int q = t; q < 512; q += NTHR) {
        int g = q & 31, j = q >> 5;            // j in [0,16)
        float2 u[8];
#pragma unroll
        for (int k = 0; k < 8; k++) u[k] = tile[j + (k << 4)][g];
        dft8(u, sgn);
#pragma unroll
        for (int k = 1; k < 8; k++) {
            float2 w = g_W128[j * k]; w.y *= sgn;
            u[k] = cmul(u[k], w);
        }
#pragma unroll
        for (int k = 0; k < 8; k++) tile[j + (k << 4)][g] = u[k];
    }
    __syncthreads();
    // stage 2: sub-len 16, span 2 (radix-8), 8 chunks
    for (int q = t; q < 512; q += NTHR) {
        int g = q & 31, qq = q >> 5;
        int j = qq & 1, m = qq >> 1;
        int base = (m << 4) + j;
        float2 u[8];
#pragma unroll
        for (int k = 0; k < 8; k++) u[k] = tile[base + (k << 1)][g];
        dft8(u, sgn);
#pragma unroll
        for (int k = 1; k < 8; k++) {
            float2 w = g_W128[(j * k) << 3];  // W_16^{jk} = W_128^{8jk}
            w.y *= sgn;
            u[k] = cmul(u[k], w);
        }
#pragma unroll
        for (int k = 0; k < 8; k++) tile[base + (k << 1)][g] = u[k];
    }
    __syncthreads();
    // stage 3: sub-len 2 (radix-2), 64 contiguous pairs per fft
    for (int q = t; q < 2048; q += NTHR) {
        int g = q & 31, p = (q >> 5) << 1;
        float2 a = tile[p][g], b = tile[p + 1][g];
        tile[p][g]     = cadd(a, b);
        tile[p + 1][g] = csub(a, b);
    }
    __syncthreads();
}

// ------------------------------------- K1: pack Z = du + i*b, FFT over c, data loss
__global__ __launch_bounds__(NTHR)
void k1_pack_fft(const float* __restrict__ up, const float* __restrict__ utr) {
    __shared__ float2 tile[FC][GT + 1];
    __shared__ double red[NTHR];
    const int t   = threadIdx.x;
    const int ab0 = blockIdx.x * GT;

    float acc = 0.f;
    for (int i = t; i < GT * FC; i += NTHR) {
        int c = i >> 5;
        int g = i & 31;
        int n = ab0 + g + AB * c;
        float du = 0.f, bw = 0.f;
        if (n < MTOT) {
            float uv = __ldg(up + n);
            float d  = uv - __ldg(utr + n);
            acc = fmaf(d, d, acc);
            if (n < MTOT - 1) {
                du = __ldg(up + n + 1) - uv;
                // EXACT replica of the reference fp32 weights (incl. cancellation noise)
                bw = __fsqrt_rn((float)(n + 1)) - __fsqrt_rn((float)n);
            }
        }
        tile[c][g] = make_float2(du, bw);
    }
    __syncthreads();

    fft128_cols(tile, t, 1.f);

    // fold digit-reversal into the global slab index (still g-fastest coalesced)
    for (int i = t; i < GT * FC; i += NTHR) {
        int p = i >> 5;
        int g = i & 31;
        g_Z[ab0 + g + AB * f128(p)] = tile[p][g];
    }

    red[t] = (double)acc;
    __syncthreads();
    for (int s = NTHR / 2; s > 0; s >>= 1) { if (t < s) red[t] += red[t + s]; __syncthreads(); }
    if (t == 0) g_data[blockIdx.x] = red[0];
}

// ---------------------- K2/K4: FFT over b (stride FA), twiddle W_16384^{b c'}
template<int FWD>
__global__ __launch_bounds__(NTHR)
void k2_fftb() {
    __shared__ float2 tile[FB][GT + 1];
    const int t  = threadIdx.x;
    const int cp = blockIdx.x >> 6;             // c' ; FA/GT = 64
    const int a0 = (blockIdx.x & 63) * GT;

    for (int i = t; i < FB * GT; i += NTHR) {
        int b = i >> 5;
        int g = i & 31;
        float2 v = g_Z[a0 + g + FA * b + AB * cp];
        if (FWD) v = cmul(v, g_W16384[b * cp]);           // pre-twiddle (forward)
        tile[b][g] = v;
    }
    __syncthreads();

    fft128_cols(tile, t, FWD ? 1.f : -1.f);

    for (int i = t; i < FB * GT; i += NTHR) {
        int p  = i >> 5;
        int g  = i & 31;
        int bb = f128(p);                                  // natural output index
        float2 v = tile[p][g];
        if (!FWD) {                                        // post-twiddle (inverse)
            float2 w = g_W16384[bb * cp]; w.y = -w.y;
            v = cmul(v, w);
        }
        g_Z[a0 + g + FA * bb + AB * cp] = v;
    }
}

// -------- K3 stage helpers: 2048 = 8*8*8*4, padded smem layout PH()
__device__ __forceinline__ void k3_r8(float2 (*sm)[FAP], int nrow, int t,
                                      int ls, int tmul, int inv) {
    const int s   = 1 << ls;
    const int tot = nrow << 8;      // 256 butterflies per row
    for (int q = t; q < tot; q += NTHR) {
        int row = q >> 8, qq = q & 255;
        int j = qq & (s - 1), m = qq >> ls;
        int base = (m << (ls + 3)) + j;
        float2 u[8];
#pragma unroll
        for (int k = 0; k < 8; k++) u[k] = sm[row][PH(base + (k << ls))];
        if (!inv) {
            dft8(u, 1.f);
#pragma unroll
            for (int k = 1; k < 8; k++) u[k] = cmul(u[k], g_W2048[tmul * j * k]);
        } else {
            // DIT inverse: conj twiddle BEFORE inverse DFT8
#pragma unroll
            for (int k = 1; k < 8; k++) {
                float2 w = g_W2048[tmul * j * k]; w.y = -w.y;
                u[k] = cmul(u[k], w);
            }
            dft8(u, -1.f);
        }
#pragma unroll
        for (int k = 0; k < 8; k++) sm[row][PH(base + (k << ls))] = u[k];
    }
    __syncthreads();
}

__device__ __forceinline__ void k3_r4(float2 (*sm)[FAP], int nrow, int t, float sgn) {
    const int tot = nrow << 9;      // 512 quads per row
    for (int q = t; q < tot; q += NTHR) {
        int row = q >> 9, b = (q & 511) << 2;
        float2 u[4];
#pragma unroll
        for (int e = 0; e < 4; e++) u[e] = sm[row][PH(b + e)];
        dft4(u, sgn);
#pragma unroll
        for (int e = 0; e < 4; e++) sm[row][PH(b + e)] = u[e];
    }
    __syncthreads();
}

__device__ __forceinline__ float2 herm_P(float2 z1, float2 z2) {
    // DU = (z1 + conj z2)/2 ; B = -i/2 * (z1 - conj z2) ; P = DU*B
    float2 du = make_float2(0.5f * (z1.x + z2.x), 0.5f * (z1.y - z2.y));
    float2 bv = make_float2(0.5f * (z1.y + z2.y), -0.5f * (z1.x - z2.x));
    return cmul(du, bv);
}

// -------- K3: fwd DIF over a (+twiddle), pointwise in scrambled domain, inverse DIT
__global__ __launch_bounds__(NTHR)
void k3_core() {
    __shared__ float2 sm[2][FAP];   // ~33 KB
    const int t  = threadIdx.x;
    const int h1 = blockIdx.x;                 // chunk index = b' + FB*c'
    const int b1 = h1 & (FB - 1), c1 = h1 >> LB;
    int h2;
    if (c1 > 0)      h2 = (FB - 1 - b1) + ((FC - c1) << LB);
    else if (b1 > 0) h2 = FB - b1;
    else             h2 = 0;
    if (h1 > h2) return;                       // partner block handles the pair
    const bool self = (h1 == h2);
    const int  nrow = self ? 1 : 2;
    const int  b2 = h2 & (FB - 1), c2 = h2 >> LB;
    const int  hk1 = c1 + FC * b1;             // frequency weight c' + FC*b'
    const int  hk2 = c2 + FC * b2;

    // fused: load chunk(s) + forward pre-twiddle W_N^{a*hk} (e < N, no mod: 2047*16383 < 2^25)
    for (int i = t; i < (nrow << LA); i += NTHR) {
        int row = i >> LA, a = i & (FA - 1);
        int e = a * (row ? hk2 : hk1);
        float2 w = cmul(g_Whi[e >> 12], g_Wlo[e & 4095]);
        sm[row][PH(a)] = cmul(g_Z[(row ? h2 : h1) * FA + a], w);
    }
    __syncthreads();

    // forward DIF: radix-8 x3 + radix-4 (output digit-scrambled: pos2048)
    k3_r8(sm, nrow, t, 8, 1,  0);   // sub-len 2048, span 256
    k3_r8(sm, nrow, t, 5, 8,  0);   // sub-len 256,  span 32
    k3_r8(sm, nrow, t, 2, 64, 0);   // sub-len 32,   span 4
    k3_r4(sm, nrow, t, 1.f);        // sub-len 4,    span 1

    // Hermitian pairing + pointwise multiply, scrambled positions
    if (!self) {
        for (int a1 = t; a1 < FA; a1 += NTHR) {
            int p1 = pos2048(a1), p2 = pos2048(FA - 1 - a1);
            float2 z1 = sm[0][PH(p1)];
            float2 z2 = sm[1][PH(p2)];
            float2 P  = herm_P(z1, z2);
            sm[0][PH(p1)] = P;
            sm[1][PH(p2)] = make_float2(P.x, -P.y);
        }
    } else if (h1 != 0) {                      // h == 64: partner a2 = FA-1-a1 in-chunk
        for (int a1 = t; a1 < FA / 2; a1 += NTHR) {
            int p1 = pos2048(a1), p2 = pos2048(FA - 1 - a1);
            float2 z1 = sm[0][PH(p1)];
            float2 z2 = sm[0][PH(p2)];
            float2 P  = herm_P(z1, z2);
            sm[0][PH(p1)] = P;
            sm[0][PH(p2)] = make_float2(P.x, -P.y);
        }
    } else {                                   // h == 0: partner a2 = (FA - a1) mod FA
        for (int a1 = t; a1 <= FA / 2; a1 += NTHR) {
            if (a1 == 0 || a1 == FA / 2) {
                int p = pos2048(a1);
                float2 z = sm[0][PH(p)];
                sm[0][PH(p)] = make_float2(z.x * z.y, 0.f);   // DU=Re(z), B=Im(z)
            } else {
                int p1 = pos2048(a1), p2 = pos2048(FA - a1);
                float2 z1 = sm[0][PH(p1)];
                float2 z2 = sm[0][PH(p2)];
                float2 P  = herm_P(z1, z2);
                sm[0][PH(p1)] = P;
                sm[0][PH(p2)] = make_float2(P.x, -P.y);
            }
        }
    }
    __syncthreads();

    // inverse DIT: mirror order, conj twiddles (scrambled in -> natural out)
    k3_r4(sm, nrow, t, -1.f);
    k3_r8(sm, nrow, t, 2, 64, 1);
    k3_r8(sm, nrow, t, 5, 8,  1);
    k3_r8(sm, nrow, t, 8, 1,  1);

    // fused: inverse post-twiddle conj(W_N^{a*hk}) + store
    for (int i = t; i < (nrow << LA); i += NTHR) {
        int row = i >> LA, a = i & (FA - 1);
        int e = a * (row ? hk2 : hk1);
        float2 w = cmul(g_Whi[e >> 12], g_Wlo[e & 4095]);
        w.y = -w.y;
        g_Z[(row ? h2 : h1) * FA + a] = cmul(sm[row][PH(a)], w);
    }
}

// -------- K5: inverse FFT over c' + fused physics-loss epilogue
__global__ __launch_bounds__(NTHR)
void k5_inv_epi(const float* __restrict__ up, float coefN) {
    __shared__ float2 tile[FC][GT + 1];
    __shared__ double red[NTHR];
    const int t   = threadIdx.x;
    const int ab0 = blockIdx.x * GT;

    for (int i = t; i < GT * FC; i += NTHR) {
        int c = i >> 5;
        int g = i & 31;
        tile[c][g] = g_Z[ab0 + g + AB * c];
    }
    __syncthreads();

    fft128_cols(tile, t, -1.f);    // inverse, output scrambled; map via f128

    float acc = 0.f;
    for (int i = t; i < GT * FC; i += NTHR) {
        int p = i >> 5;
        int g = i & 31;
        int c = f128(p);               // natural conv slab index
        int n = ab0 + g + AB * c;      // conv index
        int m = n + 1;                 // residual index (frac[m] = coef*conv[m-1])
        if (m < MTOT) {
            float um = __ldg(up + m);
            float ut = 0.f;
            if ((m & 16383) != 16383) ut = __ldg(up + m + 1) - um;  // last col: u_t = 0
            float r = ut - coefN * tile[p][g].x;
            acc = fmaf(r, r, acc);
        }
    }

    red[t] = (double)acc;
    __syncthreads();
    for (int s = NTHR / 2; s > 0; s >>= 1) { if (t < s) red[t] += red[t + s]; __syncthreads(); }
    if (t == 0) g_phys[blockIdx.x] = red[0];
}

// -------- finalize
__global__ void k_fin(const float* __restrict__ up, float* __restrict__ out) {
    __shared__ double rp[256], rd[256];
    int t = threadIdx.x;
    double sp = 0.0, sd = 0.0;
    for (int i = t; i < NBLK; i += 256) { sp += g_phys[i]; sd += g_data[i]; }
    rp[t] = sp; rd[t] = sd;
    __syncthreads();
    for (int s = 128; s > 0; s >>= 1) {
        if (t < s) { rp[t] += rp[t + s]; rd[t] += rd[t + s]; }
        __syncthreads();
    }
    if (t == 0) {
        double r0 = (double)up[1] - (double)up[0];    // m = 0 residual: u_t[0] - 0
        double phys = (rp[0] + r0 * r0) / (double)MTOT;
        double data = rd[0] / (double)MTOT;
        out[0] = (float)(data + 0.1 * phys);
        out[1] = (float)data;
        out[2] = (float)phys;
    }
}

extern "C" void kernel_launch(void* const* d_in, const int* in_sizes, int n_in,
                              void* d_out, int out_size)
{
    const float* up  = (const float*)d_in[0];  // u_pred
    const float* utr = (const float*)d_in[1];  // u_true
    (void)in_sizes; (void)n_in; (void)out_size;

    // coef = sqrt(M-1)/Gamma(1.5); fold the 1/N of the fwd+inv FFT product in here.
    double coefN = sqrt((double)(MTOT - 1)) / 0.886226925452758013649083741670572
                   / (double)NF;

    k_tw<<<64, 256>>>();
    k1_pack_fft<<<NBLK, NTHR>>>(up, utr);
    k2_fftb<1><<<NBLK, NTHR>>>();
    k3_core<<<FB * FC, NTHR>>>();
    k2_fftb<0><<<NBLK, NTHR>>>();
    k5_inv_epi<<<NBLK, NTHR>>>(up, (float)coefN);
    k_fin<<<1, 256>>>(up, (float*)d_out);
}

// round 8
// speedup vs baseline: 2.4641x; 1.1586x over previous
#include <cuda_runtime.h>
#include <math.h>

// FFT size N = 2^25 = FA * FB * FC, position n = a + FA*b + AB*c
#define LN   25
#define NF   (1 << LN)
#define LA   11
#define FA   (1 << LA)          // 2048
#define LB   7
#define FB   (1 << LB)          // 128
#define LC   7
#define FC   (1 << LC)          // 128
#define AB   (FA * FB)          // 262144
#define GT   32                 // tile width (consecutive fast-dim elements)
#define NTHR 256

#define MTOT (1 << 24)          // problem size B*N = 2^24
#define NBLK (AB / GT)          // 8192 blocks for K1/K5

#define FAP  (FA + (FA >> 5))   // padded row length for K3 smem
#define PH(p) ((p) + ((p) >> 5))

// 256 MB spectral work buffer + twiddle tables + partials (no runtime allocation)
__device__ float2 g_Z[NF];
__device__ float2 g_W16384[16384];  // W_16384^m (full)
__device__ float2 g_W2048[2048];    // W_2048^m  (full)
__device__ float2 g_W128[128];      // W_128^m   (full)
__device__ float2 g_Wlo[4096];      // W_N^j,        j < 4096
__device__ float2 g_Whi[8192];      // W_N^{4096 j}, j < 8192
__device__ double g_data[NBLK];
__device__ double g_phys[NBLK];

__device__ __forceinline__ float2 cadd(float2 a, float2 b) { return make_float2(a.x + b.x, a.y + b.y); }
__device__ __forceinline__ float2 csub(float2 a, float2 b) { return make_float2(a.x - b.x, a.y - b.y); }
__device__ __forceinline__ float2 cmul(float2 a, float2 b) {
    return make_float2(fmaf(a.x, b.x, -a.y * b.y), fmaf(a.x, b.y, a.y * b.x));
}
// multiply by -i (sgn=+1, forward) or +i (sgn=-1, inverse)
__device__ __forceinline__ float2 crot(float2 a, float sgn) { return make_float2(sgn * a.y, -sgn * a.x); }

// 8-point DFT in registers, natural-order outputs. sgn=+1 fwd, -1 inverse (unnormalized).
__device__ __forceinline__ void dft8(float2* u, float sgn) {
    const float C = 0.70710678118654752440f;
    float2 t0 = cadd(u[0], u[4]), t1 = cadd(u[1], u[5]);
    float2 t2 = cadd(u[2], u[6]), t3 = cadd(u[3], u[7]);
    float2 m4 = csub(u[0], u[4]), m5 = csub(u[1], u[5]);
    float2 m6 = csub(u[2], u[6]), m7 = csub(u[3], u[7]);
    float2 t4 = m4;
    float2 t5 = cmul(m5, make_float2(C, -sgn * C));    // W8^1
    float2 t6 = crot(m6, sgn);                         // W8^2
    float2 t7 = cmul(m7, make_float2(-C, -sgn * C));   // W8^3
    float2 s0 = cadd(t0, t2), s2 = csub(t0, t2);
    float2 s1 = cadd(t1, t3), s3 = crot(csub(t1, t3), sgn);
    float2 r0 = cadd(t4, t6), r2 = csub(t4, t6);
    float2 r1 = cadd(t5, t7), r3 = crot(csub(t5, t7), sgn);
    u[0] = cadd(s0, s1); u[4] = csub(s0, s1);
    u[2] = cadd(s2, s3); u[6] = csub(s2, s3);
    u[1] = cadd(r0, r1); u[5] = csub(r0, r1);
    u[3] = cadd(r2, r3); u[7] = csub(r2, r3);
}

// 8-point DFT with inputs 4..7 known to be zero (k1 zero-padding). In: u[0..3]; out: u[0..7].
__device__ __forceinline__ void dft8h(float2* u, float sgn) {
    const float C = 0.70710678118654752440f;
    float2 t0 = u[0], t1 = u[1], t2 = u[2], t3 = u[3];
    float2 t4 = u[0];
    float2 t5 = cmul(u[1], make_float2(C, -sgn * C));
    float2 t6 = crot(u[2], sgn);
    float2 t7 = cmul(u[3], make_float2(-C, -sgn * C));
    float2 s0 = cadd(t0, t2), s2 = csub(t0, t2);
    float2 s1 = cadd(t1, t3), s3 = crot(csub(t1, t3), sgn);
    float2 r0 = cadd(t4, t6), r2 = csub(t4, t6);
    float2 r1 = cadd(t5, t7), r3 = crot(csub(t5, t7), sgn);
    u[0] = cadd(s0, s1); u[4] = csub(s0, s1);
    u[2] = cadd(s2, s3); u[6] = csub(s2, s3);
    u[1] = cadd(r0, r1); u[5] = csub(r0, r1);
    u[3] = cadd(r2, r3); u[7] = csub(r2, r3);
}

// 4-point DFT in registers, natural order.
__device__ __forceinline__ void dft4(float2* u, float sgn) {
    float2 a0 = cadd(u[0], u[2]), b0 = csub(u[0], u[2]);
    float2 a1 = cadd(u[1], u[3]), b1 = crot(csub(u[1], u[3]), sgn);
    u[0] = cadd(a0, a1); u[2] = csub(a0, a1);
    u[1] = cadd(b0, b1); u[3] = csub(b0, b1);
}

// digit-reversal maps
// 128 = 8*8*2 DIF: position p -> natural frequency
__device__ __forceinline__ int f128(int p) {
    return (p >> 4) + (((p >> 1) & 7) << 3) + ((p & 1) << 6);
}
// 2048 = 8*8*8*4 DIF: natural frequency k -> scrambled position
__device__ __forceinline__ int pos2048(int k) {
    return ((k & 7) << 8) + (((k >> 3) & 7) << 5) + (((k >> 6) & 7) << 2) + (k >> 9);
}

// ---------------------------------------------------------------- twiddle init
__global__ void k_tw() {
    int idx = blockIdx.x * 256 + threadIdx.x;   // 64 blocks * 256 = 16384
    const double P2 = 6.283185307179586476925286766559;
    if (idx < 16384) { double a = -P2 * idx / 16384.0;    g_W16384[idx] = make_float2((float)cos(a), (float)sin(a)); }
    if (idx < 8192)  { double a = -P2 * idx / 8192.0;     g_Whi[idx]    = make_float2((float)cos(a), (float)sin(a)); }
    if (idx < 4096)  { double a = -P2 * idx / (double)NF; g_Wlo[idx]    = make_float2((float)cos(a), (float)sin(a)); }
    if (idx < 2048)  { double a = -P2 * idx / 2048.0;     g_W2048[idx]  = make_float2((float)cos(a), (float)sin(a)); }
    if (idx < 128)   { double a = -P2 * idx / 128.0;      g_W128[idx]   = make_float2((float)cos(a), (float)sin(a)); }
}

// -------------------------------------------------------------------------
// 128-pt DIF FFT over slow axis of tile[128][GT+1], 32 transforms (one per g).
// TWO smem sweeps: radix-8 (span 16) + fused register-resident 16-point.
// Output digit-scrambled: natural freq of position p is f128(p).
// -------------------------------------------------------------------------
__device__ __forceinline__ void fft128_s1(float2 (*tile)[GT + 1], int t, float sgn) {
    for (int q = t; q < 512; q += NTHR) {
        int g = q & 31, j = q >> 5;            // j in [0,16)
        float2 u[8];
#pragma unroll
        for (int k = 0; k < 8; k++) u[k] = tile[j + (k << 4)][g];
        dft8(u, sgn);
#pragma unroll
        for (int k = 1; k < 8; k++) {
            float2 w = g_W128[j * k]; w.y *= sgn;
            u[k] = cmul(u[k], w);
        }
#pragma unroll
        for (int k = 0; k < 8; k++) tile[j + (k << 4)][g] = u[k];
    }
    __syncthreads();
}

// stage 2: full 16-pt transform in registers per 16-block (m = t>>5, g = t&31)
__device__ __forceinline__ void fft128_s2(float2 (*tile)[GT + 1], int t, float sgn) {
    int g = t & 31, m = t >> 5;                // exactly 256 work items
    int base = m << 4;
    float2 e0[8], e1[8];
#pragma unroll
    for (int k = 0; k < 8; k++) {
        e0[k] = tile[base + (k << 1)][g];
        e1[k] = tile[base + (k << 1) + 1][g];
    }
    dft8(e0, sgn); dft8(e1, sgn);
#pragma unroll
    for (int k = 1; k < 8; k++) {
        float2 w = g_W128[k << 3]; w.y *= sgn; // W16^k
        e1[k] = cmul(e1[k], w);
    }
#pragma unroll
    for (int k = 0; k < 8; k++) {
        tile[base + (k << 1)][g]     = cadd(e0[k], e1[k]);
        tile[base + (k << 1) + 1][g] = csub(e0[k], e1[k]);
    }
    __syncthreads();
}

// ------------------------------------- K1: pack Z = du + i*b, FFT over c, data loss
// Input rows c >= 64 are structurally zero (n >= MTOT) -> half-input stage 1.
__global__ __launch_bounds__(NTHR)
void k1_pack_fft(const float* __restrict__ up, const float* __restrict__ utr) {
    __shared__ float2 tile[FC][GT + 1];
    __shared__ double red[NTHR];
    const int t   = threadIdx.x;
    const int ab0 = blockIdx.x * GT;

    // load rows c < 64 only, float4-vectorized (4 g per thread)
    float acc = 0.f;
    for (int i = t; i < (GT / 4) * 64; i += NTHR) {      // 512 items
        int c  = i >> 3;
        int gq = (i & 7) << 2;
        int n  = ab0 + gq + AB * c;                      // n+3 < MTOT guaranteed (c<64)
        float4 a4 = *reinterpret_cast<const float4*>(up + n);
        float4 b4 = *reinterpret_cast<const float4*>(utr + n);
        float d0 = a4.x - b4.x, d1 = a4.y - b4.y, d2 = a4.z - b4.z, d3 = a4.w - b4.w;
        acc = fmaf(d0, d0, acc); acc = fmaf(d1, d1, acc);
        acc = fmaf(d2, d2, acc); acc = fmaf(d3, d3, acc);
        float unext = (n + 4 < MTOT) ? __ldg(up + n + 4) : 0.f;
        float du0 = a4.y - a4.x, du1 = a4.z - a4.y, du2 = a4.w - a4.z, du3 = unext - a4.w;
        // EXACT replica of the reference fp32 weights (incl. cancellation noise)
        float bw0 = __fsqrt_rn((float)(n + 1)) - __fsqrt_rn((float)n);
        float bw1 = __fsqrt_rn((float)(n + 2)) - __fsqrt_rn((float)(n + 1));
        float bw2 = __fsqrt_rn((float)(n + 3)) - __fsqrt_rn((float)(n + 2));
        float bw3 = __fsqrt_rn((float)(n + 4)) - __fsqrt_rn((float)(n + 3));
        if (n + 3 >= MTOT - 1) {                          // only last elements of last block
            if (n + 0 >= MTOT - 1) { du0 = 0.f; bw0 = 0.f; }
            if (n + 1 >= MTOT - 1) { du1 = 0.f; bw1 = 0.f; }
            if (n + 2 >= MTOT - 1) { du2 = 0.f; bw2 = 0.f; }
            du3 = 0.f; bw3 = 0.f;
        }
        tile[c][gq + 0] = make_float2(du0, bw0);
        tile[c][gq + 1] = make_float2(du1, bw1);
        tile[c][gq + 2] = make_float2(du2, bw2);
        tile[c][gq + 3] = make_float2(du3, bw3);
    }
    __syncthreads();

    // stage 1 with zero top half: reads rows j+16k for k<4 (all < 64)
    for (int q = t; q < 512; q += NTHR) {
        int g = q & 31, j = q >> 5;
        float2 u[8];
#pragma unroll
        for (int k = 0; k < 4; k++) u[k] = tile[j + (k << 4)][g];
        dft8h(u, 1.f);
#pragma unroll
        for (int k = 1; k < 8; k++) {
            float2 w = g_W128[j * k];
            u[k] = cmul(u[k], w);
        }
#pragma unroll
        for (int k = 0; k < 8; k++) tile[j + (k << 4)][g] = u[k];
    }
    __syncthreads();

    fft128_s2(tile, t, 1.f);

    // store with digit-reversal folded into slab index, float4 (2 complex) per store
    for (int i = t; i < (FC * GT) / 2; i += NTHR) {      // 2048 items
        int p  = i >> 4;
        int gg = (i & 15) << 1;
        float2 v0 = tile[p][gg], v1 = tile[p][gg + 1];
        *reinterpret_cast<float4*>(g_Z + ab0 + gg + AB * f128(p)) =
            make_float4(v0.x, v0.y, v1.x, v1.y);
    }

    red[t] = (double)acc;
    __syncthreads();
    for (int s = NTHR / 2; s > 0; s >>= 1) { if (t < s) red[t] += red[t + s]; __syncthreads(); }
    if (t == 0) g_data[blockIdx.x] = red[0];
}

// ---------------------- K2/K4: FFT over b (stride FA), twiddle W_16384^{b c'}
template<int FWD>
__global__ __launch_bounds__(NTHR)
void k2_fftb() {
    __shared__ float2 tile[FB][GT + 1];
    const int t  = threadIdx.x;
    const int cp = blockIdx.x >> 6;             // c' ; FA/GT = 64
    const int a0 = (blockIdx.x & 63) * GT;

    for (int i = t; i < (FB * GT) / 2; i += NTHR) {
        int b  = i >> 4;
        int gg = (i & 15) << 1;
        float4 q4 = *reinterpret_cast<const float4*>(g_Z + a0 + gg + FA * b + AB * cp);
        float2 v0 = make_float2(q4.x, q4.y), v1 = make_float2(q4.z, q4.w);
        if (FWD) {
            float2 w = g_W16384[b * cp];        // pre-twiddle (forward)
            v0 = cmul(v0, w); v1 = cmul(v1, w);
        }
        tile[b][gg] = v0; tile[b][gg + 1] = v1;
    }
    __syncthreads();

    fft128_s1(tile, t, FWD ? 1.f : -1.f);
    fft128_s2(tile, t, FWD ? 1.f : -1.f);

    for (int i = t; i < (FB * GT) / 2; i += NTHR) {
        int p  = i >> 4;
        int gg = (i & 15) << 1;
        int bb = f128(p);                       // natural output index
        float2 v0 = tile[p][gg], v1 = tile[p][gg + 1];
        if (!FWD) {                             // post-twiddle (inverse)
            float2 w = g_W16384[bb * cp]; w.y = -w.y;
            v0 = cmul(v0, w); v1 = cmul(v1, w);
        }
        *reinterpret_cast<float4*>(g_Z + a0 + gg + FA * bb + AB * cp) =
            make_float4(v0.x, v0.y, v1.x, v1.y);
    }
}

// -------- K3 stage helpers: 2048 = 8*8*8*4, padded smem layout PH()
__device__ __forceinline__ void k3_r8(float2 (*sm)[FAP], int nrow, int t,
                                      int ls, int tmul, int inv) {
    const int s   = 1 << ls;
    const int tot = nrow << 8;      // 256 butterflies per row
    for (int q = t; q < tot; q += NTHR) {
        int row = q >> 8, qq = q & 255;
        int j = qq & (s - 1), m = qq >> ls;
        int base = (m << (ls + 3)) + j;
        float2 u[8];
#pragma unroll
        for (int k = 0; k < 8; k++) u[k] = sm[row][PH(base + (k << ls))];
        if (!inv) {
            dft8(u, 1.f);
#pragma unroll
            for (int k = 1; k < 8; k++) u[k] = cmul(u[k], g_W2048[tmul * j * k]);
        } else {
            // DIT inverse: conj twiddle BEFORE inverse DFT8
#pragma unroll
            for (int k = 1; k < 8; k++) {
                float2 w = g_W2048[tmul * j * k]; w.y = -w.y;
                u[k] = cmul(u[k], w);
            }
            dft8(u, -1.f);
        }
#pragma unroll
        for (int k = 0; k < 8; k++) sm[row][PH(base + (k << ls))] = u[k];
    }
    __syncthreads();
}

__device__ __forceinline__ void k3_r4(float2 (*sm)[FAP], int nrow, int t, float sgn) {
    const int tot = nrow << 9;      // 512 quads per row
    for (int q = t; q < tot; q += NTHR) {
        int row = q >> 9, b = (q & 511) << 2;
        float2 u[4];
#pragma unroll
        for (int e = 0; e < 4; e++) u[e] = sm[row][PH(b + e)];
        dft4(u, sgn);
#pragma unroll
        for (int e = 0; e < 4; e++) sm[row][PH(b + e)] = u[e];
    }
    __syncthreads();
}

__device__ __forceinline__ float2 herm_P(float2 z1, float2 z2) {
    // DU = (z1 + conj z2)/2 ; B = -i/2 * (z1 - conj z2) ; P = DU*B
    float2 du = make_float2(0.5f * (z1.x + z2.x), 0.5f * (z1.y - z2.y));
    float2 bv = make_float2(0.5f * (z1.y + z2.y), -0.5f * (z1.x - z2.x));
    return cmul(du, bv);
}

// -------- K3: fwd DIF over a (+twiddle), pointwise in scrambled domain, inverse DIT
// Compact grid: 8193 blocks, every block active (pair enumerated in closed form).
__global__ __launch_bounds__(NTHR, 4)
void k3_core() {
    __shared__ float2 sm[2][FAP];   // ~33 KB
    const int t   = threadIdx.x;
    const int idx = blockIdx.x;
    int b1, c1;
    if (idx < 65)       { c1 = 0;  b1 = idx; }
    else if (idx < 129) { c1 = 64; b1 = idx - 65; }
    else                { int r = idx - 129; c1 = 1 + (r >> 7); b1 = r & 127; }
    const int h1 = b1 + (c1 << LB);
    int h2;
    if (c1 > 0)      h2 = (FB - 1 - b1) + ((FC - c1) << LB);
    else if (b1 > 0) h2 = FB - b1;
    else             h2 = 0;
    const bool self = (h1 == h2);
    const int  nrow = self ? 1 : 2;
    const int  b2 = h2 & (FB - 1), c2 = h2 >> LB;
    const int  hk1 = c1 + FC * b1;             // frequency weight c' + FC*b'
    const int  hk2 = c2 + FC * b2;

    // fused: float4 load + forward pre-twiddle W_N^{a*hk} (e < N, no mod: 2047*16383 < 2^25)
    for (int i = t; i < (nrow << (LA - 1)); i += NTHR) {
        int row = i >> (LA - 1);
        int aa  = (i & ((FA >> 1) - 1)) << 1;
        int hk  = row ? hk2 : hk1;
        float4 q4 = *reinterpret_cast<const float4*>(g_Z + (row ? h2 : h1) * FA + aa);
        int e0 = aa * hk, e1 = e0 + hk;
        float2 w0 = cmul(g_Whi[e0 >> 12], g_Wlo[e0 & 4095]);
        float2 w1 = cmul(g_Whi[e1 >> 12], g_Wlo[e1 & 4095]);
        sm[row][PH(aa)]     = cmul(make_float2(q4.x, q4.y), w0);
        sm[row][PH(aa + 1)] = cmul(make_float2(q4.z, q4.w), w1);
    }
    __syncthreads();

    // forward DIF: radix-8 x3 + radix-4 (output digit-scrambled: pos2048)
    k3_r8(sm, nrow, t, 8, 1,  0);   // sub-len 2048, span 256
    k3_r8(sm, nrow, t, 5, 8,  0);   // sub-len 256,  span 32
    k3_r8(sm, nrow, t, 2, 64, 0);   // sub-len 32,   span 4
    k3_r4(sm, nrow, t, 1.f);        // sub-len 4,    span 1

    // Hermitian pairing + pointwise multiply, scrambled positions
    if (!self) {
        for (int a1 = t; a1 < FA; a1 += NTHR) {
            int p1 = pos2048(a1), p2 = pos2048(FA - 1 - a1);
            float2 z1 = sm[0][PH(p1)];
            float2 z2 = sm[1][PH(p2)];
            float2 P  = herm_P(z1, z2);
            sm[0][PH(p1)] = P;
            sm[1][PH(p2)] = make_float2(P.x, -P.y);
        }
    } else if (h1 != 0) {                      // h == 64: partner a2 = FA-1-a1 in-chunk
        for (int a1 = t; a1 < FA / 2; a1 += NTHR) {
            int p1 = pos2048(a1), p2 = pos2048(FA - 1 - a1);
            float2 z1 = sm[0][PH(p1)];
            float2 z2 = sm[0][PH(p2)];
            float2 P  = herm_P(z1, z2);
            sm[0][PH(p1)] = P;
            sm[0][PH(p2)] = make_float2(P.x, -P.y);
        }
    } else {                                   // h == 0: partner a2 = (FA - a1) mod FA
        for (int a1 = t; a1 <= FA / 2; a1 += NTHR) {
            if (a1 == 0 || a1 == FA / 2) {
                int p = pos2048(a1);
                float2 z = sm[0][PH(p)];
                sm[0][PH(p)] = make_float2(z.x * z.y, 0.f);   // DU=Re(z), B=Im(z)
            } else {
                int p1 = pos2048(a1), p2 = pos2048(FA - a1);
                float2 z1 = sm[0][PH(p1)];
                float2 z2 = sm[0][PH(p2)];
                float2 P  = herm_P(z1, z2);
                sm[0][PH(p1)] = P;
                sm[0][PH(p2)] = make_float2(P.x, -P.y);
            }
        }
    }
    __syncthreads();

    // inverse DIT: mirror order, conj twiddles (scrambled in -> natural out)
    k3_r4(sm, nrow, t, -1.f);
    k3_r8(sm, nrow, t, 2, 64, 1);
    k3_r8(sm, nrow, t, 5, 8,  1);
    k3_r8(sm, nrow, t, 8, 1,  1);

    // fused: inverse post-twiddle conj(W_N^{a*hk}) + float4 store
    for (int i = t; i < (nrow << (LA - 1)); i += NTHR) {
        int row = i >> (LA - 1);
        int aa  = (i & ((FA >> 1) - 1)) << 1;
        int hk  = row ? hk2 : hk1;
        int e0 = aa * hk, e1 = e0 + hk;
        float2 w0 = cmul(g_Whi[e0 >> 12], g_Wlo[e0 & 4095]); w0.y = -w0.y;
        float2 w1 = cmul(g_Whi[e1 >> 12], g_Wlo[e1 & 4095]); w1.y = -w1.y;
        float2 v0 = cmul(sm[row][PH(aa)],     w0);
        float2 v1 = cmul(sm[row][PH(aa + 1)], w1);
        *reinterpret_cast<float4*>(g_Z + (row ? h2 : h1) * FA + aa) =
            make_float4(v0.x, v0.y, v1.x, v1.y);
    }
}

// -------- K5: inverse FFT over c' with stage-2 fused into the physics epilogue.
// Only even positions p (c = f128(p) < 64) are ever needed -> compute even half in regs.
__global__ __launch_bounds__(NTHR)
void k5_inv_epi(const float* __restrict__ up, float coefN) {
    __shared__ float2 tile[FC][GT + 1];
    __shared__ double red[NTHR];
    const int t   = threadIdx.x;
    const int ab0 = blockIdx.x * GT;

    for (int i = t; i < (FC * GT) / 2; i += NTHR) {
        int c  = i >> 4;
        int gg = (i & 15) << 1;
        float4 q4 = *reinterpret_cast<const float4*>(g_Z + ab0 + gg + AB * c);
        tile[c][gg]     = make_float2(q4.x, q4.y);
        tile[c][gg + 1] = make_float2(q4.z, q4.w);
    }
    __syncthreads();

    fft128_s1(tile, t, -1.f);

    // fused stage 2 (even outputs only) + epilogue
    float acc = 0.f;
    {
        int g = t & 31, m = t >> 5;            // m in [0,8)
        int base = m << 4;
        float2 e0[8], e1[8];
#pragma unroll
        for (int k = 0; k < 8; k++) {
            e0[k] = tile[base + (k << 1)][g];
            e1[k] = tile[base + (k << 1) + 1][g];
        }
        dft8(e0, -1.f); dft8(e1, -1.f);
#pragma unroll
        for (int k = 1; k < 8; k++) {
            float2 w = g_W128[k << 3]; w.y = -w.y;   // conj W16^k
            e1[k] = cmul(e1[k], w);
        }
#pragma unroll
        for (int k = 0; k < 8; k++) {
            float convr = e0[k].x + e1[k].x;          // even output, real part
            int c = m + (k << 3);                     // f128(16m + 2k) = m + 8k  (< 64)
            int n = ab0 + g + AB * c;                 // conv index
            int mres = n + 1;                         // frac[mres] = coef*conv[mres-1]
            if (mres < MTOT) {
                float um = __ldg(up + mres);
                float ut = 0.f;
                if ((mres & 16383) != 16383) ut = __ldg(up + mres + 1) - um;  // last col: u_t=0
                float r = ut - coefN * convr;
                acc = fmaf(r, r, acc);
            }
        }
    }

    red[t] = (double)acc;
    __syncthreads();
    for (int s = NTHR / 2; s > 0; s >>= 1) { if (t < s) red[t] += red[t + s]; __syncthreads(); }
    if (t == 0) g_phys[blockIdx.x] = red[0];
}

// -------- finalize
__global__ void k_fin(const float* __restrict__ up, float* __restrict__ out) {
    __shared__ double rp[256], rd[256];
    int t = threadIdx.x;
    double sp = 0.0, sd = 0.0;
    for (int i = t; i < NBLK; i += 256) { sp += g_phys[i]; sd += g_data[i]; }
    rp[t] = sp; rd[t] = sd;
    __syncthreads();
    for (int s = 128; s > 0; s >>= 1) {
        if (t < s) { rp[t] += rp[t + s]; rd[t] += rd[t + s]; }
        __syncthreads();
    }
    if (t == 0) {
        double r0 = (double)up[1] - (double)up[0];    // m = 0 residual: u_t[0] - 0
        double phys = (rp[0] + r0 * r0) / (double)MTOT;
        double data = rd[0] / (double)MTOT;
        out[0] = (float)(data + 0.1 * phys);
        out[1] = (float)data;
        out[2] = (float)phys;
    }
}

extern "C" void kernel_launch(void* const* d_in, const int* in_sizes, int n_in,
                              void* d_out, int out_size)
{
    const float* up  = (const float*)d_in[0];  // u_pred
    const float* utr = (const float*)d_in[1];  // u_true
    (void)in_sizes; (void)n_in; (void)out_size;

    // coef = sqrt(M-1)/Gamma(1.5); fold the 1/N of the fwd+inv FFT product in here.
    double coefN = sqrt((double)(MTOT - 1)) / 0.886226925452758013649083741670572
                   / (double)NF;

    k_tw<<<64, 256>>>();
    k1_pack_fft<<<NBLK, NTHR>>>(up, utr);
    k2_fftb<1><<<NBLK, NTHR>>>();
    k3_core<<<8193, NTHR>>>();
    k2_fftb<0><<<NBLK, NTHR>>>();
    k5_inv_epi<<<NBLK, NTHR>>>(up, (float)coefN);
    k_fin<<<1, 256>>>(up, (float*)d_out);
}

// round 9
// speedup vs baseline: 2.9648x; 1.2032x over previous
#include <cuda_runtime.h>
#include <math.h>

// FFT size N = 2^25 = FA * FB * FC, position n = a + FA*b + AB*c
#define LN   25
#define NF   (1 << LN)
#define LA   11
#define FA   (1 << LA)          // 2048
#define LB   7
#define FB   (1 << LB)          // 128
#define LC   7
#define FC   (1 << LC)          // 128
#define AB   (FA * FB)          // 262144
#define GT   32                 // tile width (consecutive fast-dim elements)
#define NTHR 256

#define MTOT (1 << 24)          // problem size B*N = 2^24
#define NBLK (AB / GT)          // 8192 blocks for K1/K5

// XOR swizzle for k3 smem: flips element bits [1:4) from bits [4:7).
// Bijective, preserves 2-element (16B) alignment -> float4-safe.
#define SW(p) ((p) ^ ((((p) >> 4) & 7) << 1))

// 256 MB spectral work buffer + twiddle tables + partials (no runtime allocation)
__device__ float2 g_Z[NF];
__device__ float2 g_W16384[16384];  // W_16384^m (full)
__device__ float2 g_W2048[2048];    // W_2048^m  (full)
__device__ float2 g_W128[128];      // W_128^m   (full)
__device__ float2 g_Wlo[4096];      // W_N^j,        j < 4096
__device__ float2 g_Whi[8192];      // W_N^{4096 j}, j < 8192
__device__ double g_data[NBLK];
__device__ double g_phys[NBLK];

__device__ __forceinline__ float2 cadd(float2 a, float2 b) { return make_float2(a.x + b.x, a.y + b.y); }
__device__ __forceinline__ float2 csub(float2 a, float2 b) { return make_float2(a.x - b.x, a.y - b.y); }
__device__ __forceinline__ float2 cmul(float2 a, float2 b) {
    return make_float2(fmaf(a.x, b.x, -a.y * b.y), fmaf(a.x, b.y, a.y * b.x));
}
// multiply by -i (sgn=+1, forward) or +i (sgn=-1, inverse)
__device__ __forceinline__ float2 crot(float2 a, float sgn) { return make_float2(sgn * a.y, -sgn * a.x); }

// 8-point DFT in registers, natural-order outputs. sgn=+1 fwd, -1 inverse (unnormalized).
__device__ __forceinline__ void dft8(float2* u, float sgn) {
    const float C = 0.70710678118654752440f;
    float2 t0 = cadd(u[0], u[4]), t1 = cadd(u[1], u[5]);
    float2 t2 = cadd(u[2], u[6]), t3 = cadd(u[3], u[7]);
    float2 m4 = csub(u[0], u[4]), m5 = csub(u[1], u[5]);
    float2 m6 = csub(u[2], u[6]), m7 = csub(u[3], u[7]);
    float2 t4 = m4;
    float2 t5 = cmul(m5, make_float2(C, -sgn * C));    // W8^1
    float2 t6 = crot(m6, sgn);                         // W8^2
    float2 t7 = cmul(m7, make_float2(-C, -sgn * C));   // W8^3
    float2 s0 = cadd(t0, t2), s2 = csub(t0, t2);
    float2 s1 = cadd(t1, t3), s3 = crot(csub(t1, t3), sgn);
    float2 r0 = cadd(t4, t6), r2 = csub(t4, t6);
    float2 r1 = cadd(t5, t7), r3 = crot(csub(t5, t7), sgn);
    u[0] = cadd(s0, s1); u[4] = csub(s0, s1);
    u[2] = cadd(s2, s3); u[6] = csub(s2, s3);
    u[1] = cadd(r0, r1); u[5] = csub(r0, r1);
    u[3] = cadd(r2, r3); u[7] = csub(r2, r3);
}

// 8-point DFT with inputs 4..7 known to be zero (k1 zero-padding). In: u[0..3]; out: u[0..7].
__device__ __forceinline__ void dft8h(float2* u, float sgn) {
    const float C = 0.70710678118654752440f;
    float2 t0 = u[0], t1 = u[1], t2 = u[2], t3 = u[3];
    float2 t4 = u[0];
    float2 t5 = cmul(u[1], make_float2(C, -sgn * C));
    float2 t6 = crot(u[2], sgn);
    float2 t7 = cmul(u[3], make_float2(-C, -sgn * C));
    float2 s0 = cadd(t0, t2), s2 = csub(t0, t2);
    float2 s1 = cadd(t1, t3), s3 = crot(csub(t1, t3), sgn);
    float2 r0 = cadd(t4, t6), r2 = csub(t4, t6);
    float2 r1 = cadd(t5, t7), r3 = crot(csub(t5, t7), sgn);
    u[0] = cadd(s0, s1); u[4] = csub(s0, s1);
    u[2] = cadd(s2, s3); u[6] = csub(s2, s3);
    u[1] = cadd(r0, r1); u[5] = csub(r0, r1);
    u[3] = cadd(r2, r3); u[7] = csub(r2, r3);
}

// 4-point DFT in registers, natural order.
__device__ __forceinline__ void dft4(float2* u, float sgn) {
    float2 a0 = cadd(u[0], u[2]), b0 = csub(u[0], u[2]);
    float2 a1 = cadd(u[1], u[3]), b1 = crot(csub(u[1], u[3]), sgn);
    u[0] = cadd(a0, a1); u[2] = csub(a0, a1);
    u[1] = cadd(b0, b1); u[3] = csub(b0, b1);
}

// digit-reversal maps
// 128 = 8*8*2 DIF: position p -> natural frequency
__device__ __forceinline__ int f128(int p) {
    return (p >> 4) + (((p >> 1) & 7) << 3) + ((p & 1) << 6);
}
// 2048 = 8*8*8*4 DIF: natural frequency k -> scrambled position
__device__ __forceinline__ int pos2048(int k) {
    return ((k & 7) << 8) + (((k >> 3) & 7) << 5) + (((k >> 6) & 7) << 2) + (k >> 9);
}

// ---------------------------------------------------------------- twiddle init
__global__ void k_tw() {
    int idx = blockIdx.x * 256 + threadIdx.x;   // 64 blocks * 256 = 16384
    const double P2 = 6.283185307179586476925286766559;
    if (idx < 16384) { double a = -P2 * idx / 16384.0;    g_W16384[idx] = make_float2((float)cos(a), (float)sin(a)); }
    if (idx < 8192)  { double a = -P2 * idx / 8192.0;     g_Whi[idx]    = make_float2((float)cos(a), (float)sin(a)); }
    if (idx < 4096)  { double a = -P2 * idx / (double)NF; g_Wlo[idx]    = make_float2((float)cos(a), (float)sin(a)); }
    if (idx < 2048)  { double a = -P2 * idx / 2048.0;     g_W2048[idx]  = make_float2((float)cos(a), (float)sin(a)); }
    if (idx < 128)   { double a = -P2 * idx / 128.0;      g_W128[idx]   = make_float2((float)cos(a), (float)sin(a)); }
}

// -------------------------------------------------------------------------
// 128-pt DIF FFT over slow axis of tile[128][GT+1], 32 transforms (one per g).
// TWO smem sweeps: radix-8 (span 16) + fused register-resident 16-point.
// Output digit-scrambled: natural freq of position p is f128(p).
// -------------------------------------------------------------------------
__device__ __forceinline__ void fft128_s1(float2 (*tile)[GT + 1], int t, float sgn) {
    for (int q = t; q < 512; q += NTHR) {
        int g = q & 31, j = q >> 5;            // j in [0,16)
        float2 u[8];
#pragma unroll
        for (int k = 0; k < 8; k++) u[k] = tile[j + (k << 4)][g];
        dft8(u, sgn);
#pragma unroll
        for (int k = 1; k < 8; k++) {
            float2 w = g_W128[j * k]; w.y *= sgn;
            u[k] = cmul(u[k], w);
        }
#pragma unroll
        for (int k = 0; k < 8; k++) tile[j + (k << 4)][g] = u[k];
    }
    __syncthreads();
}

// stage 2: full 16-pt transform in registers per 16-block (m = t>>5, g = t&31)
__device__ __forceinline__ void fft128_s2(float2 (*tile)[GT + 1], int t, float sgn) {
    int g = t & 31, m = t >> 5;                // exactly 256 work items
    int base = m << 4;
    float2 e0[8], e1[8];
#pragma unroll
    for (int k = 0; k < 8; k++) {
        e0[k] = tile[base + (k << 1)][g];
        e1[k] = tile[base + (k << 1) + 1][g];
    }
    dft8(e0, sgn); dft8(e1, sgn);
#pragma unroll
    for (int k = 1; k < 8; k++) {
        float2 w = g_W128[k << 3]; w.y *= sgn; // W16^k
        e1[k] = cmul(e1[k], w);
    }
#pragma unroll
    for (int k = 0; k < 8; k++) {
        tile[base + (k << 1)][g]     = cadd(e0[k], e1[k]);
        tile[base + (k << 1) + 1][g] = csub(e0[k], e1[k]);
    }
    __syncthreads();
}

// ------------------------------------- K1: pack Z = du + i*b, FFT over c, data loss
// Input rows c >= 64 are structurally zero (n >= MTOT) -> half-input stage 1.
__global__ __launch_bounds__(NTHR)
void k1_pack_fft(const float* __restrict__ up, const float* __restrict__ utr) {
    __shared__ float2 tile[FC][GT + 1];
    __shared__ double red[NTHR];
    const int t   = threadIdx.x;
    const int ab0 = blockIdx.x * GT;

    // load rows c < 64 only, float4-vectorized (4 g per thread)
    float acc = 0.f;
    for (int i = t; i < (GT / 4) * 64; i += NTHR) {      // 512 items
        int c  = i >> 3;
        int gq = (i & 7) << 2;
        int n  = ab0 + gq + AB * c;                      // n+3 < MTOT guaranteed (c<64)
        float4 a4 = *reinterpret_cast<const float4*>(up + n);
        float4 b4 = *reinterpret_cast<const float4*>(utr + n);
        float d0 = a4.x - b4.x, d1 = a4.y - b4.y, d2 = a4.z - b4.z, d3 = a4.w - b4.w;
        acc = fmaf(d0, d0, acc); acc = fmaf(d1, d1, acc);
        acc = fmaf(d2, d2, acc); acc = fmaf(d3, d3, acc);
        float unext = (n + 4 < MTOT) ? __ldg(up + n + 4) : 0.f;
        float du0 = a4.y - a4.x, du1 = a4.z - a4.y, du2 = a4.w - a4.z, du3 = unext - a4.w;
        // EXACT replica of the reference fp32 weights (incl. cancellation noise)
        float bw0 = __fsqrt_rn((float)(n + 1)) - __fsqrt_rn((float)n);
        float bw1 = __fsqrt_rn((float)(n + 2)) - __fsqrt_rn((float)(n + 1));
        float bw2 = __fsqrt_rn((float)(n + 3)) - __fsqrt_rn((float)(n + 2));
        float bw3 = __fsqrt_rn((float)(n + 4)) - __fsqrt_rn((float)(n + 3));
        if (n + 3 >= MTOT - 1) {                          // only last elements of last block
            if (n + 0 >= MTOT - 1) { du0 = 0.f; bw0 = 0.f; }
            if (n + 1 >= MTOT - 1) { du1 = 0.f; bw1 = 0.f; }
            if (n + 2 >= MTOT - 1) { du2 = 0.f; bw2 = 0.f; }
            du3 = 0.f; bw3 = 0.f;
        }
        tile[c][gq + 0] = make_float2(du0, bw0);
        tile[c][gq + 1] = make_float2(du1, bw1);
        tile[c][gq + 2] = make_float2(du2, bw2);
        tile[c][gq + 3] = make_float2(du3, bw3);
    }
    __syncthreads();

    // stage 1 with zero top half: reads rows j+16k for k<4 (all < 64)
    for (int q = t; q < 512; q += NTHR) {
        int g = q & 31, j = q >> 5;
        float2 u[8];
#pragma unroll
        for (int k = 0; k < 4; k++) u[k] = tile[j + (k << 4)][g];
        dft8h(u, 1.f);
#pragma unroll
        for (int k = 1; k < 8; k++) {
            float2 w = g_W128[j * k];
            u[k] = cmul(u[k], w);
        }
#pragma unroll
        for (int k = 0; k < 8; k++) tile[j + (k << 4)][g] = u[k];
    }
    __syncthreads();

    fft128_s2(tile, t, 1.f);

    // store with digit-reversal folded into slab index, float4 (2 complex) per store
    for (int i = t; i < (FC * GT) / 2; i += NTHR) {      // 2048 items
        int p  = i >> 4;
        int gg = (i & 15) << 1;
        float2 v0 = tile[p][gg], v1 = tile[p][gg + 1];
        *reinterpret_cast<float4*>(g_Z + ab0 + gg + AB * f128(p)) =
            make_float4(v0.x, v0.y, v1.x, v1.y);
    }

    red[t] = (double)acc;
    __syncthreads();
    for (int s = NTHR / 2; s > 0; s >>= 1) { if (t < s) red[t] += red[t + s]; __syncthreads(); }
    if (t == 0) g_data[blockIdx.x] = red[0];
}

// ---------------------- K2/K4: FFT over b (stride FA), twiddle W_16384^{b c'}
template<int FWD>
__global__ __launch_bounds__(NTHR)
void k2_fftb() {
    __shared__ float2 tile[FB][GT + 1];
    const int t  = threadIdx.x;
    const int cp = blockIdx.x >> 6;             // c' ; FA/GT = 64
    const int a0 = (blockIdx.x & 63) * GT;

    for (int i = t; i < (FB * GT) / 2; i += NTHR) {
        int b  = i >> 4;
        int gg = (i & 15) << 1;
        float4 q4 = *reinterpret_cast<const float4*>(g_Z + a0 + gg + FA * b + AB * cp);
        float2 v0 = make_float2(q4.x, q4.y), v1 = make_float2(q4.z, q4.w);
        if (FWD) {
            float2 w = g_W16384[b * cp];        // pre-twiddle (forward)
            v0 = cmul(v0, w); v1 = cmul(v1, w);
        }
        tile[b][gg] = v0; tile[b][gg + 1] = v1;
    }
    __syncthreads();

    fft128_s1(tile, t, FWD ? 1.f : -1.f);
    fft128_s2(tile, t, FWD ? 1.f : -1.f);

    for (int i = t; i < (FB * GT) / 2; i += NTHR) {
        int p  = i >> 4;
        int gg = (i & 15) << 1;
        int bb = f128(p);                       // natural output index
        float2 v0 = tile[p][gg], v1 = tile[p][gg + 1];
        if (!FWD) {                             // post-twiddle (inverse)
            float2 w = g_W16384[bb * cp]; w.y = -w.y;
            v0 = cmul(v0, w); v1 = cmul(v1, w);
        }
        *reinterpret_cast<float4*>(g_Z + a0 + gg + FA * bb + AB * cp) =
            make_float4(v0.x, v0.y, v1.x, v1.y);
    }
}

// -------- K3 stage helpers: 2048 = 8*8*8*4, XOR-swizzled smem layout SW()
__device__ __forceinline__ void k3_r8(float2 (*sm)[FA], int nrow, int t,
                                      int ls, int tmul, int inv) {
    const int s   = 1 << ls;
    const int tot = nrow << 8;      // 256 butterflies per row
    for (int q = t; q < tot; q += NTHR) {
        int row = q >> 8, qq = q & 255;
        int j = qq & (s - 1), m = qq >> ls;
        int base = (m << (ls + 3)) + j;
        float2 u[8];
#pragma unroll
        for (int k = 0; k < 8; k++) u[k] = sm[row][SW(base + (k << ls))];
        if (!inv) {
            dft8(u, 1.f);
#pragma unroll
            for (int k = 1; k < 8; k++) u[k] = cmul(u[k], g_W2048[tmul * j * k]);
        } else {
            // DIT inverse: conj twiddle BEFORE inverse DFT8
#pragma unroll
            for (int k = 1; k < 8; k++) {
                float2 w = g_W2048[tmul * j * k]; w.y = -w.y;
                u[k] = cmul(u[k], w);
            }
            dft8(u, -1.f);
        }
#pragma unroll
        for (int k = 0; k < 8; k++) sm[row][SW(base + (k << ls))] = u[k];
    }
    __syncthreads();
}

// radix-4 span-1: 4 consecutive elements per butterfly, via 2x float4 (conflict-free under SW)
__device__ __forceinline__ void k3_r4(float2 (*sm)[FA], int nrow, int t, float sgn) {
    const int tot = nrow << 9;      // 512 quads per row
    for (int q = t; q < tot; q += NTHR) {
        int row = q >> 9, b = (q & 511) << 2;
        float2* rowp = sm[row];
        float4 lo = *reinterpret_cast<const float4*>(&rowp[SW(b)]);
        float4 hi = *reinterpret_cast<const float4*>(&rowp[SW(b + 2)]);
        float2 u[4] = { make_float2(lo.x, lo.y), make_float2(lo.z, lo.w),
                        make_float2(hi.x, hi.y), make_float2(hi.z, hi.w) };
        dft4(u, sgn);
        *reinterpret_cast<float4*>(&rowp[SW(b)])     = make_float4(u[0].x, u[0].y, u[1].x, u[1].y);
        *reinterpret_cast<float4*>(&rowp[SW(b + 2)]) = make_float4(u[2].x, u[2].y, u[3].x, u[3].y);
    }
    __syncthreads();
}

__device__ __forceinline__ float2 herm_P(float2 z1, float2 z2) {
    // DU = (z1 + conj z2)/2 ; B = -i/2 * (z1 - conj z2) ; P = DU*B
    float2 du = make_float2(0.5f * (z1.x + z2.x), 0.5f * (z1.y - z2.y));
    float2 bv = make_float2(0.5f * (z1.y + z2.y), -0.5f * (z1.x - z2.x));
    return cmul(du, bv);
}

// -------- K3: fwd DIF over a (+twiddle), pointwise in scrambled domain, inverse DIT
// Compact grid: 8193 blocks, every block active (pair enumerated in closed form).
// Pairing identity: pos2048(2047 - f) == 2047 - pos2048(f)  (all digits complement)
// -> partner of POSITION p is 2047 - p, so the pairing sweep is lane-consecutive.
__global__ __launch_bounds__(NTHR)
void k3_core() {
    __shared__ __align__(16) float2 sm[2][FA];   // 32 KB, XOR-swizzled
    const int t   = threadIdx.x;
    const int idx = blockIdx.x;
    int b1, c1;
    if (idx < 65)       { c1 = 0;  b1 = idx; }
    else if (idx < 129) { c1 = 64; b1 = idx - 65; }
    else                { int r = idx - 129; c1 = 1 + (r >> 7); b1 = r & 127; }
    const int h1 = b1 + (c1 << LB);
    int h2;
    if (c1 > 0)      h2 = (FB - 1 - b1) + ((FC - c1) << LB);
    else if (b1 > 0) h2 = FB - b1;
    else             h2 = 0;
    const bool self = (h1 == h2);
    const int  nrow = self ? 1 : 2;
    const int  b2 = h2 & (FB - 1), c2 = h2 >> LB;
    const int  hk1 = c1 + FC * b1;             // frequency weight c' + FC*b'
    const int  hk2 = c2 + FC * b2;

    // fused: float4 load + forward pre-twiddle W_N^{a*hk} (e < N, no mod: 2047*16383 < 2^25)
    for (int i = t; i < (nrow << (LA - 1)); i += NTHR) {
        int row = i >> (LA - 1);
        int aa  = (i & ((FA >> 1) - 1)) << 1;
        int hk  = row ? hk2 : hk1;
        float4 q4 = *reinterpret_cast<const float4*>(g_Z + (row ? h2 : h1) * FA + aa);
        int e0 = aa * hk, e1 = e0 + hk;
        float2 w0 = cmul(g_Whi[e0 >> 12], g_Wlo[e0 & 4095]);
        float2 w1 = cmul(g_Whi[e1 >> 12], g_Wlo[e1 & 4095]);
        float2 v0 = cmul(make_float2(q4.x, q4.y), w0);
        float2 v1 = cmul(make_float2(q4.z, q4.w), w1);
        *reinterpret_cast<float4*>(&sm[row][SW(aa)]) = make_float4(v0.x, v0.y, v1.x, v1.y);
    }
    __syncthreads();

    // forward DIF: radix-8 x3 + radix-4 (output digit-scrambled: pos2048)
    k3_r8(sm, nrow, t, 8, 1,  0);   // sub-len 2048, span 256
    k3_r8(sm, nrow, t, 5, 8,  0);   // sub-len 256,  span 32
    k3_r8(sm, nrow, t, 2, 64, 0);   // sub-len 32,   span 4
    k3_r4(sm, nrow, t, 1.f);        // sub-len 4,    span 1

    // Hermitian pairing + pointwise multiply — POSITION space, lane-consecutive
    if (!self) {
        for (int p = t; p < FA; p += NTHR) {
            float2 z1 = sm[0][SW(p)];
            float2 z2 = sm[1][SW(FA - 1 - p)];
            float2 P  = herm_P(z1, z2);
            sm[0][SW(p)]          = P;
            sm[1][SW(FA - 1 - p)] = make_float2(P.x, -P.y);
        }
    } else if (h1 != 0) {                      // h == 64: partner position = 2047 - p
        for (int p = t; p < FA / 2; p += NTHR) {
            float2 z1 = sm[0][SW(p)];
            float2 z2 = sm[0][SW(FA - 1 - p)];
            float2 P  = herm_P(z1, z2);
            sm[0][SW(p)]          = P;
            sm[0][SW(FA - 1 - p)] = make_float2(P.x, -P.y);
        }
    } else {                                   // h == 0: partner f2 = (FA - f1) mod FA (single block)
        for (int a1 = t; a1 <= FA / 2; a1 += NTHR) {
            if (a1 == 0 || a1 == FA / 2) {
                int p = pos2048(a1);
                float2 z = sm[0][SW(p)];
                sm[0][SW(p)] = make_float2(z.x * z.y, 0.f);   // DU=Re(z), B=Im(z)
            } else {
                int p1 = pos2048(a1), p2 = pos2048(FA - a1);
                float2 z1 = sm[0][SW(p1)];
                float2 z2 = sm[0][SW(p2)];
                float2 P  = herm_P(z1, z2);
                sm[0][SW(p1)] = P;
                sm[0][SW(p2)] = make_float2(P.x, -P.y);
            }
        }
    }
    __syncthreads();

    // inverse DIT: mirror order, conj twiddles (scrambled in -> natural out)
    k3_r4(sm, nrow, t, -1.f);
    k3_r8(sm, nrow, t, 2, 64, 1);
    k3_r8(sm, nrow, t, 5, 8,  1);
    k3_r8(sm, nrow, t, 8, 1,  1);

    // fused: inverse post-twiddle conj(W_N^{a*hk}) + float4 store
    for (int i = t; i < (nrow << (LA - 1)); i += NTHR) {
        int row = i >> (LA - 1);
        int aa  = (i & ((FA >> 1) - 1)) << 1;
        int hk  = row ? hk2 : hk1;
        int e0 = aa * hk, e1 = e0 + hk;
        float2 w0 = cmul(g_Whi[e0 >> 12], g_Wlo[e0 & 4095]); w0.y = -w0.y;
        float2 w1 = cmul(g_Whi[e1 >> 12], g_Wlo[e1 & 4095]); w1.y = -w1.y;
        float4 q4 = *reinterpret_cast<const float4*>(&sm[row][SW(aa)]);
        float2 v0 = cmul(make_float2(q4.x, q4.y), w0);
        float2 v1 = cmul(make_float2(q4.z, q4.w), w1);
        *reinterpret_cast<float4*>(g_Z + (row ? h2 : h1) * FA + aa) =
            make_float4(v0.x, v0.y, v1.x, v1.y);
    }
}

// -------- K5: inverse FFT over c' with stage-2 fused into the physics epilogue.
// Only even positions p (c = f128(p) < 64) are ever needed -> compute even half in regs.
__global__ __launch_bounds__(NTHR)
void k5_inv_epi(const float* __restrict__ up, float coefN) {
    __shared__ float2 tile[FC][GT + 1];
    __shared__ double red[NTHR];
    const int t   = threadIdx.x;
    const int ab0 = blockIdx.x * GT;

    for (int i = t; i < (FC * GT) / 2; i += NTHR) {
        int c  = i >> 4;
        int gg = (i & 15) << 1;
        float4 q4 = *reinterpret_cast<const float4*>(g_Z + ab0 + gg + AB * c);
        tile[c][gg]     = make_float2(q4.x, q4.y);
        tile[c][gg + 1] = make_float2(q4.z, q4.w);
    }
    __syncthreads();

    fft128_s1(tile, t, -1.f);

    // fused stage 2 (even outputs only) + epilogue
    float acc = 0.f;
    {
        int g = t & 31, m = t >> 5;            // m in [0,8)
        int base = m << 4;
        float2 e0[8], e1[8];
#pragma unroll
        for (int k = 0; k < 8; k++) {
            e0[k] = tile[base + (k << 1)][g];
            e1[k] = tile[base + (k << 1) + 1][g];
        }
        dft8(e0, -1.f); dft8(e1, -1.f);
#pragma unroll
        for (int k = 1; k < 8; k++) {
            float2 w = g_W128[k << 3]; w.y = -w.y;   // conj W16^k
            e1[k] = cmul(e1[k], w);
        }
#pragma unroll
        for (int k = 0; k < 8; k++) {
            float convr = e0[k].x + e1[k].x;          // even output, real part
            int c = m + (k << 3);                     // f128(16m + 2k) = m + 8k  (< 64)
            int n = ab0 + g + AB * c;                 // conv index
            int mres = n + 1;                         // frac[mres] = coef*conv[mres-1]
            if (mres < MTOT) {
                float um = __ldg(up + mres);
                float ut = 0.f;
                if ((mres & 16383) != 16383) ut = __ldg(up + mres + 1) - um;  // last col: u_t=0
                float r = ut - coefN * convr;
                acc = fmaf(r, r, acc);
            }
        }
    }

    red[t] = (double)acc;
    __syncthreads();
    for (int s = NTHR / 2; s > 0; s >>= 1) { if (t < s) red[t] += red[t + s]; __syncthreads(); }
    if (t == 0) g_phys[blockIdx.x] = red[0];
}

// -------- finalize
__global__ void k_fin(const float* __restrict__ up, float* __restrict__ out) {
    __shared__ double rp[256], rd[256];
    int t = threadIdx.x;
    double sp = 0.0, sd = 0.0;
    for (int i = t; i < NBLK; i += 256) { sp += g_phys[i]; sd += g_data[i]; }
    rp[t] = sp; rd[t] = sd;
    __syncthreads();
    for (int s = 128; s > 0; s >>= 1) {
        if (t < s) { rp[t] += rp[t + s]; rd[t] += rd[t + s]; }
        __syncthreads();
    }
    if (t == 0) {
        double r0 = (double)up[1] - (double)up[0];    // m = 0 residual: u_t[0] - 0
        double phys = (rp[0] + r0 * r0) / (double)MTOT;
        double data = rd[0] / (double)MTOT;
        out[0] = (float)(data + 0.1 * phys);
        out[1] = (float)data;
        out[2] = (float)phys;
    }
}

extern "C" void kernel_launch(void* const* d_in, const int* in_sizes, int n_in,
                              void* d_out, int out_size)
{
    const float* up  = (const float*)d_in[0];  // u_pred
    const float* utr = (const float*)d_in[1];  // u_true
    (void)in_sizes; (void)n_in; (void)out_size;

    // coef = sqrt(M-1)/Gamma(1.5); fold the 1/N of the fwd+inv FFT product in here.
    double coefN = sqrt((double)(MTOT - 1)) / 0.886226925452758013649083741670572
                   / (double)NF;

    k_tw<<<64, 256>>>();
    k1_pack_fft<<<NBLK, NTHR>>>(up, utr);
    k2_fftb<1><<<NBLK, NTHR>>>();
    k3_core<<<8193, NTHR>>>();
    k2_fftb<0><<<NBLK, NTHR>>>();
    k5_inv_epi<<<NBLK, NTHR>>>(up, (float)coefN);
    k_fin<<<1, 256>>>(up, (float*)d_out);
}

// round 10
// speedup vs baseline: 3.5103x; 1.1840x over previous
#include <cuda_runtime.h>
#include <math.h>

// FFT size N = 2^25 = FA * FB * FC, position n = a + FA*b + AB*c
#define LN   25
#define NF   (1 << LN)
#define LA   11
#define FA   (1 << LA)          // 2048
#define LB   7
#define FB   (1 << LB)          // 128
#define LC   7
#define FC   (1 << LC)          // 128
#define AB   (FA * FB)          // 262144
#define GT   32                 // tile width (consecutive fast-dim elements)
#define NTHR 256

#define MTOT (1 << 24)          // problem size B*N = 2^24
#define NBLK (AB / GT)          // 8192 blocks for K1/K5

// XOR swizzle for k3 smem: flips element bits [1:4) from bits [4:7).
// Bijective, preserves 2-element (16B) alignment -> float4-safe.
#define SW(p) ((p) ^ ((((p) >> 4) & 7) << 1))

// 256 MB spectral work buffer + twiddle tables + partials (no runtime allocation)
__device__ float2 g_Z[NF];
__device__ float2 g_W16384[16384];  // W_16384^m (full)
__device__ float2 g_W2048[2048];    // W_2048^m  (full)
__device__ float2 g_W128[128];      // W_128^m   (full)
__device__ float2 g_Wlo[4096];      // W_N^j,        j < 4096
__device__ float2 g_Whi[8192];      // W_N^{4096 j}, j < 8192
__device__ double g_data[NBLK];
__device__ double g_phys[NBLK];

__device__ __forceinline__ float2 cadd(float2 a, float2 b) { return make_float2(a.x + b.x, a.y + b.y); }
__device__ __forceinline__ float2 csub(float2 a, float2 b) { return make_float2(a.x - b.x, a.y - b.y); }
__device__ __forceinline__ float2 cmul(float2 a, float2 b) {
    return make_float2(fmaf(a.x, b.x, -a.y * b.y), fmaf(a.x, b.y, a.y * b.x));
}
// multiply by -i (sgn=+1, forward) or +i (sgn=-1, inverse)
__device__ __forceinline__ float2 crot(float2 a, float sgn) { return make_float2(sgn * a.y, -sgn * a.x); }

// 8-point DFT in registers, natural-order outputs. sgn=+1 fwd, -1 inverse (unnormalized).
__device__ __forceinline__ void dft8(float2* u, float sgn) {
    const float C = 0.70710678118654752440f;
    float2 t0 = cadd(u[0], u[4]), t1 = cadd(u[1], u[5]);
    float2 t2 = cadd(u[2], u[6]), t3 = cadd(u[3], u[7]);
    float2 m4 = csub(u[0], u[4]), m5 = csub(u[1], u[5]);
    float2 m6 = csub(u[2], u[6]), m7 = csub(u[3], u[7]);
    float2 t4 = m4;
    float2 t5 = cmul(m5, make_float2(C, -sgn * C));    // W8^1
    float2 t6 = crot(m6, sgn);                         // W8^2
    float2 t7 = cmul(m7, make_float2(-C, -sgn * C));   // W8^3
    float2 s0 = cadd(t0, t2), s2 = csub(t0, t2);
    float2 s1 = cadd(t1, t3), s3 = crot(csub(t1, t3), sgn);
    float2 r0 = cadd(t4, t6), r2 = csub(t4, t6);
    float2 r1 = cadd(t5, t7), r3 = crot(csub(t5, t7), sgn);
    u[0] = cadd(s0, s1); u[4] = csub(s0, s1);
    u[2] = cadd(s2, s3); u[6] = csub(s2, s3);
    u[1] = cadd(r0, r1); u[5] = csub(r0, r1);
    u[3] = cadd(r2, r3); u[7] = csub(r2, r3);
}

// 8-point DFT with inputs 4..7 known to be zero (k1 zero-padding). In: u[0..3]; out: u[0..7].
__device__ __forceinline__ void dft8h(float2* u, float sgn) {
    const float C = 0.70710678118654752440f;
    float2 t0 = u[0], t1 = u[1], t2 = u[2], t3 = u[3];
    float2 t4 = u[0];
    float2 t5 = cmul(u[1], make_float2(C, -sgn * C));
    float2 t6 = crot(u[2], sgn);
    float2 t7 = cmul(u[3], make_float2(-C, -sgn * C));
    float2 s0 = cadd(t0, t2), s2 = csub(t0, t2);
    float2 s1 = cadd(t1, t3), s3 = crot(csub(t1, t3), sgn);
    float2 r0 = cadd(t4, t6), r2 = csub(t4, t6);
    float2 r1 = cadd(t5, t7), r3 = crot(csub(t5, t7), sgn);
    u[0] = cadd(s0, s1); u[4] = csub(s0, s1);
    u[2] = cadd(s2, s3); u[6] = csub(s2, s3);
    u[1] = cadd(r0, r1); u[5] = csub(r0, r1);
    u[3] = cadd(r2, r3); u[7] = csub(r2, r3);
}

// 4-point DFT in registers, natural order.
__device__ __forceinline__ void dft4(float2* u, float sgn) {
    float2 a0 = cadd(u[0], u[2]), b0 = csub(u[0], u[2]);
    float2 a1 = cadd(u[1], u[3]), b1 = crot(csub(u[1], u[3]), sgn);
    u[0] = cadd(a0, a1); u[2] = csub(a0, a1);
    u[1] = cadd(b0, b1); u[3] = csub(b0, b1);
}

// apply w^k (k=1..7) to u[1..7] via cmul chain from a single loaded w1
__device__ __forceinline__ void twiddle_chain8(float2* u, float2 w1) {
    float2 w = w1;
    u[1] = cmul(u[1], w);
#pragma unroll
    for (int k = 2; k < 8; k++) { w = cmul(w, w1); u[k] = cmul(u[k], w); }
}

// digit-reversal maps
// 128 = 8*8*2 DIF: position p -> natural frequency
__device__ __forceinline__ int f128(int p) {
    return (p >> 4) + (((p >> 1) & 7) << 3) + ((p & 1) << 6);
}
// 2048 = 8*8*8*4 DIF: natural frequency k -> scrambled position
__device__ __forceinline__ int pos2048(int k) {
    return ((k & 7) << 8) + (((k >> 3) & 7) << 5) + (((k >> 6) & 7) << 2) + (k >> 9);
}

// ---------------------------------------------------------------- twiddle init
__global__ void k_tw() {
    int idx = blockIdx.x * 256 + threadIdx.x;   // 64 blocks * 256 = 16384
    const double P2 = 6.283185307179586476925286766559;
    if (idx < 16384) { double a = -P2 * idx / 16384.0;    g_W16384[idx] = make_float2((float)cos(a), (float)sin(a)); }
    if (idx < 8192)  { double a = -P2 * idx / 8192.0;     g_Whi[idx]    = make_float2((float)cos(a), (float)sin(a)); }
    if (idx < 4096)  { double a = -P2 * idx / (double)NF; g_Wlo[idx]    = make_float2((float)cos(a), (float)sin(a)); }
    if (idx < 2048)  { double a = -P2 * idx / 2048.0;     g_W2048[idx]  = make_float2((float)cos(a), (float)sin(a)); }
    if (idx < 128)   { double a = -P2 * idx / 128.0;      g_W128[idx]   = make_float2((float)cos(a), (float)sin(a)); }
}

// -------------------------------------------------------------------------
// 128-pt DIF FFT over slow axis of tile[128][GT+1], 32 transforms (one per g).
// TWO smem sweeps: radix-8 (span 16) + fused register-resident 16-point.
// Output digit-scrambled: natural freq of position p is f128(p).
// -------------------------------------------------------------------------
__device__ __forceinline__ void fft128_s1(float2 (*tile)[GT + 1], int t, float sgn) {
    for (int q = t; q < 512; q += NTHR) {
        int g = q & 31, j = q >> 5;            // j in [0,16)
        float2 u[8];
#pragma unroll
        for (int k = 0; k < 8; k++) u[k] = tile[j + (k << 4)][g];
        dft8(u, sgn);
        float2 w1 = g_W128[j]; w1.y *= sgn;
        twiddle_chain8(u, w1);
#pragma unroll
        for (int k = 0; k < 8; k++) tile[j + (k << 4)][g] = u[k];
    }
    __syncthreads();
}

// stage 2: full 16-pt transform in registers per 16-block (m = t>>5, g = t&31)
__device__ __forceinline__ void fft128_s2(float2 (*tile)[GT + 1], int t, float sgn) {
    int g = t & 31, m = t >> 5;                // exactly 256 work items
    int base = m << 4;
    float2 e0[8], e1[8];
#pragma unroll
    for (int k = 0; k < 8; k++) {
        e0[k] = tile[base + (k << 1)][g];
        e1[k] = tile[base + (k << 1) + 1][g];
    }
    dft8(e0, sgn); dft8(e1, sgn);
#pragma unroll
    for (int k = 1; k < 8; k++) {
        float2 w = g_W128[k << 3]; w.y *= sgn; // W16^k (broadcast, cheap)
        e1[k] = cmul(e1[k], w);
    }
#pragma unroll
    for (int k = 0; k < 8; k++) {
        tile[base + (k << 1)][g]     = cadd(e0[k], e1[k]);
        tile[base + (k << 1) + 1][g] = csub(e0[k], e1[k]);
    }
    __syncthreads();
}

// ------------------------------------- K1: pack Z = du + i*b, FFT over c, data loss
// Input rows c >= 64 are structurally zero (n >= MTOT) -> half-input stage 1.
__global__ __launch_bounds__(NTHR)
void k1_pack_fft(const float* __restrict__ up, const float* __restrict__ utr) {
    __shared__ float2 tile[FC][GT + 1];
    __shared__ double red[NTHR];
    const int t   = threadIdx.x;
    const int ab0 = blockIdx.x * GT;

    // load rows c < 64 only, float4-vectorized (4 g per thread)
    float acc = 0.f;
    for (int i = t; i < (GT / 4) * 64; i += NTHR) {      // 512 items
        int c  = i >> 3;
        int gq = (i & 7) << 2;
        int n  = ab0 + gq + AB * c;                      // n+3 < MTOT guaranteed (c<64)
        float4 a4 = *reinterpret_cast<const float4*>(up + n);
        float4 b4 = *reinterpret_cast<const float4*>(utr + n);
        float d0 = a4.x - b4.x, d1 = a4.y - b4.y, d2 = a4.z - b4.z, d3 = a4.w - b4.w;
        acc = fmaf(d0, d0, acc); acc = fmaf(d1, d1, acc);
        acc = fmaf(d2, d2, acc); acc = fmaf(d3, d3, acc);
        float unext = (n + 4 < MTOT) ? __ldg(up + n + 4) : 0.f;
        float du0 = a4.y - a4.x, du1 = a4.z - a4.y, du2 = a4.w - a4.z, du3 = unext - a4.w;
        // EXACT replica of the reference fp32 weights (incl. cancellation noise)
        float bw0 = __fsqrt_rn((float)(n + 1)) - __fsqrt_rn((float)n);
        float bw1 = __fsqrt_rn((float)(n + 2)) - __fsqrt_rn((float)(n + 1));
        float bw2 = __fsqrt_rn((float)(n + 3)) - __fsqrt_rn((float)(n + 2));
        float bw3 = __fsqrt_rn((float)(n + 4)) - __fsqrt_rn((float)(n + 3));
        if (n + 3 >= MTOT - 1) {                          // only last elements of last block
            if (n + 0 >= MTOT - 1) { du0 = 0.f; bw0 = 0.f; }
            if (n + 1 >= MTOT - 1) { du1 = 0.f; bw1 = 0.f; }
            if (n + 2 >= MTOT - 1) { du2 = 0.f; bw2 = 0.f; }
            du3 = 0.f; bw3 = 0.f;
        }
        tile[c][gq + 0] = make_float2(du0, bw0);
        tile[c][gq + 1] = make_float2(du1, bw1);
        tile[c][gq + 2] = make_float2(du2, bw2);
        tile[c][gq + 3] = make_float2(du3, bw3);
    }
    __syncthreads();

    // stage 1 with zero top half: reads rows j+16k for k<4 (all < 64)
    for (int q = t; q < 512; q += NTHR) {
        int g = q & 31, j = q >> 5;
        float2 u[8];
#pragma unroll
        for (int k = 0; k < 4; k++) u[k] = tile[j + (k << 4)][g];
        dft8h(u, 1.f);
        float2 w1 = g_W128[j];
        twiddle_chain8(u, w1);
#pragma unroll
        for (int k = 0; k < 8; k++) tile[j + (k << 4)][g] = u[k];
    }
    __syncthreads();

    fft128_s2(tile, t, 1.f);

    // store with digit-reversal folded into slab index, float4 (2 complex) per store
    for (int i = t; i < (FC * GT) / 2; i += NTHR) {      // 2048 items
        int p  = i >> 4;
        int gg = (i & 15) << 1;
        float2 v0 = tile[p][gg], v1 = tile[p][gg + 1];
        *reinterpret_cast<float4*>(g_Z + ab0 + gg + AB * f128(p)) =
            make_float4(v0.x, v0.y, v1.x, v1.y);
    }

    red[t] = (double)acc;
    __syncthreads();
    for (int s = NTHR / 2; s > 0; s >>= 1) { if (t < s) red[t] += red[t + s]; __syncthreads(); }
    if (t == 0) g_data[blockIdx.x] = red[0];
}

// ---------------------- K2/K4: FFT over b (stride FA), twiddle W_16384^{b c'}
template<int FWD>
__global__ __launch_bounds__(NTHR)
void k2_fftb() {
    __shared__ float2 tile[FB][GT + 1];
    const int t  = threadIdx.x;
    const int cp = blockIdx.x >> 6;             // c' ; FA/GT = 64
    const int a0 = (blockIdx.x & 63) * GT;

    for (int i = t; i < (FB * GT) / 2; i += NTHR) {
        int b  = i >> 4;
        int gg = (i & 15) << 1;
        float4 q4 = *reinterpret_cast<const float4*>(g_Z + a0 + gg + FA * b + AB * cp);
        float2 v0 = make_float2(q4.x, q4.y), v1 = make_float2(q4.z, q4.w);
        if (FWD) {
            float2 w = g_W16384[b * cp];        // pre-twiddle (forward)
            v0 = cmul(v0, w); v1 = cmul(v1, w);
        }
        tile[b][gg] = v0; tile[b][gg + 1] = v1;
    }
    __syncthreads();

    fft128_s1(tile, t, FWD ? 1.f : -1.f);
    fft128_s2(tile, t, FWD ? 1.f : -1.f);

    for (int i = t; i < (FB * GT) / 2; i += NTHR) {
        int p  = i >> 4;
        int gg = (i & 15) << 1;
        int bb = f128(p);                       // natural output index
        float2 v0 = tile[p][gg], v1 = tile[p][gg + 1];
        if (!FWD) {                             // post-twiddle (inverse)
            float2 w = g_W16384[bb * cp]; w.y = -w.y;
            v0 = cmul(v0, w); v1 = cmul(v1, w);
        }
        *reinterpret_cast<float4*>(g_Z + a0 + gg + FA * bb + AB * cp) =
            make_float4(v0.x, v0.y, v1.x, v1.y);
    }
}

// -------- K3 stage helpers: 2048 = 8*8*8*4, XOR-swizzled smem layout SW()
__device__ __forceinline__ void k3_r8(float2 (*sm)[FA], int nrow, int t,
                                      int ls, int tmul, int inv) {
    const int s   = 1 << ls;
    const int tot = nrow << 8;      // 256 butterflies per row
    for (int q = t; q < tot; q += NTHR) {
        int row = q >> 8, qq = q & 255;
        int j = qq & (s - 1), m = qq >> ls;
        int base = (m << (ls + 3)) + j;
        float2 u[8];
#pragma unroll
        for (int k = 0; k < 8; k++) u[k] = sm[row][SW(base + (k << ls))];
        float2 w1 = g_W2048[tmul * j];          // single coalesced twiddle load
        if (!inv) {
            dft8(u, 1.f);
            twiddle_chain8(u, w1);
        } else {
            // DIT inverse: conj twiddle BEFORE inverse DFT8
            w1.y = -w1.y;
            twiddle_chain8(u, w1);
            dft8(u, -1.f);
        }
#pragma unroll
        for (int k = 0; k < 8; k++) sm[row][SW(base + (k << ls))] = u[k];
    }
    __syncthreads();
}

// radix-4 span-1 (kept for the h==0 block's unfused path)
__device__ __forceinline__ void k3_r4(float2 (*sm)[FA], int nrow, int t, float sgn) {
    const int tot = nrow << 9;      // 512 quads per row
    for (int q = t; q < tot; q += NTHR) {
        int row = q >> 9, b = (q & 511) << 2;
        float2* rowp = sm[row];
        float4 lo = *reinterpret_cast<const float4*>(&rowp[SW(b)]);
        float4 hi = *reinterpret_cast<const float4*>(&rowp[SW(b + 2)]);
        float2 u[4] = { make_float2(lo.x, lo.y), make_float2(lo.z, lo.w),
                        make_float2(hi.x, hi.y), make_float2(hi.z, hi.w) };
        dft4(u, sgn);
        *reinterpret_cast<float4*>(&rowp[SW(b)])     = make_float4(u[0].x, u[0].y, u[1].x, u[1].y);
        *reinterpret_cast<float4*>(&rowp[SW(b + 2)]) = make_float4(u[2].x, u[2].y, u[3].x, u[3].y);
    }
    __syncthreads();
}

__device__ __forceinline__ float2 herm_P(float2 z1, float2 z2) {
    // DU = (z1 + conj z2)/2 ; B = -i/2 * (z1 - conj z2) ; P = DU*B
    float2 du = make_float2(0.5f * (z1.x + z2.x), 0.5f * (z1.y - z2.y));
    float2 bv = make_float2(0.5f * (z1.y + z2.y), -0.5f * (z1.x - z2.x));
    return cmul(du, bv);
}

// -------- K3: fwd DIF over a (+twiddle), pointwise in scrambled domain, inverse DIT
// Compact grid: 8193 blocks, every block active (pair enumerated in closed form).
// Pairing identity: pos2048(2047 - f) == 2047 - pos2048(f)  (all digits complement)
// -> partner of POSITION p is 2047 - p; quad w pairs with quad 511 - w, elem e <-> 3-e.
// Middle (r4 fwd + pairing + r4 inv) is fused into ONE register pass for all
// blocks except idx==0 (h==0 has the (2048-f) mod 2048 partner map).
__global__ __launch_bounds__(NTHR)
void k3_core() {
    __shared__ __align__(16) float2 sm[2][FA];   // 32 KB, XOR-swizzled
    const int t   = threadIdx.x;
    const int idx = blockIdx.x;
    int b1, c1;
    if (idx < 65)       { c1 = 0;  b1 = idx; }
    else if (idx < 129) { c1 = 64; b1 = idx - 65; }
    else                { int r = idx - 129; c1 = 1 + (r >> 7); b1 = r & 127; }
    const int h1 = b1 + (c1 << LB);
    int h2;
    if (c1 > 0)      h2 = (FB - 1 - b1) + ((FC - c1) << LB);
    else if (b1 > 0) h2 = FB - b1;
    else             h2 = 0;
    const bool self = (h1 == h2);
    const int  nrow = self ? 1 : 2;
    const int  b2 = h2 & (FB - 1), c2 = h2 >> LB;
    const int  hk1 = c1 + FC * b1;             // frequency weight c' + FC*b'
    const int  hk2 = c2 + FC * b2;

    // fused: float4 load + forward pre-twiddle W_N^{a*hk} (e < N, no mod: 2047*16383 < 2^25)
    for (int i = t; i < (nrow << (LA - 1)); i += NTHR) {
        int row = i >> (LA - 1);
        int aa  = (i & ((FA >> 1) - 1)) << 1;
        int hk  = row ? hk2 : hk1;
        float4 q4 = *reinterpret_cast<const float4*>(g_Z + (row ? h2 : h1) * FA + aa);
        int e0 = aa * hk, e1 = e0 + hk;
        float2 w0 = cmul(g_Whi[e0 >> 12], g_Wlo[e0 & 4095]);
        float2 w1 = cmul(g_Whi[e1 >> 12], g_Wlo[e1 & 4095]);
        float2 v0 = cmul(make_float2(q4.x, q4.y), w0);
        float2 v1 = cmul(make_float2(q4.z, q4.w), w1);
        *reinterpret_cast<float4*>(&sm[row][SW(aa)]) = make_float4(v0.x, v0.y, v1.x, v1.y);
    }
    __syncthreads();

    // forward DIF: radix-8 x3 (output after fused middle is digit-scrambled pos2048)
    k3_r8(sm, nrow, t, 8, 1,  0);   // sub-len 2048, span 256
    k3_r8(sm, nrow, t, 5, 8,  0);   // sub-len 256,  span 32
    k3_r8(sm, nrow, t, 2, 64, 0);   // sub-len 32,   span 4

    if (idx == 0) {
        // h == 0: unfused path (partner f2 = (FA - f1) mod FA)
        k3_r4(sm, nrow, t, 1.f);
        for (int a1 = t; a1 <= FA / 2; a1 += NTHR) {
            if (a1 == 0 || a1 == FA / 2) {
                int p = pos2048(a1);
                float2 z = sm[0][SW(p)];
                sm[0][SW(p)] = make_float2(z.x * z.y, 0.f);   // DU=Re(z), B=Im(z)
            } else {
                int p1 = pos2048(a1), p2 = pos2048(FA - a1);
                float2 z1 = sm[0][SW(p1)];
                float2 z2 = sm[0][SW(p2)];
                float2 P  = herm_P(z1, z2);
                sm[0][SW(p1)] = P;
                sm[0][SW(p2)] = make_float2(P.x, -P.y);
            }
        }
        __syncthreads();
        k3_r4(sm, nrow, t, -1.f);
    } else {
        // fused middle: r4 fwd + Hermitian pairing + r4 inv, one register pass
        const int ntask = self ? 256 : 512;
        for (int w = t; w < ntask; w += NTHR) {
            float2* rA = sm[0];
            float2* rB = self ? sm[0] : sm[1];
            const int ba = w << 2;
            const int bb = (511 - w) << 2;
            float4 alo = *reinterpret_cast<const float4*>(&rA[SW(ba)]);
            float4 ahi = *reinterpret_cast<const float4*>(&rA[SW(ba + 2)]);
            float4 blo = *reinterpret_cast<const float4*>(&rB[SW(bb)]);
            float4 bhi = *reinterpret_cast<const float4*>(&rB[SW(bb + 2)]);
            float2 uA[4] = { make_float2(alo.x, alo.y), make_float2(alo.z, alo.w),
                             make_float2(ahi.x, ahi.y), make_float2(ahi.z, ahi.w) };
            float2 uB[4] = { make_float2(blo.x, blo.y), make_float2(blo.z, blo.w),
                             make_float2(bhi.x, bhi.y), make_float2(bhi.z, bhi.w) };
            dft4(uA, 1.f); dft4(uB, 1.f);
#pragma unroll
            for (int e = 0; e < 4; e++) {
                // partner of position ba+e is bb+(3-e) (= 2047 - (ba+e))
                float2 P = herm_P(uA[e], uB[3 - e]);
                uA[e]     = P;
                uB[3 - e] = make_float2(P.x, -P.y);
            }
            dft4(uA, -1.f); dft4(uB, -1.f);
            *reinterpret_cast<float4*>(&rA[SW(ba)])     = make_float4(uA[0].x, uA[0].y, uA[1].x, uA[1].y);
            *reinterpret_cast<float4*>(&rA[SW(ba + 2)]) = make_float4(uA[2].x, uA[2].y, uA[3].x, uA[3].y);
            *reinterpret_cast<float4*>(&rB[SW(bb)])     = make_float4(uB[0].x, uB[0].y, uB[1].x, uB[1].y);
            *reinterpret_cast<float4*>(&rB[SW(bb + 2)]) = make_float4(uB[2].x, uB[2].y, uB[3].x, uB[3].y);
        }
        __syncthreads();
    }

    // inverse DIT: mirror order, conj twiddles (scrambled in -> natural out)
    k3_r8(sm, nrow, t, 2, 64, 1);
    k3_r8(sm, nrow, t, 5, 8,  1);
    k3_r8(sm, nrow, t, 8, 1,  1);

    // fused: inverse post-twiddle conj(W_N^{a*hk}) + float4 store
    for (int i = t; i < (nrow << (LA - 1)); i += NTHR) {
        int row = i >> (LA - 1);
        int aa  = (i & ((FA >> 1) - 1)) << 1;
        int hk  = row ? hk2 : hk1;
        int e0 = aa * hk, e1 = e0 + hk;
        float2 w0 = cmul(g_Whi[e0 >> 12], g_Wlo[e0 & 4095]); w0.y = -w0.y;
        float2 w1 = cmul(g_Whi[e1 >> 12], g_Wlo[e1 & 4095]); w1.y = -w1.y;
        float4 q4 = *reinterpret_cast<const float4*>(&sm[row][SW(aa)]);
        float2 v0 = cmul(make_float2(q4.x, q4.y), w0);
        float2 v1 = cmul(make_float2(q4.z, q4.w), w1);
        *reinterpret_cast<float4*>(g_Z + (row ? h2 : h1) * FA + aa) =
            make_float4(v0.x, v0.y, v1.x, v1.y);
    }
}

// -------- K5: inverse FFT over c' with stage-2 fused into the physics epilogue.
// Only even positions p (c = f128(p) < 64) are ever needed -> compute even half in regs.
__global__ __launch_bounds__(NTHR)
void k5_inv_epi(const float* __restrict__ up, float coefN) {
    __shared__ float2 tile[FC][GT + 1];
    __shared__ double red[NTHR];
    const int t   = threadIdx.x;
    const int ab0 = blockIdx.x * GT;

    for (int i = t; i < (FC * GT) / 2; i += NTHR) {
        int c  = i >> 4;
        int gg = (i & 15) << 1;
        float4 q4 = *reinterpret_cast<const float4*>(g_Z + ab0 + gg + AB * c);
        tile[c][gg]     = make_float2(q4.x, q4.y);
        tile[c][gg + 1] = make_float2(q4.z, q4.w);
    }
    __syncthreads();

    fft128_s1(tile, t, -1.f);

    // fused stage 2 (even outputs only) + epilogue
    float acc = 0.f;
    {
        int g = t & 31, m = t >> 5;            // m in [0,8)
        int base = m << 4;
        float2 e0[8], e1[8];
#pragma unroll
        for (int k = 0; k < 8; k++) {
            e0[k] = tile[base + (k << 1)][g];
            e1[k] = tile[base + (k << 1) + 1][g];
        }
        dft8(e0, -1.f); dft8(e1, -1.f);
#pragma unroll
        for (int k = 1; k < 8; k++) {
            float2 w = g_W128[k << 3]; w.y = -w.y;   // conj W16^k
            e1[k] = cmul(e1[k], w);
        }
#pragma unroll
        for (int k = 0; k < 8; k++) {
            float convr = e0[k].x + e1[k].x;          // even output, real part
            int c = m + (k << 3);                     // f128(16m + 2k) = m + 8k  (< 64)
            int n = ab0 + g + AB * c;                 // conv index
            int mres = n + 1;                         // frac[mres] = coef*conv[mres-1]
            if (mres < MTOT) {
                float um = __ldg(up + mres);
                float ut = 0.f;
                if ((mres & 16383) != 16383) ut = __ldg(up + mres + 1) - um;  // last col: u_t=0
                float r = ut - coefN * convr;
                acc = fmaf(r, r, acc);
            }
        }
    }

    red[t] = (double)acc;
    __syncthreads();
    for (int s = NTHR / 2; s > 0; s >>= 1) { if (t < s) red[t] += red[t + s]; __syncthreads(); }
    if (t == 0) g_phys[blockIdx.x] = red[0];
}

// -------- finalize
__global__ void k_fin(const float* __restrict__ up, float* __restrict__ out) {
    __shared__ double rp[256], rd[256];
    int t = threadIdx.x;
    double sp = 0.0, sd = 0.0;
    for (int i = t; i < NBLK; i += 256) { sp += g_phys[i]; sd += g_data[i]; }
    rp[t] = sp; rd[t] = sd;
    __syncthreads();
    for (int s = 128; s > 0; s >>= 1) {
        if (t < s) { rp[t] += rp[t + s]; rd[t] += rd[t + s]; }
        __syncthreads();
    }
    if (t == 0) {
        double r0 = (double)up[1] - (double)up[0];    // m = 0 residual: u_t[0] - 0
        double phys = (rp[0] + r0 * r0) / (double)MTOT;
        double data = rd[0] / (double)MTOT;
        out[0] = (float)(data + 0.1 * phys);
        out[1] = (float)data;
        out[2] = (float)phys;
    }
}

extern "C" void kernel_launch(void* const* d_in, const int* in_sizes, int n_in,
                              void* d_out, int out_size)
{
    const float* up  = (const float*)d_in[0];  // u_pred
    const float* utr = (const float*)d_in[1];  // u_true
    (void)in_sizes; (void)n_in; (void)out_size;

    // coef = sqrt(M-1)/Gamma(1.5); fold the 1/N of the fwd+inv FFT product in here.
    double coefN = sqrt((double)(MTOT - 1)) / 0.886226925452758013649083741670572
                   / (double)NF;

    k_tw<<<64, 256>>>();
    k1_pack_fft<<<NBLK, NTHR>>>(up, utr);
    k2_fftb<1><<<NBLK, NTHR>>>();
    k3_core<<<8193, NTHR>>>();
    k2_fftb<0><<<NBLK, NTHR>>>();
    k5_inv_epi<<<NBLK, NTHR>>>(up, (float)coefN);
    k_fin<<<1, 256>>>(up, (float*)d_out);
}

// round 11
// speedup vs baseline: 4.1563x; 1.1840x over previous
#include <cuda_runtime.h>
#include <math.h>

// FFT size N = 2^25 = FA * FB * FC, position n = a + FA*b + AB*c
#define LN   25
#define NF   (1 << LN)
#define LA   11
#define FA   (1 << LA)          // 2048
#define LB   7
#define FB   (1 << LB)          // 128
#define LC   7
#define FC   (1 << LC)          // 128
#define AB   (FA * FB)          // 262144
#define GT   32                 // tile width (consecutive fast-dim elements)
#define NTHR 256

#define MTOT (1 << 24)          // problem size B*N = 2^24
#define NBLK (AB / GT)          // 8192 blocks for K1/K5

// XOR swizzle for k3 smem: flips element bits [1:4) from bits [4:7).
// Bijective, preserves 2-element (16B) alignment -> float4-safe.
#define SW(p) ((p) ^ ((((p) >> 4) & 7) << 1))

// 256 MB spectral work buffer + twiddle tables + partials (no runtime allocation)
__device__ float2 g_Z[NF];
__device__ float2 g_W16384[16384];  // W_16384^m (full)
__device__ float2 g_W2048[2048];    // W_2048^m  (full)
__device__ float2 g_W128[128];      // W_128^m   (full)
__device__ float2 g_Wlo[4096];      // W_N^j,        j < 4096
__device__ float2 g_Whi[8192];      // W_N^{4096 j}, j < 8192
__device__ double g_data[NBLK];
__device__ double g_phys[NBLK];

__device__ __forceinline__ float2 cadd(float2 a, float2 b) { return make_float2(a.x + b.x, a.y + b.y); }
__device__ __forceinline__ float2 csub(float2 a, float2 b) { return make_float2(a.x - b.x, a.y - b.y); }
__device__ __forceinline__ float2 cmul(float2 a, float2 b) {
    return make_float2(fmaf(a.x, b.x, -a.y * b.y), fmaf(a.x, b.y, a.y * b.x));
}
// multiply by -i (sgn=+1, forward) or +i (sgn=-1, inverse)
__device__ __forceinline__ float2 crot(float2 a, float sgn) { return make_float2(sgn * a.y, -sgn * a.x); }

// 8-point DFT in registers, natural-order outputs. sgn=+1 fwd, -1 inverse (unnormalized).
__device__ __forceinline__ void dft8(float2* u, float sgn) {
    const float C = 0.70710678118654752440f;
    float2 t0 = cadd(u[0], u[4]), t1 = cadd(u[1], u[5]);
    float2 t2 = cadd(u[2], u[6]), t3 = cadd(u[3], u[7]);
    float2 m4 = csub(u[0], u[4]), m5 = csub(u[1], u[5]);
    float2 m6 = csub(u[2], u[6]), m7 = csub(u[3], u[7]);
    float2 t4 = m4;
    float2 t5 = cmul(m5, make_float2(C, -sgn * C));    // W8^1
    float2 t6 = crot(m6, sgn);                         // W8^2
    float2 t7 = cmul(m7, make_float2(-C, -sgn * C));   // W8^3
    float2 s0 = cadd(t0, t2), s2 = csub(t0, t2);
    float2 s1 = cadd(t1, t3), s3 = crot(csub(t1, t3), sgn);
    float2 r0 = cadd(t4, t6), r2 = csub(t4, t6);
    float2 r1 = cadd(t5, t7), r3 = crot(csub(t5, t7), sgn);
    u[0] = cadd(s0, s1); u[4] = csub(s0, s1);
    u[2] = cadd(s2, s3); u[6] = csub(s2, s3);
    u[1] = cadd(r0, r1); u[5] = csub(r0, r1);
    u[3] = cadd(r2, r3); u[7] = csub(r2, r3);
}

// 8-point DFT with inputs 4..7 known to be zero (k1 zero-padding). In: u[0..3]; out: u[0..7].
__device__ __forceinline__ void dft8h(float2* u, float sgn) {
    const float C = 0.70710678118654752440f;
    float2 t0 = u[0], t1 = u[1], t2 = u[2], t3 = u[3];
    float2 t4 = u[0];
    float2 t5 = cmul(u[1], make_float2(C, -sgn * C));
    float2 t6 = crot(u[2], sgn);
    float2 t7 = cmul(u[3], make_float2(-C, -sgn * C));
    float2 s0 = cadd(t0, t2), s2 = csub(t0, t2);
    float2 s1 = cadd(t1, t3), s3 = crot(csub(t1, t3), sgn);
    float2 r0 = cadd(t4, t6), r2 = csub(t4, t6);
    float2 r1 = cadd(t5, t7), r3 = crot(csub(t5, t7), sgn);
    u[0] = cadd(s0, s1); u[4] = csub(s0, s1);
    u[2] = cadd(s2, s3); u[6] = csub(s2, s3);
    u[1] = cadd(r0, r1); u[5] = csub(r0, r1);
    u[3] = cadd(r2, r3); u[7] = csub(r2, r3);
}

// 4-point DFT in registers, natural order.
__device__ __forceinline__ void dft4(float2* u, float sgn) {
    float2 a0 = cadd(u[0], u[2]), b0 = csub(u[0], u[2]);
    float2 a1 = cadd(u[1], u[3]), b1 = crot(csub(u[1], u[3]), sgn);
    u[0] = cadd(a0, a1); u[2] = csub(a0, a1);
    u[1] = cadd(b0, b1); u[3] = csub(b0, b1);
}

// apply w^k (k=1..7) to u[1..7] via cmul chain from a single loaded w1
__device__ __forceinline__ void twiddle_chain8(float2* u, float2 w1) {
    float2 w = w1;
    u[1] = cmul(u[1], w);
#pragma unroll
    for (int k = 2; k < 8; k++) { w = cmul(w, w1); u[k] = cmul(u[k], w); }
}

// digit-reversal maps
// 128 = 8*8*2 DIF: position p -> natural frequency
__device__ __forceinline__ int f128(int p) {
    return (p >> 4) + (((p >> 1) & 7) << 3) + ((p & 1) << 6);
}
// 2048 = 8*8*8*4 DIF: natural frequency k -> scrambled position
__device__ __forceinline__ int pos2048(int k) {
    return ((k & 7) << 8) + (((k >> 3) & 7) << 5) + (((k >> 6) & 7) << 2) + (k >> 9);
}

// ---------------------------------------------------------------- twiddle init
__global__ void k_tw() {
    int idx = blockIdx.x * 256 + threadIdx.x;   // 64 blocks * 256 = 16384
    const double P2 = 6.283185307179586476925286766559;
    if (idx < 16384) { double a = -P2 * idx / 16384.0;    g_W16384[idx] = make_float2((float)cos(a), (float)sin(a)); }
    if (idx < 8192)  { double a = -P2 * idx / 8192.0;     g_Whi[idx]    = make_float2((float)cos(a), (float)sin(a)); }
    if (idx < 4096)  { double a = -P2 * idx / (double)NF; g_Wlo[idx]    = make_float2((float)cos(a), (float)sin(a)); }
    if (idx < 2048)  { double a = -P2 * idx / 2048.0;     g_W2048[idx]  = make_float2((float)cos(a), (float)sin(a)); }
    if (idx < 128)   { double a = -P2 * idx / 128.0;      g_W128[idx]   = make_float2((float)cos(a), (float)sin(a)); }
}

// -------------------------------------------------------------------------
// 128-pt DIF FFT over slow axis of tile[128][GT+1], 32 transforms (one per g).
// TWO smem sweeps: radix-8 (span 16) + fused register-resident 16-point.
// Output digit-scrambled: natural freq of position p is f128(p).
// -------------------------------------------------------------------------
__device__ __forceinline__ void fft128_s1(float2 (*tile)[GT + 1], int t, float sgn) {
    for (int q = t; q < 512; q += NTHR) {
        int g = q & 31, j = q >> 5;            // j in [0,16)
        float2 u[8];
#pragma unroll
        for (int k = 0; k < 8; k++) u[k] = tile[j + (k << 4)][g];
        dft8(u, sgn);
        float2 w1 = g_W128[j]; w1.y *= sgn;
        twiddle_chain8(u, w1);
#pragma unroll
        for (int k = 0; k < 8; k++) tile[j + (k << 4)][g] = u[k];
    }
    __syncthreads();
}

// stage 2: full 16-pt transform in registers per 16-block (m = t>>5, g = t&31)
__device__ __forceinline__ void fft128_s2(float2 (*tile)[GT + 1], int t, float sgn) {
    int g = t & 31, m = t >> 5;                // exactly 256 work items
    int base = m << 4;
    float2 e0[8], e1[8];
#pragma unroll
    for (int k = 0; k < 8; k++) {
        e0[k] = tile[base + (k << 1)][g];
        e1[k] = tile[base + (k << 1) + 1][g];
    }
    dft8(e0, sgn); dft8(e1, sgn);
#pragma unroll
    for (int k = 1; k < 8; k++) {
        float2 w = g_W128[k << 3]; w.y *= sgn; // W16^k (broadcast, cheap)
        e1[k] = cmul(e1[k], w);
    }
#pragma unroll
    for (int k = 0; k < 8; k++) {
        tile[base + (k << 1)][g]     = cadd(e0[k], e1[k]);
        tile[base + (k << 1) + 1][g] = csub(e0[k], e1[k]);
    }
    __syncthreads();
}

// ------------------------------------- K1: pack Z = du + i*b, FFT over c, data loss
// Input rows c >= 64 are structurally zero (n >= MTOT) -> half-input stage 1.
__global__ __launch_bounds__(NTHR)
void k1_pack_fft(const float* __restrict__ up, const float* __restrict__ utr) {
    __shared__ float2 tile[FC][GT + 1];
    __shared__ double red[NTHR];
    const int t   = threadIdx.x;
    const int ab0 = blockIdx.x * GT;

    // load rows c < 64 only, float4-vectorized (4 g per thread)
    float acc = 0.f;
    for (int i = t; i < (GT / 4) * 64; i += NTHR) {      // 512 items
        int c  = i >> 3;
        int gq = (i & 7) << 2;
        int n  = ab0 + gq + AB * c;                      // n+3 < MTOT guaranteed (c<64)
        float4 a4 = *reinterpret_cast<const float4*>(up + n);
        float4 b4 = *reinterpret_cast<const float4*>(utr + n);
        float d0 = a4.x - b4.x, d1 = a4.y - b4.y, d2 = a4.z - b4.z, d3 = a4.w - b4.w;
        acc = fmaf(d0, d0, acc); acc = fmaf(d1, d1, acc);
        acc = fmaf(d2, d2, acc); acc = fmaf(d3, d3, acc);
        float unext = (n + 4 < MTOT) ? __ldg(up + n + 4) : 0.f;
        float du0 = a4.y - a4.x, du1 = a4.z - a4.y, du2 = a4.w - a4.z, du3 = unext - a4.w;
        // EXACT replica of the reference fp32 weights (incl. cancellation noise)
        float bw0 = __fsqrt_rn((float)(n + 1)) - __fsqrt_rn((float)n);
        float bw1 = __fsqrt_rn((float)(n + 2)) - __fsqrt_rn((float)(n + 1));
        float bw2 = __fsqrt_rn((float)(n + 3)) - __fsqrt_rn((float)(n + 2));
        float bw3 = __fsqrt_rn((float)(n + 4)) - __fsqrt_rn((float)(n + 3));
        if (n + 3 >= MTOT - 1) {                          // only last elements of last block
            if (n + 0 >= MTOT - 1) { du0 = 0.f; bw0 = 0.f; }
            if (n + 1 >= MTOT - 1) { du1 = 0.f; bw1 = 0.f; }
            if (n + 2 >= MTOT - 1) { du2 = 0.f; bw2 = 0.f; }
            du3 = 0.f; bw3 = 0.f;
        }
        tile[c][gq + 0] = make_float2(du0, bw0);
        tile[c][gq + 1] = make_float2(du1, bw1);
        tile[c][gq + 2] = make_float2(du2, bw2);
        tile[c][gq + 3] = make_float2(du3, bw3);
    }
    __syncthreads();

    // stage 1 with zero top half: reads rows j+16k for k<4 (all < 64)
    for (int q = t; q < 512; q += NTHR) {
        int g = q & 31, j = q >> 5;
        float2 u[8];
#pragma unroll
        for (int k = 0; k < 4; k++) u[k] = tile[j + (k << 4)][g];
        dft8h(u, 1.f);
        float2 w1 = g_W128[j];
        twiddle_chain8(u, w1);
#pragma unroll
        for (int k = 0; k < 8; k++) tile[j + (k << 4)][g] = u[k];
    }
    __syncthreads();

    fft128_s2(tile, t, 1.f);

    // store with digit-reversal folded into slab index, float4 (2 complex) per store
    for (int i = t; i < (FC * GT) / 2; i += NTHR) {      // 2048 items
        int p  = i >> 4;
        int gg = (i & 15) << 1;
        float2 v0 = tile[p][gg], v1 = tile[p][gg + 1];
        *reinterpret_cast<float4*>(g_Z + ab0 + gg + AB * f128(p)) =
            make_float4(v0.x, v0.y, v1.x, v1.y);
    }

    red[t] = (double)acc;
    __syncthreads();
    for (int s = NTHR / 2; s > 0; s >>= 1) { if (t < s) red[t] += red[t + s]; __syncthreads(); }
    if (t == 0) g_data[blockIdx.x] = red[0];
}

// ---------------------- K2/K4: FFT over b (stride FA), twiddle W_16384^{b c'}
// Inverse (FWD=0) is launched with grid 65*64 only: the post-k4 intermediate is
// c'-Hermitian (conv is real), so only c' in [0,64] is ever consumed by K5.
template<int FWD>
__global__ __launch_bounds__(NTHR)
void k2_fftb() {
    __shared__ float2 tile[FB][GT + 1];
    const int t  = threadIdx.x;
    const int cp = blockIdx.x >> 6;             // c' ; FA/GT = 64
    const int a0 = (blockIdx.x & 63) * GT;

    for (int i = t; i < (FB * GT) / 2; i += NTHR) {
        int b  = i >> 4;
        int gg = (i & 15) << 1;
        float4 q4 = *reinterpret_cast<const float4*>(g_Z + a0 + gg + FA * b + AB * cp);
        float2 v0 = make_float2(q4.x, q4.y), v1 = make_float2(q4.z, q4.w);
        if (FWD) {
            float2 w = g_W16384[b * cp];        // pre-twiddle (forward)
            v0 = cmul(v0, w); v1 = cmul(v1, w);
        }
        tile[b][gg] = v0; tile[b][gg + 1] = v1;
    }
    __syncthreads();

    fft128_s1(tile, t, FWD ? 1.f : -1.f);
    fft128_s2(tile, t, FWD ? 1.f : -1.f);

    for (int i = t; i < (FB * GT) / 2; i += NTHR) {
        int p  = i >> 4;
        int gg = (i & 15) << 1;
        int bb = f128(p);                       // natural output index
        float2 v0 = tile[p][gg], v1 = tile[p][gg + 1];
        if (!FWD) {                             // post-twiddle (inverse)
            float2 w = g_W16384[bb * cp]; w.y = -w.y;
            v0 = cmul(v0, w); v1 = cmul(v1, w);
        }
        *reinterpret_cast<float4*>(g_Z + a0 + gg + FA * bb + AB * cp) =
            make_float4(v0.x, v0.y, v1.x, v1.y);
    }
}

// -------- K3 stage helpers: 2048 = 8*8*8*4, XOR-swizzled smem layout SW()
__device__ __forceinline__ void k3_r8(float2 (*sm)[FA], int nrow, int t,
                                      int ls, int tmul, int inv) {
    const int s   = 1 << ls;
    const int tot = nrow << 8;      // 256 butterflies per row
    for (int q = t; q < tot; q += NTHR) {
        int row = q >> 8, qq = q & 255;
        int j = qq & (s - 1), m = qq >> ls;
        int base = (m << (ls + 3)) + j;
        float2 u[8];
#pragma unroll
        for (int k = 0; k < 8; k++) u[k] = sm[row][SW(base + (k << ls))];
        float2 w1 = g_W2048[tmul * j];          // single coalesced twiddle load
        if (!inv) {
            dft8(u, 1.f);
            twiddle_chain8(u, w1);
        } else {
            // DIT inverse: conj twiddle BEFORE inverse DFT8
            w1.y = -w1.y;
            twiddle_chain8(u, w1);
            dft8(u, -1.f);
        }
#pragma unroll
        for (int k = 0; k < 8; k++) sm[row][SW(base + (k << ls))] = u[k];
    }
    __syncthreads();
}

// radix-4 span-1 (kept for the h==0 block's unfused path)
__device__ __forceinline__ void k3_r4(float2 (*sm)[FA], int nrow, int t, float sgn) {
    const int tot = nrow << 9;      // 512 quads per row
    for (int q = t; q < tot; q += NTHR) {
        int row = q >> 9, b = (q & 511) << 2;
        float2* rowp = sm[row];
        float4 lo = *reinterpret_cast<const float4*>(&rowp[SW(b)]);
        float4 hi = *reinterpret_cast<const float4*>(&rowp[SW(b + 2)]);
        float2 u[4] = { make_float2(lo.x, lo.y), make_float2(lo.z, lo.w),
                        make_float2(hi.x, hi.y), make_float2(hi.z, hi.w) };
        dft4(u, sgn);
        *reinterpret_cast<float4*>(&rowp[SW(b)])     = make_float4(u[0].x, u[0].y, u[1].x, u[1].y);
        *reinterpret_cast<float4*>(&rowp[SW(b + 2)]) = make_float4(u[2].x, u[2].y, u[3].x, u[3].y);
    }
    __syncthreads();
}

__device__ __forceinline__ float2 herm_P(float2 z1, float2 z2) {
    // DU = (z1 + conj z2)/2 ; B = -i/2 * (z1 - conj z2) ; P = DU*B
    float2 du = make_float2(0.5f * (z1.x + z2.x), 0.5f * (z1.y - z2.y));
    float2 bv = make_float2(0.5f * (z1.y + z2.y), -0.5f * (z1.x - z2.x));
    return cmul(du, bv);
}

// -------- K3: fwd DIF over a (+twiddle), pointwise in scrambled domain, inverse DIT
// Compact grid: 8193 blocks, every block active (pair enumerated in closed form).
// Pairing identity: pos2048(2047 - f) == 2047 - pos2048(f)  (all digits complement)
// -> partner of POSITION p is 2047 - p; quad w pairs with quad 511 - w, elem e <-> 3-e.
// Middle (r4 fwd + pairing + r4 inv) is fused into ONE register pass for all
// blocks except idx==0 (h==0 has the (2048-f) mod 2048 partner map).
// Output chunks with c' > 64 are never consumed downstream (c'-Hermitian
// symmetry, K4 runs only c' <= 64) -> skip storing row1 when c2 > 64.
__global__ __launch_bounds__(NTHR)
void k3_core() {
    __shared__ __align__(16) float2 sm[2][FA];   // 32 KB, XOR-swizzled
    const int t   = threadIdx.x;
    const int idx = blockIdx.x;
    int b1, c1;
    if (idx < 65)       { c1 = 0;  b1 = idx; }
    else if (idx < 129) { c1 = 64; b1 = idx - 65; }
    else                { int r = idx - 129; c1 = 1 + (r >> 7); b1 = r & 127; }
    const int h1 = b1 + (c1 << LB);
    int h2;
    if (c1 > 0)      h2 = (FB - 1 - b1) + ((FC - c1) << LB);
    else if (b1 > 0) h2 = FB - b1;
    else             h2 = 0;
    const bool self = (h1 == h2);
    const int  nrow = self ? 1 : 2;
    const int  b2 = h2 & (FB - 1), c2 = h2 >> LB;
    const int  hk1 = c1 + FC * b1;             // frequency weight c' + FC*b'
    const int  hk2 = c2 + FC * b2;

    // fused: float4 load + forward pre-twiddle W_N^{a*hk} (e < N, no mod: 2047*16383 < 2^25)
    for (int i = t; i < (nrow << (LA - 1)); i += NTHR) {
        int row = i >> (LA - 1);
        int aa  = (i & ((FA >> 1) - 1)) << 1;
        int hk  = row ? hk2 : hk1;
        float4 q4 = *reinterpret_cast<const float4*>(g_Z + (row ? h2 : h1) * FA + aa);
        int e0 = aa * hk, e1 = e0 + hk;
        float2 w0 = cmul(g_Whi[e0 >> 12], g_Wlo[e0 & 4095]);
        float2 w1 = cmul(g_Whi[e1 >> 12], g_Wlo[e1 & 4095]);
        float2 v0 = cmul(make_float2(q4.x, q4.y), w0);
        float2 v1 = cmul(make_float2(q4.z, q4.w), w1);
        *reinterpret_cast<float4*>(&sm[row][SW(aa)]) = make_float4(v0.x, v0.y, v1.x, v1.y);
    }
    __syncthreads();

    // forward DIF: radix-8 x3 (output after fused middle is digit-scrambled pos2048)
    k3_r8(sm, nrow, t, 8, 1,  0);   // sub-len 2048, span 256
    k3_r8(sm, nrow, t, 5, 8,  0);   // sub-len 256,  span 32
    k3_r8(sm, nrow, t, 2, 64, 0);   // sub-len 32,   span 4

    if (idx == 0) {
        // h == 0: unfused path (partner f2 = (FA - f1) mod FA)
        k3_r4(sm, nrow, t, 1.f);
        for (int a1 = t; a1 <= FA / 2; a1 += NTHR) {
            if (a1 == 0 || a1 == FA / 2) {
                int p = pos2048(a1);
                float2 z = sm[0][SW(p)];
                sm[0][SW(p)] = make_float2(z.x * z.y, 0.f);   // DU=Re(z), B=Im(z)
            } else {
                int p1 = pos2048(a1), p2 = pos2048(FA - a1);
                float2 z1 = sm[0][SW(p1)];
                float2 z2 = sm[0][SW(p2)];
                float2 P  = herm_P(z1, z2);
                sm[0][SW(p1)] = P;
                sm[0][SW(p2)] = make_float2(P.x, -P.y);
            }
        }
        __syncthreads();
        k3_r4(sm, nrow, t, -1.f);
    } else {
        // fused middle: r4 fwd + Hermitian pairing + r4 inv, one register pass
        const int ntask = self ? 256 : 512;
        for (int w = t; w < ntask; w += NTHR) {
            float2* rA = sm[0];
            float2* rB = self ? sm[0] : sm[1];
            const int ba = w << 2;
            const int bb = (511 - w) << 2;
            float4 alo = *reinterpret_cast<const float4*>(&rA[SW(ba)]);
            float4 ahi = *reinterpret_cast<const float4*>(&rA[SW(ba + 2)]);
            float4 blo = *reinterpret_cast<const float4*>(&rB[SW(bb)]);
            float4 bhi = *reinterpret_cast<const float4*>(&rB[SW(bb + 2)]);
            float2 uA[4] = { make_float2(alo.x, alo.y), make_float2(alo.z, alo.w),
                             make_float2(ahi.x, ahi.y), make_float2(ahi.z, ahi.w) };
            float2 uB[4] = { make_float2(blo.x, blo.y), make_float2(blo.z, blo.w),
                             make_float2(bhi.x, bhi.y), make_float2(bhi.z, bhi.w) };
            dft4(uA, 1.f); dft4(uB, 1.f);
#pragma unroll
            for (int e = 0; e < 4; e++) {
                // partner of position ba+e is bb+(3-e) (= 2047 - (ba+e))
                float2 P = herm_P(uA[e], uB[3 - e]);
                uA[e]     = P;
                uB[3 - e] = make_float2(P.x, -P.y);
            }
            dft4(uA, -1.f); dft4(uB, -1.f);
            *reinterpret_cast<float4*>(&rA[SW(ba)])     = make_float4(uA[0].x, uA[0].y, uA[1].x, uA[1].y);
            *reinterpret_cast<float4*>(&rA[SW(ba + 2)]) = make_float4(uA[2].x, uA[2].y, uA[3].x, uA[3].y);
            *reinterpret_cast<float4*>(&rB[SW(bb)])     = make_float4(uB[0].x, uB[0].y, uB[1].x, uB[1].y);
            *reinterpret_cast<float4*>(&rB[SW(bb + 2)]) = make_float4(uB[2].x, uB[2].y, uB[3].x, uB[3].y);
        }
        __syncthreads();
    }

    // inverse DIT: mirror order, conj twiddles (scrambled in -> natural out)
    k3_r8(sm, nrow, t, 2, 64, 1);
    k3_r8(sm, nrow, t, 5, 8,  1);
    k3_r8(sm, nrow, t, 8, 1,  1);

    // fused: inverse post-twiddle conj(W_N^{a*hk}) + float4 store
    // Skip row1 store when its chunk has c' > 64 (never consumed downstream).
    const int nstore = (c2 <= 64) ? nrow : 1;
    for (int i = t; i < (nstore << (LA - 1)); i += NTHR) {
        int row = i >> (LA - 1);
        int aa  = (i & ((FA >> 1) - 1)) << 1;
        int hk  = row ? hk2 : hk1;
        int e0 = aa * hk, e1 = e0 + hk;
        float2 w0 = cmul(g_Whi[e0 >> 12], g_Wlo[e0 & 4095]); w0.y = -w0.y;
        float2 w1 = cmul(g_Whi[e1 >> 12], g_Wlo[e1 & 4095]); w1.y = -w1.y;
        float4 q4 = *reinterpret_cast<const float4*>(&sm[row][SW(aa)]);
        float2 v0 = cmul(make_float2(q4.x, q4.y), w0);
        float2 v1 = cmul(make_float2(q4.z, q4.w), w1);
        *reinterpret_cast<float4*>(g_Z + (row ? h2 : h1) * FA + aa) =
            make_float4(v0.x, v0.y, v1.x, v1.y);
    }
}

// -------- K5: inverse FFT over c' with stage-2 fused into the physics epilogue.
// Reads only slabs c' in [0,64]; rows 65..127 reconstructed in smem via the
// c'-Hermitian symmetry Y[.., c'] = conj(Y[.., 128-c']) (conv is real).
// Only even positions p (c = f128(p) < 64) are ever needed -> even half in regs.
__global__ __launch_bounds__(NTHR)
void k5_inv_epi(const float* __restrict__ up, float coefN) {
    __shared__ float2 tile[FC][GT + 1];
    __shared__ double red[NTHR];
    const int t   = threadIdx.x;
    const int ab0 = blockIdx.x * GT;

    // load slabs c' = 0..64 only (float4)
    for (int i = t; i < 65 * (GT / 2); i += NTHR) {      // 1040 items
        int c  = i >> 4;
        int gg = (i & 15) << 1;
        float4 q4 = *reinterpret_cast<const float4*>(g_Z + ab0 + gg + AB * c);
        tile[c][gg]     = make_float2(q4.x, q4.y);
        tile[c][gg + 1] = make_float2(q4.z, q4.w);
    }
    __syncthreads();

    // mirror-fill rows 65..127 = conj(row 128-c)
    for (int i = t; i < 63 * 32; i += NTHR) {
        int c = 65 + (i >> 5);
        int g = i & 31;
        float2 v = tile[128 - c][g];
        tile[c][g] = make_float2(v.x, -v.y);
    }
    __syncthreads();

    fft128_s1(tile, t, -1.f);

    // fused stage 2 (even outputs only) + epilogue
    float acc = 0.f;
    {
        int g = t & 31, m = t >> 5;            // m in [0,8)
        int base = m << 4;
        float2 e0[8], e1[8];
#pragma unroll
        for (int k = 0; k < 8; k++) {
            e0[k] = tile[base + (k << 1)][g];
            e1[k] = tile[base + (k << 1) + 1][g];
        }
        dft8(e0, -1.f); dft8(e1, -1.f);
#pragma unroll
        for (int k = 1; k < 8; k++) {
            float2 w = g_W128[k << 3]; w.y = -w.y;   // conj W16^k
            e1[k] = cmul(e1[k], w);
        }
#pragma unroll
        for (int k = 0; k < 8; k++) {
            float convr = e0[k].x + e1[k].x;          // even output, real part
            int c = m + (k << 3);                     // f128(16m + 2k) = m + 8k  (< 64)
            int n = ab0 + g + AB * c;                 // conv index
            int mres = n + 1;                         // frac[mres] = coef*conv[mres-1]
            if (mres < MTOT) {
                float um = __ldg(up + mres);
                float ut = 0.f;
                if ((mres & 16383) != 16383) ut = __ldg(up + mres + 1) - um;  // last col: u_t=0
                float r = ut - coefN * convr;
                acc = fmaf(r, r, acc);
            }
        }
    }

    red[t] = (double)acc;
    __syncthreads();
    for (int s = NTHR / 2; s > 0; s >>= 1) { if (t < s) red[t] += red[t + s]; __syncthreads(); }
    if (t == 0) g_phys[blockIdx.x] = red[0];
}

// -------- finalize
__global__ void k_fin(const float* __restrict__ up, float* __restrict__ out) {
    __shared__ double rp[256], rd[256];
    int t = threadIdx.x;
    double sp = 0.0, sd = 0.0;
    for (int i = t; i < NBLK; i += 256) { sp += g_phys[i]; sd += g_data[i]; }
    rp[t] = sp; rd[t] = sd;
    __syncthreads();
    for (int s = 128; s > 0; s >>= 1) {
        if (t < s) { rp[t] += rp[t + s]; rd[t] += rd[t + s]; }
        __syncthreads();
    }
    if (t == 0) {
        double r0 = (double)up[1] - (double)up[0];    // m = 0 residual: u_t[0] - 0
        double phys = (rp[0] + r0 * r0) / (double)MTOT;
        double data = rd[0] / (double)MTOT;
        out[0] = (float)(data + 0.1 * phys);
        out[1] = (float)data;
        out[2] = (float)phys;
    }
}

extern "C" void kernel_launch(void* const* d_in, const int* in_sizes, int n_in,
                              void* d_out, int out_size)
{
    const float* up  = (const float*)d_in[0];  // u_pred
    const float* utr = (const float*)d_in[1];  // u_true
    (void)in_sizes; (void)n_in; (void)out_size;

    // coef = sqrt(M-1)/Gamma(1.5); fold the 1/N of the fwd+inv FFT product in here.
    double coefN = sqrt((double)(MTOT - 1)) / 0.886226925452758013649083741670572
                   / (double)NF;

    k_tw<<<64, 256>>>();
    k1_pack_fft<<<NBLK, NTHR>>>(up, utr);
    k2_fftb<1><<<NBLK, NTHR>>>();
    k3_core<<<8193, NTHR>>>();
    k2_fftb<0><<<65 * 64, NTHR>>>();           // only c' <= 64 needed (Hermitian)
    k5_inv_epi<<<NBLK, NTHR>>>(up, (float)coefN);
    k_fin<<<1, 256>>>(up, (float*)d_out);
}

// round 12
// speedup vs baseline: 4.9036x; 1.1798x over previous
#include <cuda_runtime.h>
#include <math.h>

// FFT size N = 2^25 = FA * FB * FC, position n = a + FA*b + AB*c
#define LN   25
#define NF   (1 << LN)
#define LA   11
#define FA   (1 << LA)          // 2048
#define LB   7
#define FB   (1 << LB)          // 128
#define LC   7
#define FC   (1 << LC)          // 128
#define AB   (FA * FB)          // 262144
#define GT   32                 // tile width (consecutive fast-dim elements)
#define NTHR 256

#define MTOT (1 << 24)          // problem size B*N = 2^24
#define NBLK (AB / GT)          // 8192 blocks for K1/K5

// XOR swizzle for k3 smem: flips element bits [1:4) from bits [4:7).
// Bijective, preserves 2-element (16B) alignment -> float4-safe.
#define SW(p) ((p) ^ ((((p) >> 4) & 7) << 1))

// 256 MB spectral work buffer + twiddle tables + partials (no runtime allocation)
__device__ float2 g_Z[NF];
__device__ float2 g_W16384[16384];  // W_16384^m (full)
__device__ float2 g_W2048[2048];    // W_2048^m  (full)
__device__ float2 g_W128[128];      // W_128^m   (full)
__device__ float2 g_Wlo[4096];      // W_N^j,        j < 4096
__device__ float2 g_Whi[8192];      // W_N^{4096 j}, j < 8192
__device__ double g_data[NBLK];
__device__ double g_phys[NBLK];

__device__ __forceinline__ float2 cadd(float2 a, float2 b) { return make_float2(a.x + b.x, a.y + b.y); }
__device__ __forceinline__ float2 csub(float2 a, float2 b) { return make_float2(a.x - b.x, a.y - b.y); }
__device__ __forceinline__ float2 cmul(float2 a, float2 b) {
    return make_float2(fmaf(a.x, b.x, -a.y * b.y), fmaf(a.x, b.y, a.y * b.x));
}
// multiply by -i (sgn=+1, forward) or +i (sgn=-1, inverse)
__device__ __forceinline__ float2 crot(float2 a, float sgn) { return make_float2(sgn * a.y, -sgn * a.x); }

// 8-point DFT in registers, natural-order outputs. sgn=+1 fwd, -1 inverse (unnormalized).
__device__ __forceinline__ void dft8(float2* u, float sgn) {
    const float C = 0.70710678118654752440f;
    float2 t0 = cadd(u[0], u[4]), t1 = cadd(u[1], u[5]);
    float2 t2 = cadd(u[2], u[6]), t3 = cadd(u[3], u[7]);
    float2 m4 = csub(u[0], u[4]), m5 = csub(u[1], u[5]);
    float2 m6 = csub(u[2], u[6]), m7 = csub(u[3], u[7]);
    float2 t4 = m4;
    float2 t5 = cmul(m5, make_float2(C, -sgn * C));    // W8^1
    float2 t6 = crot(m6, sgn);                         // W8^2
    float2 t7 = cmul(m7, make_float2(-C, -sgn * C));   // W8^3
    float2 s0 = cadd(t0, t2), s2 = csub(t0, t2);
    float2 s1 = cadd(t1, t3), s3 = crot(csub(t1, t3), sgn);
    float2 r0 = cadd(t4, t6), r2 = csub(t4, t6);
    float2 r1 = cadd(t5, t7), r3 = crot(csub(t5, t7), sgn);
    u[0] = cadd(s0, s1); u[4] = csub(s0, s1);
    u[2] = cadd(s2, s3); u[6] = csub(s2, s3);
    u[1] = cadd(r0, r1); u[5] = csub(r0, r1);
    u[3] = cadd(r2, r3); u[7] = csub(r2, r3);
}

// 8-point DFT with inputs 4..7 known to be zero (k1 zero-padding). In: u[0..3]; out: u[0..7].
__device__ __forceinline__ void dft8h(float2* u, float sgn) {
    const float C = 0.70710678118654752440f;
    float2 t0 = u[0], t1 = u[1], t2 = u[2], t3 = u[3];
    float2 t4 = u[0];
    float2 t5 = cmul(u[1], make_float2(C, -sgn * C));
    float2 t6 = crot(u[2], sgn);
    float2 t7 = cmul(u[3], make_float2(-C, -sgn * C));
    float2 s0 = cadd(t0, t2), s2 = csub(t0, t2);
    float2 s1 = cadd(t1, t3), s3 = crot(csub(t1, t3), sgn);
    float2 r0 = cadd(t4, t6), r2 = csub(t4, t6);
    float2 r1 = cadd(t5, t7), r3 = crot(csub(t5, t7), sgn);
    u[0] = cadd(s0, s1); u[4] = csub(s0, s1);
    u[2] = cadd(s2, s3); u[6] = csub(s2, s3);
    u[1] = cadd(r0, r1); u[5] = csub(r0, r1);
    u[3] = cadd(r2, r3); u[7] = csub(r2, r3);
}

// 4-point DFT in registers, natural order.
__device__ __forceinline__ void dft4(float2* u, float sgn) {
    float2 a0 = cadd(u[0], u[2]), b0 = csub(u[0], u[2]);
    float2 a1 = cadd(u[1], u[3]), b1 = crot(csub(u[1], u[3]), sgn);
    u[0] = cadd(a0, a1); u[2] = csub(a0, a1);
    u[1] = cadd(b0, b1); u[3] = csub(b0, b1);
}

// apply w^k (k=1..7) to u[1..7] via cmul chain from a single loaded w1
__device__ __forceinline__ void twiddle_chain8(float2* u, float2 w1) {
    float2 w = w1;
    u[1] = cmul(u[1], w);
#pragma unroll
    for (int k = 2; k < 8; k++) { w = cmul(w, w1); u[k] = cmul(u[k], w); }
}

// digit-reversal maps
// 128 = 8*8*2 DIF: position p -> natural frequency
__device__ __forceinline__ int f128(int p) {
    return (p >> 4) + (((p >> 1) & 7) << 3) + ((p & 1) << 6);
}
// 2048 = 8*8*8*4 DIF: natural frequency k -> scrambled position
__device__ __forceinline__ int pos2048(int k) {
    return ((k & 7) << 8) + (((k >> 3) & 7) << 5) + (((k >> 6) & 7) << 2) + (k >> 9);
}

// ---------------------------------------------------------------- twiddle init
__global__ void k_tw() {
    int idx = blockIdx.x * 256 + threadIdx.x;   // 64 blocks * 256 = 16384
    const double P2 = 6.283185307179586476925286766559;
    if (idx < 16384) { double a = -P2 * idx / 16384.0;    g_W16384[idx] = make_float2((float)cos(a), (float)sin(a)); }
    if (idx < 8192)  { double a = -P2 * idx / 8192.0;     g_Whi[idx]    = make_float2((float)cos(a), (float)sin(a)); }
    if (idx < 4096)  { double a = -P2 * idx / (double)NF; g_Wlo[idx]    = make_float2((float)cos(a), (float)sin(a)); }
    if (idx < 2048)  { double a = -P2 * idx / 2048.0;     g_W2048[idx]  = make_float2((float)cos(a), (float)sin(a)); }
    if (idx < 128)   { double a = -P2 * idx / 128.0;      g_W128[idx]   = make_float2((float)cos(a), (float)sin(a)); }
}

// ------------------------------------- K1: pack Z = du + i*b, FFT over c, data loss
// Input rows c >= 64 are structurally zero (n >= MTOT) -> half-input stage 1.
// Stage 2 writes directly to global (register->STG, coalesced per warp).
__global__ __launch_bounds__(NTHR)
void k1_pack_fft(const float* __restrict__ up, const float* __restrict__ utr) {
    __shared__ float2 tile[FC][GT + 1];
    __shared__ double red[NTHR];
    const int t   = threadIdx.x;
    const int ab0 = blockIdx.x * GT;

    // load rows c < 64 only, float4-vectorized (4 g per thread)
    float acc = 0.f;
    for (int i = t; i < (GT / 4) * 64; i += NTHR) {      // 512 items
        int c  = i >> 3;
        int gq = (i & 7) << 2;
        int n  = ab0 + gq + AB * c;                      // n+3 < MTOT guaranteed (c<64)
        float4 a4 = *reinterpret_cast<const float4*>(up + n);
        float4 b4 = *reinterpret_cast<const float4*>(utr + n);
        float d0 = a4.x - b4.x, d1 = a4.y - b4.y, d2 = a4.z - b4.z, d3 = a4.w - b4.w;
        acc = fmaf(d0, d0, acc); acc = fmaf(d1, d1, acc);
        acc = fmaf(d2, d2, acc); acc = fmaf(d3, d3, acc);
        float unext = (n + 4 < MTOT) ? __ldg(up + n + 4) : 0.f;
        float du0 = a4.y - a4.x, du1 = a4.z - a4.y, du2 = a4.w - a4.z, du3 = unext - a4.w;
        // EXACT replica of the reference fp32 weights (incl. cancellation noise)
        float bw0 = __fsqrt_rn((float)(n + 1)) - __fsqrt_rn((float)n);
        float bw1 = __fsqrt_rn((float)(n + 2)) - __fsqrt_rn((float)(n + 1));
        float bw2 = __fsqrt_rn((float)(n + 3)) - __fsqrt_rn((float)(n + 2));
        float bw3 = __fsqrt_rn((float)(n + 4)) - __fsqrt_rn((float)(n + 3));
        if (n + 3 >= MTOT - 1) {                          // only last elements of last block
            if (n + 0 >= MTOT - 1) { du0 = 0.f; bw0 = 0.f; }
            if (n + 1 >= MTOT - 1) { du1 = 0.f; bw1 = 0.f; }
            if (n + 2 >= MTOT - 1) { du2 = 0.f; bw2 = 0.f; }
            du3 = 0.f; bw3 = 0.f;
        }
        tile[c][gq + 0] = make_float2(du0, bw0);
        tile[c][gq + 1] = make_float2(du1, bw1);
        tile[c][gq + 2] = make_float2(du2, bw2);
        tile[c][gq + 3] = make_float2(du3, bw3);
    }
    __syncthreads();

    // stage 1 with zero top half: reads rows j+16k for k<4 (all < 64)
    for (int q = t; q < 512; q += NTHR) {
        int g = q & 31, j = q >> 5;
        float2 u[8];
#pragma unroll
        for (int k = 0; k < 4; k++) u[k] = tile[j + (k << 4)][g];
        dft8h(u, 1.f);
        float2 w1 = g_W128[j];
        twiddle_chain8(u, w1);
#pragma unroll
        for (int k = 0; k < 8; k++) tile[j + (k << 4)][g] = u[k];
    }
    __syncthreads();

    // stage 2 in registers + DIRECT global store (digit-reversal in slab index)
    {
        int g = t & 31, m = t >> 5;
        int base = m << 4;
        float2 e0[8], e1[8];
#pragma unroll
        for (int k = 0; k < 8; k++) {
            e0[k] = tile[base + (k << 1)][g];
            e1[k] = tile[base + (k << 1) + 1][g];
        }
        dft8(e0, 1.f); dft8(e1, 1.f);
#pragma unroll
        for (int k = 1; k < 8; k++) e1[k] = cmul(e1[k], g_W128[k << 3]);   // W16^k
#pragma unroll
        for (int k = 0; k < 8; k++) {
            int p0 = base + (k << 1), p1 = p0 + 1;
            g_Z[ab0 + g + AB * f128(p0)] = cadd(e0[k], e1[k]);
            g_Z[ab0 + g + AB * f128(p1)] = csub(e0[k], e1[k]);
        }
    }

    red[t] = (double)acc;
    __syncthreads();
    for (int s = NTHR / 2; s > 0; s >>= 1) { if (t < s) red[t] += red[t + s]; __syncthreads(); }
    if (t == 0) g_data[blockIdx.x] = red[0];
}

// ---------------------- K2/K4: FFT over b (stride FA), twiddle W_16384^{b c'}
// Stage 1 loads DIRECTLY from global (coalesced 256B rows per warp) with
// register pre-twiddle; stage 2 stores DIRECTLY to global with post-twiddle.
// Inverse (FWD=0) is launched with grid 65*64 only: the post-k4 intermediate is
// c'-Hermitian (conv is real), so only c' in [0,64] is ever consumed by K5.
template<int FWD>
__global__ __launch_bounds__(NTHR)
void k2_fftb() {
    __shared__ float2 tile[FB][GT + 1];
    const int t  = threadIdx.x;
    const int cp = blockIdx.x >> 6;             // c' ; FA/GT = 64
    const int a0 = (blockIdx.x & 63) * GT;
    const float sgn = FWD ? 1.f : -1.f;

    // stage 1: global -> registers -> dft8 -> smem
    for (int q = t; q < 512; q += NTHR) {
        int g = q & 31, j = q >> 5;
        float2 u[8];
#pragma unroll
        for (int k = 0; k < 8; k++) {
            int b = j + (k << 4);
            float2 v = g_Z[a0 + g + FA * b + AB * cp];
            if (FWD) v = cmul(v, g_W16384[b * cp]);       // pre-twiddle (uniform/row)
            u[k] = v;
        }
        dft8(u, sgn);
        float2 w1 = g_W128[j]; w1.y *= sgn;
        twiddle_chain8(u, w1);
#pragma unroll
        for (int k = 0; k < 8; k++) tile[j + (k << 4)][g] = u[k];
    }
    __syncthreads();

    // stage 2: smem -> registers -> 16-pt -> DIRECT global store
    {
        int g = t & 31, m = t >> 5;
        int base = m << 4;
        float2 e0[8], e1[8];
#pragma unroll
        for (int k = 0; k < 8; k++) {
            e0[k] = tile[base + (k << 1)][g];
            e1[k] = tile[base + (k << 1) + 1][g];
        }
        dft8(e0, sgn); dft8(e1, sgn);
#pragma unroll
        for (int k = 1; k < 8; k++) {
            float2 w = g_W128[k << 3]; w.y *= sgn;        // W16^k
            e1[k] = cmul(e1[k], w);
        }
#pragma unroll
        for (int k = 0; k < 8; k++) {
            int p0 = base + (k << 1), p1 = p0 + 1;
            int bb0 = f128(p0), bb1 = f128(p1);
            float2 v0 = cadd(e0[k], e1[k]);
            float2 v1 = csub(e0[k], e1[k]);
            if (!FWD) {                                    // post-twiddle (uniform/row)
                float2 w0 = g_W16384[bb0 * cp]; w0.y = -w0.y;
                float2 w1 = g_W16384[bb1 * cp]; w1.y = -w1.y;
                v0 = cmul(v0, w0); v1 = cmul(v1, w1);
            }
            g_Z[a0 + g + FA * bb0 + AB * cp] = v0;
            g_Z[a0 + g + FA * bb1 + AB * cp] = v1;
        }
    }
}

// -------- K3 stage helpers: 2048 = 8*8*8*4, XOR-swizzled smem layout SW()
__device__ __forceinline__ void k3_r8(float2 (*sm)[FA], int nrow, int t,
                                      int ls, int tmul, int inv) {
    const int s   = 1 << ls;
    const int tot = nrow << 8;      // 256 butterflies per row
    for (int q = t; q < tot; q += NTHR) {
        int row = q >> 8, qq = q & 255;
        int j = qq & (s - 1), m = qq >> ls;
        int base = (m << (ls + 3)) + j;
        float2 u[8];
#pragma unroll
        for (int k = 0; k < 8; k++) u[k] = sm[row][SW(base + (k << ls))];
        float2 w1 = g_W2048[tmul * j];          // single coalesced twiddle load
        if (!inv) {
            dft8(u, 1.f);
            twiddle_chain8(u, w1);
        } else {
            // DIT inverse: conj twiddle BEFORE inverse DFT8
            w1.y = -w1.y;
            twiddle_chain8(u, w1);
            dft8(u, -1.f);
        }
#pragma unroll
        for (int k = 0; k < 8; k++) sm[row][SW(base + (k << ls))] = u[k];
    }
    __syncthreads();
}

// radix-4 span-1 (kept for the h==0 block's unfused path)
__device__ __forceinline__ void k3_r4(float2 (*sm)[FA], int nrow, int t, float sgn) {
    const int tot = nrow << 9;      // 512 quads per row
    for (int q = t; q < tot; q += NTHR) {
        int row = q >> 9, b = (q & 511) << 2;
        float2* rowp = sm[row];
        float4 lo = *reinterpret_cast<const float4*>(&rowp[SW(b)]);
        float4 hi = *reinterpret_cast<const float4*>(&rowp[SW(b + 2)]);
        float2 u[4] = { make_float2(lo.x, lo.y), make_float2(lo.z, lo.w),
                        make_float2(hi.x, hi.y), make_float2(hi.z, hi.w) };
        dft4(u, sgn);
        *reinterpret_cast<float4*>(&rowp[SW(b)])     = make_float4(u[0].x, u[0].y, u[1].x, u[1].y);
        *reinterpret_cast<float4*>(&rowp[SW(b + 2)]) = make_float4(u[2].x, u[2].y, u[3].x, u[3].y);
    }
    __syncthreads();
}

__device__ __forceinline__ float2 herm_P(float2 z1, float2 z2) {
    // DU = (z1 + conj z2)/2 ; B = -i/2 * (z1 - conj z2) ; P = DU*B
    float2 du = make_float2(0.5f * (z1.x + z2.x), 0.5f * (z1.y - z2.y));
    float2 bv = make_float2(0.5f * (z1.y + z2.y), -0.5f * (z1.x - z2.x));
    return cmul(du, bv);
}

// -------- K3: fwd DIF over a (+twiddle), pointwise in scrambled domain, inverse DIT
// Compact grid: 8193 blocks, every block active (pair enumerated in closed form).
// Pairing identity: pos2048(2047 - f) == 2047 - pos2048(f)  (all digits complement)
// -> partner of POSITION p is 2047 - p; quad w pairs with quad 511 - w, elem e <-> 3-e.
// Middle (r4 fwd + pairing + r4 inv) is fused into ONE register pass for all
// blocks except idx==0 (h==0 has the (2048-f) mod 2048 partner map).
// Output chunks with c' > 64 are never consumed downstream (c'-Hermitian
// symmetry, K4 runs only c' <= 64) -> skip row1's inverse stages AND store.
__global__ __launch_bounds__(NTHR)
void k3_core() {
    __shared__ __align__(16) float2 sm[2][FA];   // 32 KB, XOR-swizzled
    const int t   = threadIdx.x;
    const int idx = blockIdx.x;
    int b1, c1;
    if (idx < 65)       { c1 = 0;  b1 = idx; }
    else if (idx < 129) { c1 = 64; b1 = idx - 65; }
    else                { int r = idx - 129; c1 = 1 + (r >> 7); b1 = r & 127; }
    const int h1 = b1 + (c1 << LB);
    int h2;
    if (c1 > 0)      h2 = (FB - 1 - b1) + ((FC - c1) << LB);
    else if (b1 > 0) h2 = FB - b1;
    else             h2 = 0;
    const bool self = (h1 == h2);
    const int  nrow = self ? 1 : 2;
    const int  b2 = h2 & (FB - 1), c2 = h2 >> LB;
    const int  hk1 = c1 + FC * b1;             // frequency weight c' + FC*b'
    const int  hk2 = c2 + FC * b2;
    const bool keep1 = (c2 <= 64);             // row1 consumed downstream?
    const int  nrow_inv = keep1 ? nrow : 1;    // rows needing inverse transform

    // fused: float4 load + forward pre-twiddle W_N^{a*hk} (e < N, no mod: 2047*16383 < 2^25)
    for (int i = t; i < (nrow << (LA - 1)); i += NTHR) {
        int row = i >> (LA - 1);
        int aa  = (i & ((FA >> 1) - 1)) << 1;
        int hk  = row ? hk2 : hk1;
        float4 q4 = *reinterpret_cast<const float4*>(g_Z + (row ? h2 : h1) * FA + aa);
        int e0 = aa * hk, e1 = e0 + hk;
        float2 w0 = cmul(g_Whi[e0 >> 12], g_Wlo[e0 & 4095]);
        float2 w1 = cmul(g_Whi[e1 >> 12], g_Wlo[e1 & 4095]);
        float2 v0 = cmul(make_float2(q4.x, q4.y), w0);
        float2 v1 = cmul(make_float2(q4.z, q4.w), w1);
        *reinterpret_cast<float4*>(&sm[row][SW(aa)]) = make_float4(v0.x, v0.y, v1.x, v1.y);
    }
    __syncthreads();

    // forward DIF: radix-8 x3 (output after fused middle is digit-scrambled pos2048)
    k3_r8(sm, nrow, t, 8, 1,  0);   // sub-len 2048, span 256
    k3_r8(sm, nrow, t, 5, 8,  0);   // sub-len 256,  span 32
    k3_r8(sm, nrow, t, 2, 64, 0);   // sub-len 32,   span 4

    if (idx == 0) {
        // h == 0: unfused path (partner f2 = (FA - f1) mod FA)
        k3_r4(sm, nrow, t, 1.f);
        for (int a1 = t; a1 <= FA / 2; a1 += NTHR) {
            if (a1 == 0 || a1 == FA / 2) {
                int p = pos2048(a1);
                float2 z = sm[0][SW(p)];
                sm[0][SW(p)] = make_float2(z.x * z.y, 0.f);   // DU=Re(z), B=Im(z)
            } else {
                int p1 = pos2048(a1), p2 = pos2048(FA - a1);
                float2 z1 = sm[0][SW(p1)];
                float2 z2 = sm[0][SW(p2)];
                float2 P  = herm_P(z1, z2);
                sm[0][SW(p1)] = P;
                sm[0][SW(p2)] = make_float2(P.x, -P.y);
            }
        }
        __syncthreads();
        k3_r4(sm, nrow, t, -1.f);
    } else {
        // fused middle: r4 fwd + Hermitian pairing + r4 inv, one register pass
        const int ntask = self ? 256 : 512;
        for (int w = t; w < ntask; w += NTHR) {
            float2* rA = sm[0];
            float2* rB = self ? sm[0] : sm[1];
            const int ba = w << 2;
            const int bb = (511 - w) << 2;
            float4 alo = *reinterpret_cast<const float4*>(&rA[SW(ba)]);
            float4 ahi = *reinterpret_cast<const float4*>(&rA[SW(ba + 2)]);
            float4 blo = *reinterpret_cast<const float4*>(&rB[SW(bb)]);
            float4 bhi = *reinterpret_cast<const float4*>(&rB[SW(bb + 2)]);
            float2 uA[4] = { make_float2(alo.x, alo.y), make_float2(alo.z, alo.w),
                             make_float2(ahi.x, ahi.y), make_float2(ahi.z, ahi.w) };
            float2 uB[4] = { make_float2(blo.x, blo.y), make_float2(blo.z, blo.w),
                             make_float2(bhi.x, bhi.y), make_float2(bhi.z, bhi.w) };
            dft4(uA, 1.f); dft4(uB, 1.f);
#pragma unroll
            for (int e = 0; e < 4; e++) {
                // partner of position ba+e is bb+(3-e) (= 2047 - (ba+e))
                float2 P = herm_P(uA[e], uB[3 - e]);
                uA[e]     = P;
                uB[3 - e] = make_float2(P.x, -P.y);
            }
            dft4(uA, -1.f);
            *reinterpret_cast<float4*>(&rA[SW(ba)])     = make_float4(uA[0].x, uA[0].y, uA[1].x, uA[1].y);
            *reinterpret_cast<float4*>(&rA[SW(ba + 2)]) = make_float4(uA[2].x, uA[2].y, uA[3].x, uA[3].y);
            if (self || keep1) {               // row1 (rB) consumed downstream?
                dft4(uB, -1.f);
                *reinterpret_cast<float4*>(&rB[SW(bb)])     = make_float4(uB[0].x, uB[0].y, uB[1].x, uB[1].y);
                *reinterpret_cast<float4*>(&rB[SW(bb + 2)]) = make_float4(uB[2].x, uB[2].y, uB[3].x, uB[3].y);
            }
        }
        __syncthreads();
    }

    // inverse DIT: mirror order, conj twiddles (scrambled in -> natural out).
    // Only nrow_inv rows — row1 skipped entirely when its chunk is dead.
    k3_r8(sm, nrow_inv, t, 2, 64, 1);
    k3_r8(sm, nrow_inv, t, 5, 8,  1);
    k3_r8(sm, nrow_inv, t, 8, 1,  1);

    // fused: inverse post-twiddle conj(W_N^{a*hk}) + float4 store
    for (int i = t; i < (nrow_inv << (LA - 1)); i += NTHR) {
        int row = i >> (LA - 1);
        int aa  = (i & ((FA >> 1) - 1)) << 1;
        int hk  = row ? hk2 : hk1;
        int e0 = aa * hk, e1 = e0 + hk;
        float2 w0 = cmul(g_Whi[e0 >> 12], g_Wlo[e0 & 4095]); w0.y = -w0.y;
        float2 w1 = cmul(g_Whi[e1 >> 12], g_Wlo[e1 & 4095]); w1.y = -w1.y;
        float4 q4 = *reinterpret_cast<const float4*>(&sm[row][SW(aa)]);
        float2 v0 = cmul(make_float2(q4.x, q4.y), w0);
        float2 v1 = cmul(make_float2(q4.z, q4.w), w1);
        *reinterpret_cast<float4*>(g_Z + (row ? h2 : h1) * FA + aa) =
            make_float4(v0.x, v0.y, v1.x, v1.y);
    }
}

// -------- K5: inverse FFT over c' with stage-2 fused into the physics epilogue.
// Stage 1 reads DIRECTLY from global: slabs c' in [0,64] as stored, rows
// 65..127 as conj(slab 128-row) (c'-Hermitian symmetry; 2nd touch is L1-hot).
// Only even positions p (c = f128(p) < 64) are ever needed -> even half in regs.
__global__ __launch_bounds__(NTHR)
void k5_inv_epi(const float* __restrict__ up, float coefN) {
    __shared__ float2 tile[FC][GT + 1];
    __shared__ double red[NTHR];
    const int t   = threadIdx.x;
    const int ab0 = blockIdx.x * GT;

    // stage 1: global (+mirror conj) -> registers -> inverse dft8 -> smem
    for (int q = t; q < 512; q += NTHR) {
        int g = q & 31, j = q >> 5;
        float2 u[8];
#pragma unroll
        for (int k = 0; k < 8; k++) {
            int row = j + (k << 4);
            float2 v;
            if (row <= 64) {
                v = g_Z[ab0 + g + AB * row];
            } else {
                v = g_Z[ab0 + g + AB * (128 - row)];
                v.y = -v.y;
            }
            u[k] = v;
        }
        dft8(u, -1.f);
        float2 w1 = g_W128[j]; w1.y = -w1.y;
        twiddle_chain8(u, w1);
#pragma unroll
        for (int k = 0; k < 8; k++) tile[j + (k << 4)][g] = u[k];
    }
    __syncthreads();

    // fused stage 2 (even outputs only) + epilogue
    float acc = 0.f;
    {
        int g = t & 31, m = t >> 5;            // m in [0,8)
        int base = m << 4;
        float2 e0[8], e1[8];
#pragma unroll
        for (int k = 0; k < 8; k++) {
            e0[k] = tile[base + (k << 1)][g];
            e1[k] = tile[base + (k << 1) + 1][g];
        }
        dft8(e0, -1.f); dft8(e1, -1.f);
#pragma unroll
        for (int k = 1; k < 8; k++) {
            float2 w = g_W128[k << 3]; w.y = -w.y;   // conj W16^k
            e1[k] = cmul(e1[k], w);
        }
#pragma unroll
        for (int k = 0; k < 8; k++) {
            float convr = e0[k].x + e1[k].x;          // even output, real part
            int c = m + (k << 3);                     // f128(16m + 2k) = m + 8k  (< 64)
            int n = ab0 + g + AB * c;                 // conv index
            int mres = n + 1;                         // frac[mres] = coef*conv[mres-1]
            if (mres < MTOT) {
                float um = __ldg(up + mres);
                float ut = 0.f;
                if ((mres & 16383) != 16383) ut = __ldg(up + mres + 1) - um;  // last col: u_t=0
                float r = ut - coefN * convr;
                acc = fmaf(r, r, acc);
            }
        }
    }

    red[t] = (double)acc;
    __syncthreads();
    for (int s = NTHR / 2; s > 0; s >>= 1) { if (t < s) red[t] += red[t + s]; __syncthreads(); }
    if (t == 0) g_phys[blockIdx.x] = red[0];
}

// -------- finalize
__global__ void k_fin(const float* __restrict__ up, float* __restrict__ out) {
    __shared__ double rp[256], rd[256];
    int t = threadIdx.x;
    double sp = 0.0, sd = 0.0;
    for (int i = t; i < NBLK; i += 256) { sp += g_phys[i]; sd += g_data[i]; }
    rp[t] = sp; rd[t] = sd;
    __syncthreads();
    for (int s = 128; s > 0; s >>= 1) {
        if (t < s) { rp[t] += rp[t + s]; rd[t] += rd[t + s]; }
        __syncthreads();
    }
    if (t == 0) {
        double r0 = (double)up[1] - (double)up[0];    // m = 0 residual: u_t[0] - 0
        double phys = (rp[0] + r0 * r0) / (double)MTOT;
        double data = rd[0] / (double)MTOT;
        out[0] = (float)(data + 0.1 * phys);
        out[1] = (float)data;
        out[2] = (float)phys;
    }
}

extern "C" void kernel_launch(void* const* d_in, const int* in_sizes, int n_in,
                              void* d_out, int out_size)
{
    const float* up  = (const float*)d_in[0];  // u_pred
    const float* utr = (const float*)d_in[1];  // u_true
    (void)in_sizes; (void)n_in; (void)out_size;

    // coef = sqrt(M-1)/Gamma(1.5); fold the 1/N of the fwd+inv FFT product in here.
    double coefN = sqrt((double)(MTOT - 1)) / 0.886226925452758013649083741670572
                   / (double)NF;

    k_tw<<<64, 256>>>();
    k1_pack_fft<<<NBLK, NTHR>>>(up, utr);
    k2_fftb<1><<<NBLK, NTHR>>>();
    k3_core<<<8193, NTHR>>>();
    k2_fftb<0><<<65 * 64, NTHR>>>();           // only c' <= 64 needed (Hermitian)
    k5_inv_epi<<<NBLK, NTHR>>>(up, (float)coefN);
    k_fin<<<1, 256>>>(up, (float*)d_out);
}

// round 13
// speedup vs baseline: 4.9751x; 1.0146x over previous
#include <cuda_runtime.h>
#include <math.h>

// FFT size N = 2^25 = FA * FB * FC, position n = a + FA*b + AB*c
#define LN   25
#define NF   (1 << LN)
#define LA   11
#define FA   (1 << LA)          // 2048
#define LB   7
#define FB   (1 << LB)          // 128
#define LC   7
#define FC   (1 << LC)          // 128
#define AB   (FA * FB)          // 262144
#define GT   32                 // tile width (consecutive fast-dim elements)
#define NTHR 256

#define MTOT (1 << 24)          // problem size B*N = 2^24
#define NBLK (AB / GT)          // 8192 blocks for K1/K5

// XOR swizzle for k3 smem: flips element bits [1:4) from bits [4:7).
// Bijective, preserves 2-element (16B) alignment -> float4-safe.
#define SW(p) ((p) ^ ((((p) >> 4) & 7) << 1))

// 256 MB spectral work buffer + twiddle tables + partials (no runtime allocation)
__device__ float2 g_Z[NF];
__device__ float2 g_W16384[16384];  // W_16384^m (full)
__device__ float2 g_W2048[2048];    // W_2048^m  (full)
__device__ float2 g_W128[128];      // W_128^m   (full)
__device__ float2 g_Wlo[4096];      // W_N^j,        j < 4096
__device__ float2 g_Whi[8192];      // W_N^{4096 j}, j < 8192
__device__ double g_data[NBLK];
__device__ double g_phys[NBLK];

__device__ __forceinline__ float2 cadd(float2 a, float2 b) { return make_float2(a.x + b.x, a.y + b.y); }
__device__ __forceinline__ float2 csub(float2 a, float2 b) { return make_float2(a.x - b.x, a.y - b.y); }
__device__ __forceinline__ float2 cmul(float2 a, float2 b) {
    return make_float2(fmaf(a.x, b.x, -a.y * b.y), fmaf(a.x, b.y, a.y * b.x));
}
// multiply by -i (sgn=+1, forward) or +i (sgn=-1, inverse)
__device__ __forceinline__ float2 crot(float2 a, float sgn) { return make_float2(sgn * a.y, -sgn * a.x); }

// 8-point DFT in registers, natural-order outputs. sgn=+1 fwd, -1 inverse (unnormalized).
__device__ __forceinline__ void dft8(float2* u, float sgn) {
    const float C = 0.70710678118654752440f;
    float2 t0 = cadd(u[0], u[4]), t1 = cadd(u[1], u[5]);
    float2 t2 = cadd(u[2], u[6]), t3 = cadd(u[3], u[7]);
    float2 m4 = csub(u[0], u[4]), m5 = csub(u[1], u[5]);
    float2 m6 = csub(u[2], u[6]), m7 = csub(u[3], u[7]);
    float2 t4 = m4;
    float2 t5 = cmul(m5, make_float2(C, -sgn * C));    // W8^1
    float2 t6 = crot(m6, sgn);                         // W8^2
    float2 t7 = cmul(m7, make_float2(-C, -sgn * C));   // W8^3
    float2 s0 = cadd(t0, t2), s2 = csub(t0, t2);
    float2 s1 = cadd(t1, t3), s3 = crot(csub(t1, t3), sgn);
    float2 r0 = cadd(t4, t6), r2 = csub(t4, t6);
    float2 r1 = cadd(t5, t7), r3 = crot(csub(t5, t7), sgn);
    u[0] = cadd(s0, s1); u[4] = csub(s0, s1);
    u[2] = cadd(s2, s3); u[6] = csub(s2, s3);
    u[1] = cadd(r0, r1); u[5] = csub(r0, r1);
    u[3] = cadd(r2, r3); u[7] = csub(r2, r3);
}

// 8-point DFT with inputs 4..7 known to be zero (k1 zero-padding). In: u[0..3]; out: u[0..7].
__device__ __forceinline__ void dft8h(float2* u, float sgn) {
    const float C = 0.70710678118654752440f;
    float2 t0 = u[0], t1 = u[1], t2 = u[2], t3 = u[3];
    float2 t4 = u[0];
    float2 t5 = cmul(u[1], make_float2(C, -sgn * C));
    float2 t6 = crot(u[2], sgn);
    float2 t7 = cmul(u[3], make_float2(-C, -sgn * C));
    float2 s0 = cadd(t0, t2), s2 = csub(t0, t2);
    float2 s1 = cadd(t1, t3), s3 = crot(csub(t1, t3), sgn);
    float2 r0 = cadd(t4, t6), r2 = csub(t4, t6);
    float2 r1 = cadd(t5, t7), r3 = crot(csub(t5, t7), sgn);
    u[0] = cadd(s0, s1); u[4] = csub(s0, s1);
    u[2] = cadd(s2, s3); u[6] = csub(s2, s3);
    u[1] = cadd(r0, r1); u[5] = csub(r0, r1);
    u[3] = cadd(r2, r3); u[7] = csub(r2, r3);
}

// 4-point DFT in registers, natural order.
__device__ __forceinline__ void dft4(float2* u, float sgn) {
    float2 a0 = cadd(u[0], u[2]), b0 = csub(u[0], u[2]);
    float2 a1 = cadd(u[1], u[3]), b1 = crot(csub(u[1], u[3]), sgn);
    u[0] = cadd(a0, a1); u[2] = csub(a0, a1);
    u[1] = cadd(b0, b1); u[3] = csub(b0, b1);
}

// apply w^k (k=1..7) to u[1..7] via cmul chain from a single loaded w1
__device__ __forceinline__ void twiddle_chain8(float2* u, float2 w1) {
    float2 w = w1;
    u[1] = cmul(u[1], w);
#pragma unroll
    for (int k = 2; k < 8; k++) { w = cmul(w, w1); u[k] = cmul(u[k], w); }
}

// digit-reversal maps
// 128 = 8*8*2 DIF: position p -> natural frequency
__device__ __forceinline__ int f128(int p) {
    return (p >> 4) + (((p >> 1) & 7) << 3) + ((p & 1) << 6);
}
// 2048 = 8*8*8*4 DIF: natural frequency k -> scrambled position
__device__ __forceinline__ int pos2048(int k) {
    return ((k & 7) << 8) + (((k >> 3) & 7) << 5) + (((k >> 6) & 7) << 2) + (k >> 9);
}

// ---------------------------------------------------------------- twiddle init
__global__ void k_tw() {
    int idx = blockIdx.x * 128 + threadIdx.x;   // 128 blocks * 128 = 16384
    const double P2 = 6.283185307179586476925286766559;
    if (idx < 16384) { double a = -P2 * idx / 16384.0;    g_W16384[idx] = make_float2((float)cos(a), (float)sin(a)); }
    if (idx < 8192)  { double a = -P2 * idx / 8192.0;     g_Whi[idx]    = make_float2((float)cos(a), (float)sin(a)); }
    if (idx < 4096)  { double a = -P2 * idx / (double)NF; g_Wlo[idx]    = make_float2((float)cos(a), (float)sin(a)); }
    if (idx < 2048)  { double a = -P2 * idx / 2048.0;     g_W2048[idx]  = make_float2((float)cos(a), (float)sin(a)); }
    if (idx < 128)   { double a = -P2 * idx / 128.0;      g_W128[idx]   = make_float2((float)cos(a), (float)sin(a)); }
}

// ------------------------------------- K1: pack Z = du + i*b, FFT over c, data loss
// Input rows c >= 64 are structurally zero (n >= MTOT) -> half-input stage 1.
// Stage 2 writes directly to global (register->STG, coalesced per warp).
__global__ __launch_bounds__(NTHR)
void k1_pack_fft(const float* __restrict__ up, const float* __restrict__ utr) {
    __shared__ float2 tile[FC][GT + 1];
    __shared__ double red[NTHR];
    const int t   = threadIdx.x;
    const int ab0 = blockIdx.x * GT;

    // load rows c < 64 only, float4-vectorized (4 g per thread); 2 iterations unrolled
    float acc = 0.f;
#pragma unroll
    for (int i = t; i < (GT / 4) * 64; i += NTHR) {      // 512 items
        int c  = i >> 3;
        int gq = (i & 7) << 2;
        int n  = ab0 + gq + AB * c;                      // n+3 < MTOT guaranteed (c<64)
        float4 a4 = *reinterpret_cast<const float4*>(up + n);
        float4 b4 = *reinterpret_cast<const float4*>(utr + n);
        float d0 = a4.x - b4.x, d1 = a4.y - b4.y, d2 = a4.z - b4.z, d3 = a4.w - b4.w;
        acc = fmaf(d0, d0, acc); acc = fmaf(d1, d1, acc);
        acc = fmaf(d2, d2, acc); acc = fmaf(d3, d3, acc);
        float unext = (n + 4 < MTOT) ? __ldg(up + n + 4) : 0.f;
        float du0 = a4.y - a4.x, du1 = a4.z - a4.y, du2 = a4.w - a4.z, du3 = unext - a4.w;
        // EXACT replica of the reference fp32 weights (incl. cancellation noise).
        // Explicit 5-sqrt CSE: adjacent weights share endpoints.
        float s0 = __fsqrt_rn((float)n);
        float s1 = __fsqrt_rn((float)(n + 1));
        float s2 = __fsqrt_rn((float)(n + 2));
        float s3 = __fsqrt_rn((float)(n + 3));
        float s4 = __fsqrt_rn((float)(n + 4));
        float bw0 = s1 - s0, bw1 = s2 - s1, bw2 = s3 - s2, bw3 = s4 - s3;
        if (n + 3 >= MTOT - 1) {                          // only last elements of last block
            if (n + 0 >= MTOT - 1) { du0 = 0.f; bw0 = 0.f; }
            if (n + 1 >= MTOT - 1) { du1 = 0.f; bw1 = 0.f; }
            if (n + 2 >= MTOT - 1) { du2 = 0.f; bw2 = 0.f; }
            du3 = 0.f; bw3 = 0.f;
        }
        tile[c][gq + 0] = make_float2(du0, bw0);
        tile[c][gq + 1] = make_float2(du1, bw1);
        tile[c][gq + 2] = make_float2(du2, bw2);
        tile[c][gq + 3] = make_float2(du3, bw3);
    }
    __syncthreads();

    // stage 1 with zero top half: reads rows j+16k for k<4 (all < 64); 2 iters unrolled
#pragma unroll
    for (int q = t; q < 512; q += NTHR) {
        int g = q & 31, j = q >> 5;
        float2 u[8];
#pragma unroll
        for (int k = 0; k < 4; k++) u[k] = tile[j + (k << 4)][g];
        dft8h(u, 1.f);
        float2 w1 = g_W128[j];
        twiddle_chain8(u, w1);
#pragma unroll
        for (int k = 0; k < 8; k++) tile[j + (k << 4)][g] = u[k];
    }
    __syncthreads();

    // stage 2 in registers + DIRECT global store (digit-reversal in slab index)
    {
        int g = t & 31, m = t >> 5;
        int base = m << 4;
        float2 e0[8], e1[8];
#pragma unroll
        for (int k = 0; k < 8; k++) {
            e0[k] = tile[base + (k << 1)][g];
            e1[k] = tile[base + (k << 1) + 1][g];
        }
        dft8(e0, 1.f); dft8(e1, 1.f);
#pragma unroll
        for (int k = 1; k < 8; k++) e1[k] = cmul(e1[k], g_W128[k << 3]);   // W16^k
#pragma unroll
        for (int k = 0; k < 8; k++) {
            int p0 = base + (k << 1), p1 = p0 + 1;
            g_Z[ab0 + g + AB * f128(p0)] = cadd(e0[k], e1[k]);
            g_Z[ab0 + g + AB * f128(p1)] = csub(e0[k], e1[k]);
        }
    }

    red[t] = (double)acc;
    __syncthreads();
    for (int s = NTHR / 2; s > 0; s >>= 1) { if (t < s) red[t] += red[t + s]; __syncthreads(); }
    if (t == 0) g_data[blockIdx.x] = red[0];
}

// ---------------------- K2/K4: FFT over b (stride FA), twiddle W_16384^{b c'}
// Stage 1 loads DIRECTLY from global (coalesced 256B rows per warp) with
// register pre-twiddle; stage 2 stores DIRECTLY to global with post-twiddle.
// Inverse (FWD=0) is launched with grid 65*64 only: the post-k4 intermediate is
// c'-Hermitian (conv is real), so only c' in [0,64] is ever consumed by K5.
template<int FWD>
__global__ __launch_bounds__(NTHR)
void k2_fftb() {
    __shared__ float2 tile[FB][GT + 1];
    const int t  = threadIdx.x;
    const int cp = blockIdx.x >> 6;             // c' ; FA/GT = 64
    const int a0 = (blockIdx.x & 63) * GT;
    const float sgn = FWD ? 1.f : -1.f;

    // stage 1: global -> registers -> dft8 -> smem; 2 iterations unrolled (16 LDGs in flight)
#pragma unroll
    for (int q = t; q < 512; q += NTHR) {
        int g = q & 31, j = q >> 5;
        float2 u[8];
#pragma unroll
        for (int k = 0; k < 8; k++) {
            int b = j + (k << 4);
            float2 v = g_Z[a0 + g + FA * b + AB * cp];
            if (FWD) v = cmul(v, g_W16384[b * cp]);       // pre-twiddle (uniform/row)
            u[k] = v;
        }
        dft8(u, sgn);
        float2 w1 = g_W128[j]; w1.y *= sgn;
        twiddle_chain8(u, w1);
#pragma unroll
        for (int k = 0; k < 8; k++) tile[j + (k << 4)][g] = u[k];
    }
    __syncthreads();

    // stage 2: smem -> registers -> 16-pt -> DIRECT global store
    {
        int g = t & 31, m = t >> 5;
        int base = m << 4;
        float2 e0[8], e1[8];
#pragma unroll
        for (int k = 0; k < 8; k++) {
            e0[k] = tile[base + (k << 1)][g];
            e1[k] = tile[base + (k << 1) + 1][g];
        }
        dft8(e0, sgn); dft8(e1, sgn);
#pragma unroll
        for (int k = 1; k < 8; k++) {
            float2 w = g_W128[k << 3]; w.y *= sgn;        // W16^k
            e1[k] = cmul(e1[k], w);
        }
#pragma unroll
        for (int k = 0; k < 8; k++) {
            int p0 = base + (k << 1), p1 = p0 + 1;
            int bb0 = f128(p0), bb1 = f128(p1);
            float2 v0 = cadd(e0[k], e1[k]);
            float2 v1 = csub(e0[k], e1[k]);
            if (!FWD) {                                    // post-twiddle (uniform/row)
                float2 w0 = g_W16384[bb0 * cp]; w0.y = -w0.y;
                float2 w1 = g_W16384[bb1 * cp]; w1.y = -w1.y;
                v0 = cmul(v0, w0); v1 = cmul(v1, w1);
            }
            g_Z[a0 + g + FA * bb0 + AB * cp] = v0;
            g_Z[a0 + g + FA * bb1 + AB * cp] = v1;
        }
    }
}

// -------- K3 stage helpers: 2048 = 8*8*8*4, XOR-swizzled smem layout SW()
__device__ __forceinline__ void k3_r8(float2 (*sm)[FA], int nrow, int t,
                                      int ls, int tmul, int inv) {
    const int s   = 1 << ls;
    const int tot = nrow << 8;      // 256 butterflies per row
    for (int q = t; q < tot; q += NTHR) {
        int row = q >> 8, qq = q & 255;
        int j = qq & (s - 1), m = qq >> ls;
        int base = (m << (ls + 3)) + j;
        float2 u[8];
#pragma unroll
        for (int k = 0; k < 8; k++) u[k] = sm[row][SW(base + (k << ls))];
        float2 w1 = g_W2048[tmul * j];          // single coalesced twiddle load
        if (!inv) {
            dft8(u, 1.f);
            twiddle_chain8(u, w1);
        } else {
            // DIT inverse: conj twiddle BEFORE inverse DFT8
            w1.y = -w1.y;
            twiddle_chain8(u, w1);
            dft8(u, -1.f);
        }
#pragma unroll
        for (int k = 0; k < 8; k++) sm[row][SW(base + (k << ls))] = u[k];
    }
    __syncthreads();
}

// radix-4 span-1 (kept for the h==0 block's unfused path)
__device__ __forceinline__ void k3_r4(float2 (*sm)[FA], int nrow, int t, float sgn) {
    const int tot = nrow << 9;      // 512 quads per row
    for (int q = t; q < tot; q += NTHR) {
        int row = q >> 9, b = (q & 511) << 2;
        float2* rowp = sm[row];
        float4 lo = *reinterpret_cast<const float4*>(&rowp[SW(b)]);
        float4 hi = *reinterpret_cast<const float4*>(&rowp[SW(b + 2)]);
        float2 u[4] = { make_float2(lo.x, lo.y), make_float2(lo.z, lo.w),
                        make_float2(hi.x, hi.y), make_float2(hi.z, hi.w) };
        dft4(u, sgn);
        *reinterpret_cast<float4*>(&rowp[SW(b)])     = make_float4(u[0].x, u[0].y, u[1].x, u[1].y);
        *reinterpret_cast<float4*>(&rowp[SW(b + 2)]) = make_float4(u[2].x, u[2].y, u[3].x, u[3].y);
    }
    __syncthreads();
}

__device__ __forceinline__ float2 herm_P(float2 z1, float2 z2) {
    // DU = (z1 + conj z2)/2 ; B = -i/2 * (z1 - conj z2) ; P = DU*B
    float2 du = make_float2(0.5f * (z1.x + z2.x), 0.5f * (z1.y - z2.y));
    float2 bv = make_float2(0.5f * (z1.y + z2.y), -0.5f * (z1.x - z2.x));
    return cmul(du, bv);
}

// -------- K3: fwd DIF over a (+twiddle), pointwise in scrambled domain, inverse DIT
// Compact grid: 8193 blocks, every block active (pair enumerated in closed form).
// Pairing identity: pos2048(2047 - f) == 2047 - pos2048(f)  (all digits complement)
// -> partner of POSITION p is 2047 - p; quad w pairs with quad 511 - w, elem e <-> 3-e.
// Middle (r4 fwd + pairing + r4 inv) is fused into ONE register pass for all
// blocks except idx==0 (h==0 has the (2048-f) mod 2048 partner map).
// Output chunks with c' > 64 are never consumed downstream (c'-Hermitian
// symmetry, K4 runs only c' <= 64) -> skip row1's inverse stages AND store.
__global__ __launch_bounds__(NTHR)
void k3_core() {
    __shared__ __align__(16) float2 sm[2][FA];   // 32 KB, XOR-swizzled
    const int t   = threadIdx.x;
    const int idx = blockIdx.x;
    int b1, c1;
    if (idx < 65)       { c1 = 0;  b1 = idx; }
    else if (idx < 129) { c1 = 64; b1 = idx - 65; }
    else                { int r = idx - 129; c1 = 1 + (r >> 7); b1 = r & 127; }
    const int h1 = b1 + (c1 << LB);
    int h2;
    if (c1 > 0)      h2 = (FB - 1 - b1) + ((FC - c1) << LB);
    else if (b1 > 0) h2 = FB - b1;
    else             h2 = 0;
    const bool self = (h1 == h2);
    const int  nrow = self ? 1 : 2;
    const int  b2 = h2 & (FB - 1), c2 = h2 >> LB;
    const int  hk1 = c1 + FC * b1;             // frequency weight c' + FC*b'
    const int  hk2 = c2 + FC * b2;
    const bool keep1 = (c2 <= 64);             // row1 consumed downstream?
    const int  nrow_inv = keep1 ? nrow : 1;    // rows needing inverse transform

    // fused: float4 load + forward pre-twiddle W_N^{a*hk}; unroll 4 -> LDGs in flight
#pragma unroll 4
    for (int i = t; i < (nrow << (LA - 1)); i += NTHR) {
        int row = i >> (LA - 1);
        int aa  = (i & ((FA >> 1) - 1)) << 1;
        int hk  = row ? hk2 : hk1;
        float4 q4 = *reinterpret_cast<const float4*>(g_Z + (row ? h2 : h1) * FA + aa);
        int e0 = aa * hk, e1 = e0 + hk;
        float2 w0 = cmul(g_Whi[e0 >> 12], g_Wlo[e0 & 4095]);
        float2 w1 = cmul(g_Whi[e1 >> 12], g_Wlo[e1 & 4095]);
        float2 v0 = cmul(make_float2(q4.x, q4.y), w0);
        float2 v1 = cmul(make_float2(q4.z, q4.w), w1);
        *reinterpret_cast<float4*>(&sm[row][SW(aa)]) = make_float4(v0.x, v0.y, v1.x, v1.y);
    }
    __syncthreads();

    // forward DIF: radix-8 x3 (output after fused middle is digit-scrambled pos2048)
    k3_r8(sm, nrow, t, 8, 1,  0);   // sub-len 2048, span 256
    k3_r8(sm, nrow, t, 5, 8,  0);   // sub-len 256,  span 32
    k3_r8(sm, nrow, t, 2, 64, 0);   // sub-len 32,   span 4

    if (idx == 0) {
        // h == 0: unfused path (partner f2 = (FA - f1) mod FA)
        k3_r4(sm, nrow, t, 1.f);
        for (int a1 = t; a1 <= FA / 2; a1 += NTHR) {
            if (a1 == 0 || a1 == FA / 2) {
                int p = pos2048(a1);
                float2 z = sm[0][SW(p)];
                sm[0][SW(p)] = make_float2(z.x * z.y, 0.f);   // DU=Re(z), B=Im(z)
            } else {
                int p1 = pos2048(a1), p2 = pos2048(FA - a1);
                float2 z1 = sm[0][SW(p1)];
                float2 z2 = sm[0][SW(p2)];
                float2 P  = herm_P(z1, z2);
                sm[0][SW(p1)] = P;
                sm[0][SW(p2)] = make_float2(P.x, -P.y);
            }
        }
        __syncthreads();
        k3_r4(sm, nrow, t, -1.f);
    } else {
        // fused middle: r4 fwd + Hermitian pairing + r4 inv, one register pass
        const int ntask = self ? 256 : 512;
        for (int w = t; w < ntask; w += NTHR) {
            float2* rA = sm[0];
            float2* rB = self ? sm[0] : sm[1];
            const int ba = w << 2;
            const int bb = (511 - w) << 2;
            float4 alo = *reinterpret_cast<const float4*>(&rA[SW(ba)]);
            float4 ahi = *reinterpret_cast<const float4*>(&rA[SW(ba + 2)]);
            float4 blo = *reinterpret_cast<const float4*>(&rB[SW(bb)]);
            float4 bhi = *reinterpret_cast<const float4*>(&rB[SW(bb + 2)]);
            float2 uA[4] = { make_float2(alo.x, alo.y), make_float2(alo.z, alo.w),
                             make_float2(ahi.x, ahi.y), make_float2(ahi.z, ahi.w) };
            float2 uB[4] = { make_float2(blo.x, blo.y), make_float2(blo.z, blo.w),
                             make_float2(bhi.x, bhi.y), make_float2(bhi.z, bhi.w) };
            dft4(uA, 1.f); dft4(uB, 1.f);
#pragma unroll
            for (int e = 0; e < 4; e++) {
                // partner of position ba+e is bb+(3-e) (= 2047 - (ba+e))
                float2 P = herm_P(uA[e], uB[3 - e]);
                uA[e]     = P;
                uB[3 - e] = make_float2(P.x, -P.y);
            }
            dft4(uA, -1.f);
            *reinterpret_cast<float4*>(&rA[SW(ba)])     = make_float4(uA[0].x, uA[0].y, uA[1].x, uA[1].y);
            *reinterpret_cast<float4*>(&rA[SW(ba + 2)]) = make_float4(uA[2].x, uA[2].y, uA[3].x, uA[3].y);
            if (self || keep1) {               // row1 (rB) consumed downstream?
                dft4(uB, -1.f);
                *reinterpret_cast<float4*>(&rB[SW(bb)])     = make_float4(uB[0].x, uB[0].y, uB[1].x, uB[1].y);
                *reinterpret_cast<float4*>(&rB[SW(bb + 2)]) = make_float4(uB[2].x, uB[2].y, uB[3].x, uB[3].y);
            }
        }
        __syncthreads();
    }

    // inverse DIT: mirror order, conj twiddles (scrambled in -> natural out).
    // Only nrow_inv rows — row1 skipped entirely when its chunk is dead.
    k3_r8(sm, nrow_inv, t, 2, 64, 1);
    k3_r8(sm, nrow_inv, t, 5, 8,  1);
    k3_r8(sm, nrow_inv, t, 8, 1,  1);

    // fused: inverse post-twiddle conj(W_N^{a*hk}) + float4 store; unroll 4
#pragma unroll 4
    for (int i = t; i < (nrow_inv << (LA - 1)); i += NTHR) {
        int row = i >> (LA - 1);
        int aa  = (i & ((FA >> 1) - 1)) << 1;
        int hk  = row ? hk2 : hk1;
        int e0 = aa * hk, e1 = e0 + hk;
        float2 w0 = cmul(g_Whi[e0 >> 12], g_Wlo[e0 & 4095]); w0.y = -w0.y;
        float2 w1 = cmul(g_Whi[e1 >> 12], g_Wlo[e1 & 4095]); w1.y = -w1.y;
        float4 q4 = *reinterpret_cast<const float4*>(&sm[row][SW(aa)]);
        float2 v0 = cmul(make_float2(q4.x, q4.y), w0);
        float2 v1 = cmul(make_float2(q4.z, q4.w), w1);
        *reinterpret_cast<float4*>(g_Z + (row ? h2 : h1) * FA + aa) =
            make_float4(v0.x, v0.y, v1.x, v1.y);
    }
}

// -------- K5: inverse FFT over c' with stage-2 fused into the physics epilogue.
// Stage 1 reads DIRECTLY from global: slabs c' in [0,64] as stored, rows
// 65..127 as conj(slab 128-row) (c'-Hermitian symmetry; 2nd touch is L1-hot).
// Only even positions p (c = f128(p) < 64) are ever needed -> even half in regs.
__global__ __launch_bounds__(NTHR)
void k5_inv_epi(const float* __restrict__ up, float coefN) {
    __shared__ float2 tile[FC][GT + 1];
    __shared__ double red[NTHR];
    const int t   = threadIdx.x;
    const int ab0 = blockIdx.x * GT;

    // stage 1: global (+mirror conj) -> registers -> inverse dft8 -> smem; 2 iters unrolled
#pragma unroll
    for (int q = t; q < 512; q += NTHR) {
        int g = q & 31, j = q >> 5;
        float2 u[8];
#pragma unroll
        for (int k = 0; k < 8; k++) {
            int row = j + (k << 4);
            float2 v;
            if (row <= 64) {
                v = g_Z[ab0 + g + AB * row];
            } else {
                v = g_Z[ab0 + g + AB * (128 - row)];
                v.y = -v.y;
            }
            u[k] = v;
        }
        dft8(u, -1.f);
        float2 w1 = g_W128[j]; w1.y = -w1.y;
        twiddle_chain8(u, w1);
#pragma unroll
        for (int k = 0; k < 8; k++) tile[j + (k << 4)][g] = u[k];
    }
    __syncthreads();

    // fused stage 2 (even outputs only) + epilogue
    float acc = 0.f;
    {
        int g = t & 31, m = t >> 5;            // m in [0,8)
        int base = m << 4;
        float2 e0[8], e1[8];
#pragma unroll
        for (int k = 0; k < 8; k++) {
            e0[k] = tile[base + (k << 1)][g];
            e1[k] = tile[base + (k << 1) + 1][g];
        }
        dft8(e0, -1.f); dft8(e1, -1.f);
#pragma unroll
        for (int k = 1; k < 8; k++) {
            float2 w = g_W128[k << 3]; w.y = -w.y;   // conj W16^k
            e1[k] = cmul(e1[k], w);
        }
#pragma unroll
        for (int k = 0; k < 8; k++) {
            float convr = e0[k].x + e1[k].x;          // even output, real part
            int c = m + (k << 3);                     // f128(16m + 2k) = m + 8k  (< 64)
            int n = ab0 + g + AB * c;                 // conv index
            int mres = n + 1;                         // frac[mres] = coef*conv[mres-1]
            if (mres < MTOT) {
                float um = __ldg(up + mres);
                float ut = 0.f;
                if ((mres & 16383) != 16383) ut = __ldg(up + mres + 1) - um;  // last col: u_t=0
                float r = ut - coefN * convr;
                acc = fmaf(r, r, acc);
            }
        }
    }

    red[t] = (double)acc;
    __syncthreads();
    for (int s = NTHR / 2; s > 0; s >>= 1) { if (t < s) red[t] += red[t + s]; __syncthreads(); }
    if (t == 0) g_phys[blockIdx.x] = red[0];
}

// -------- finalize
__global__ void k_fin(const float* __restrict__ up, float* __restrict__ out) {
    __shared__ double rp[256], rd[256];
    int t = threadIdx.x;
    double sp = 0.0, sd = 0.0;
    for (int i = t; i < NBLK; i += 256) { sp += g_phys[i]; sd += g_data[i]; }
    rp[t] = sp; rd[t] = sd;
    __syncthreads();
    for (int s = 128; s > 0; s >>= 1) {
        if (t < s) { rp[t] += rp[t + s]; rd[t] += rd[t + s]; }
        __syncthreads();
    }
    if (t == 0) {
        double r0 = (double)up[1] - (double)up[0];    // m = 0 residual: u_t[0] - 0
        double phys = (rp[0] + r0 * r0) / (double)MTOT;
        double data = rd[0] / (double)MTOT;
        out[0] = (float)(data + 0.1 * phys);
        out[1] = (float)data;
        out[2] = (float)phys;
    }
}

extern "C" void kernel_launch(void* const* d_in, const int* in_sizes, int n_in,
                              void* d_out, int out_size)
{
    const float* up  = (const float*)d_in[0];  // u_pred
    const float* utr = (const float*)d_in[1];  // u_true
    (void)in_sizes; (void)n_in; (void)out_size;

    // coef = sqrt(M-1)/Gamma(1.5); fold the 1/N of the fwd+inv FFT product in here.
    double coefN = sqrt((double)(MTOT - 1)) / 0.886226925452758013649083741670572
                   / (double)NF;

    k_tw<<<128, 128>>>();
    k1_pack_fft<<<NBLK, NTHR>>>(up, utr);
    k2_fftb<1><<<NBLK, NTHR>>>();
    k3_core<<<8193, NTHR>>>();
    k2_fftb<0><<<65 * 64, NTHR>>>();           // only c' <= 64 needed (Hermitian)
    k5_inv_epi<<<NBLK, NTHR>>>(up, (float)coefN);
    k_fin<<<1, 256>>>(up, (float*)d_out);
}

// round 15
// speedup vs baseline: 5.3135x; 1.0680x over previous
#include <cuda_runtime.h>
#include <math.h>

// FFT size N = 2^25 = FA * FB * FC, position n = a + FA*b + AB*c
#define LN   25
#define NF   (1 << LN)
#define LA   11
#define FA   (1 << LA)          // 2048
#define LB   7
#define FB   (1 << LB)          // 128
#define LC   7
#define FC   (1 << LC)          // 128
#define AB   (FA * FB)          // 262144
#define GT   32                 // tile width (consecutive fast-dim elements)
#define NTHR 256

#define MTOT (1 << 24)          // problem size B*N = 2^24
#define NBLK (AB / GT)          // 8192 blocks for K1/K5

// XOR swizzle for k3 smem: flips element bits [1:4) from bits [4:7).
// Bijective, preserves 2-element (16B) alignment -> float4-safe.
#define SW(p) ((p) ^ ((((p) >> 4) & 7) << 1))

// 256 MB spectral work buffer + twiddle tables + partials (no runtime allocation)
__device__ float2 g_Z[NF];
__device__ float2 g_W16384[16384];  // W_16384^m (full)
__device__ float2 g_W2048[2048];    // W_2048^m  (full)
__device__ float2 g_W128[128];      // W_128^m   (full)
__device__ float2 g_Wlo[4096];      // W_N^j,        j < 4096
__device__ float2 g_Whi[8192];      // W_N^{4096 j}, j < 8192
__device__ double g_data[NBLK];
__device__ double g_phys[NBLK];

__device__ __forceinline__ float2 cadd(float2 a, float2 b) { return make_float2(a.x + b.x, a.y + b.y); }
__device__ __forceinline__ float2 csub(float2 a, float2 b) { return make_float2(a.x - b.x, a.y - b.y); }
__device__ __forceinline__ float2 cmul(float2 a, float2 b) {
    return make_float2(fmaf(a.x, b.x, -a.y * b.y), fmaf(a.x, b.y, a.y * b.x));
}
// multiply by -i (sgn=+1, forward) or +i (sgn=-1, inverse)
__device__ __forceinline__ float2 crot(float2 a, float sgn) { return make_float2(sgn * a.y, -sgn * a.x); }

// 8-point DFT in registers, natural-order outputs. sgn=+1 fwd, -1 inverse (unnormalized).
__device__ __forceinline__ void dft8(float2* u, float sgn) {
    const float C = 0.70710678118654752440f;
    float2 t0 = cadd(u[0], u[4]), t1 = cadd(u[1], u[5]);
    float2 t2 = cadd(u[2], u[6]), t3 = cadd(u[3], u[7]);
    float2 m4 = csub(u[0], u[4]), m5 = csub(u[1], u[5]);
    float2 m6 = csub(u[2], u[6]), m7 = csub(u[3], u[7]);
    float2 t4 = m4;
    float2 t5 = cmul(m5, make_float2(C, -sgn * C));    // W8^1
    float2 t6 = crot(m6, sgn);                         // W8^2
    float2 t7 = cmul(m7, make_float2(-C, -sgn * C));   // W8^3
    float2 s0 = cadd(t0, t2), s2 = csub(t0, t2);
    float2 s1 = cadd(t1, t3), s3 = crot(csub(t1, t3), sgn);
    float2 r0 = cadd(t4, t6), r2 = csub(t4, t6);
    float2 r1 = cadd(t5, t7), r3 = crot(csub(t5, t7), sgn);
    u[0] = cadd(s0, s1); u[4] = csub(s0, s1);
    u[2] = cadd(s2, s3); u[6] = csub(s2, s3);
    u[1] = cadd(r0, r1); u[5] = csub(r0, r1);
    u[3] = cadd(r2, r3); u[7] = csub(r2, r3);
}

// 8-point DFT with inputs 4..7 known to be zero (k1 zero-padding). In: u[0..3]; out: u[0..7].
__device__ __forceinline__ void dft8h(float2* u, float sgn) {
    const float C = 0.70710678118654752440f;
    float2 t0 = u[0], t1 = u[1], t2 = u[2], t3 = u[3];
    float2 t4 = u[0];
    float2 t5 = cmul(u[1], make_float2(C, -sgn * C));
    float2 t6 = crot(u[2], sgn);
    float2 t7 = cmul(u[3], make_float2(-C, -sgn * C));
    float2 s0 = cadd(t0, t2), s2 = csub(t0, t2);
    float2 s1 = cadd(t1, t3), s3 = crot(csub(t1, t3), sgn);
    float2 r0 = cadd(t4, t6), r2 = csub(t4, t6);
    float2 r1 = cadd(t5, t7), r3 = crot(csub(t5, t7), sgn);
    u[0] = cadd(s0, s1); u[4] = csub(s0, s1);
    u[2] = cadd(s2, s3); u[6] = csub(s2, s3);
    u[1] = cadd(r0, r1); u[5] = csub(r0, r1);
    u[3] = cadd(r2, r3); u[7] = csub(r2, r3);
}

// 4-point DFT in registers, natural order.
__device__ __forceinline__ void dft4(float2* u, float sgn) {
    float2 a0 = cadd(u[0], u[2]), b0 = csub(u[0], u[2]);
    float2 a1 = cadd(u[1], u[3]), b1 = crot(csub(u[1], u[3]), sgn);
    u[0] = cadd(a0, a1); u[2] = csub(a0, a1);
    u[1] = cadd(b0, b1); u[3] = csub(b0, b1);
}

// apply w^k (k=1..7) to u[1..7] via cmul chain from a single loaded w1
__device__ __forceinline__ void twiddle_chain8(float2* u, float2 w1) {
    float2 w = w1;
    u[1] = cmul(u[1], w);
#pragma unroll
    for (int k = 2; k < 8; k++) { w = cmul(w, w1); u[k] = cmul(u[k], w); }
}

// digit-reversal maps
// 128 = 8*8*2 DIF: position p -> natural frequency
__device__ __forceinline__ int f128(int p) {
    return (p >> 4) + (((p >> 1) & 7) << 3) + ((p & 1) << 6);
}
// 2048 = 8*8*8*4 DIF: natural frequency k -> scrambled position
__device__ __forceinline__ int pos2048(int k) {
    return ((k & 7) << 8) + (((k >> 3) & 7) << 5) + (((k >> 6) & 7) << 2) + (k >> 9);
}

// ---------------------------------------------------------------- twiddle init
__global__ void k_tw() {
    int idx = blockIdx.x * 128 + threadIdx.x;   // 128 blocks * 128 = 16384
    const double P2 = 6.283185307179586476925286766559;
    if (idx < 16384) { double a = -P2 * idx / 16384.0;    g_W16384[idx] = make_float2((float)cos(a), (float)sin(a)); }
    if (idx < 8192)  { double a = -P2 * idx / 8192.0;     g_Whi[idx]    = make_float2((float)cos(a), (float)sin(a)); }
    if (idx < 4096)  { double a = -P2 * idx / (double)NF; g_Wlo[idx]    = make_float2((float)cos(a), (float)sin(a)); }
    if (idx < 2048)  { double a = -P2 * idx / 2048.0;     g_W2048[idx]  = make_float2((float)cos(a), (float)sin(a)); }
    if (idx < 128)   { double a = -P2 * idx / 128.0;      g_W128[idx]   = make_float2((float)cos(a), (float)sin(a)); }
}

// ------------------------------------- K1: pack Z = du + i*b, FFT over c, data loss
// Input rows c >= 64 are structurally zero (n >= MTOT) -> half-input stage 1.
// Stage 2 writes directly to global (register->STG, coalesced per warp).
__global__ __launch_bounds__(NTHR)
void k1_pack_fft(const float* __restrict__ up, const float* __restrict__ utr) {
    __shared__ float2 tile[FC][GT + 1];
    __shared__ double red[NTHR];
    const int t   = threadIdx.x;
    const int ab0 = blockIdx.x * GT;

    // load rows c < 64 only, float4-vectorized (4 g per thread); 2 iterations unrolled
    float acc = 0.f;
#pragma unroll
    for (int i = t; i < (GT / 4) * 64; i += NTHR) {      // 512 items
        int c  = i >> 3;
        int gq = (i & 7) << 2;
        int n  = ab0 + gq + AB * c;                      // n+3 < MTOT guaranteed (c<64)
        float4 a4 = *reinterpret_cast<const float4*>(up + n);
        float4 b4 = *reinterpret_cast<const float4*>(utr + n);
        float d0 = a4.x - b4.x, d1 = a4.y - b4.y, d2 = a4.z - b4.z, d3 = a4.w - b4.w;
        acc = fmaf(d0, d0, acc); acc = fmaf(d1, d1, acc);
        acc = fmaf(d2, d2, acc); acc = fmaf(d3, d3, acc);
        float unext = (n + 4 < MTOT) ? __ldg(up + n + 4) : 0.f;
        float du0 = a4.y - a4.x, du1 = a4.z - a4.y, du2 = a4.w - a4.z, du3 = unext - a4.w;
        // EXACT replica of the reference fp32 weights (incl. cancellation noise).
        // Explicit 5-sqrt CSE: adjacent weights share endpoints.
        float s0 = __fsqrt_rn((float)n);
        float s1 = __fsqrt_rn((float)(n + 1));
        float s2 = __fsqrt_rn((float)(n + 2));
        float s3 = __fsqrt_rn((float)(n + 3));
        float s4 = __fsqrt_rn((float)(n + 4));
        float bw0 = s1 - s0, bw1 = s2 - s1, bw2 = s3 - s2, bw3 = s4 - s3;
        if (n + 3 >= MTOT - 1) {                          // only last elements of last block
            if (n + 0 >= MTOT - 1) { du0 = 0.f; bw0 = 0.f; }
            if (n + 1 >= MTOT - 1) { du1 = 0.f; bw1 = 0.f; }
            if (n + 2 >= MTOT - 1) { du2 = 0.f; bw2 = 0.f; }
            du3 = 0.f; bw3 = 0.f;
        }
        tile[c][gq + 0] = make_float2(du0, bw0);
        tile[c][gq + 1] = make_float2(du1, bw1);
        tile[c][gq + 2] = make_float2(du2, bw2);
        tile[c][gq + 3] = make_float2(du3, bw3);
    }
    __syncthreads();

    // stage 1 with zero top half: reads rows j+16k for k<4 (all < 64); 2 iters unrolled
#pragma unroll
    for (int q = t; q < 512; q += NTHR) {
        int g = q & 31, j = q >> 5;
        float2 u[8];
#pragma unroll
        for (int k = 0; k < 4; k++) u[k] = tile[j + (k << 4)][g];
        dft8h(u, 1.f);
        float2 w1 = g_W128[j];
        twiddle_chain8(u, w1);
#pragma unroll
        for (int k = 0; k < 8; k++) tile[j + (k << 4)][g] = u[k];
    }
    __syncthreads();

    // stage 2 in registers + DIRECT global store (digit-reversal in slab index)
    {
        int g = t & 31, m = t >> 5;
        int base = m << 4;
        float2 e0[8], e1[8];
#pragma unroll
        for (int k = 0; k < 8; k++) {
            e0[k] = tile[base + (k << 1)][g];
            e1[k] = tile[base + (k << 1) + 1][g];
        }
        dft8(e0, 1.f); dft8(e1, 1.f);
#pragma unroll
        for (int k = 1; k < 8; k++) e1[k] = cmul(e1[k], g_W128[k << 3]);   // W16^k
#pragma unroll
        for (int k = 0; k < 8; k++) {
            int p0 = base + (k << 1), p1 = p0 + 1;
            g_Z[ab0 + g + AB * f128(p0)] = cadd(e0[k], e1[k]);
            g_Z[ab0 + g + AB * f128(p1)] = csub(e0[k], e1[k]);
        }
    }

    red[t] = (double)acc;
    __syncthreads();
    for (int s = NTHR / 2; s > 0; s >>= 1) { if (t < s) red[t] += red[t + s]; __syncthreads(); }
    if (t == 0) g_data[blockIdx.x] = red[0];
}

// ---------------------- K2/K4: FFT over b (stride FA), twiddle W_16384^{b c'}
// Stage 1 loads DIRECTLY from global (coalesced 256B rows per warp) with
// register pre-twiddle; stage 2 stores DIRECTLY to global with post-twiddle.
// Inverse (FWD=0) is launched with grid 65*64 only: the post-k4 intermediate is
// c'-Hermitian (conv is real), so only c' in [0,64] is ever consumed by K5.
template<int FWD>
__global__ __launch_bounds__(NTHR)
void k2_fftb() {
    __shared__ float2 tile[FB][GT + 1];
    const int t  = threadIdx.x;
    const int cp = blockIdx.x >> 6;             // c' ; FA/GT = 64
    const int a0 = (blockIdx.x & 63) * GT;
    const float sgn = FWD ? 1.f : -1.f;

    // stage 1: global -> registers -> dft8 -> smem; 2 iterations unrolled (16 LDGs in flight)
#pragma unroll
    for (int q = t; q < 512; q += NTHR) {
        int g = q & 31, j = q >> 5;
        float2 u[8];
#pragma unroll
        for (int k = 0; k < 8; k++) {
            int b = j + (k << 4);
            float2 v = g_Z[a0 + g + FA * b + AB * cp];
            if (FWD) v = cmul(v, g_W16384[b * cp]);       // pre-twiddle (uniform/row)
            u[k] = v;
        }
        dft8(u, sgn);
        float2 w1 = g_W128[j]; w1.y *= sgn;
        twiddle_chain8(u, w1);
#pragma unroll
        for (int k = 0; k < 8; k++) tile[j + (k << 4)][g] = u[k];
    }
    __syncthreads();

    // stage 2: smem -> registers -> 16-pt -> DIRECT global store
    {
        int g = t & 31, m = t >> 5;
        int base = m << 4;
        float2 e0[8], e1[8];
#pragma unroll
        for (int k = 0; k < 8; k++) {
            e0[k] = tile[base + (k << 1)][g];
            e1[k] = tile[base + (k << 1) + 1][g];
        }
        dft8(e0, sgn); dft8(e1, sgn);
#pragma unroll
        for (int k = 1; k < 8; k++) {
            float2 w = g_W128[k << 3]; w.y *= sgn;        // W16^k
            e1[k] = cmul(e1[k], w);
        }
#pragma unroll
        for (int k = 0; k < 8; k++) {
            int p0 = base + (k << 1), p1 = p0 + 1;
            int bb0 = f128(p0), bb1 = f128(p1);
            float2 v0 = cadd(e0[k], e1[k]);
            float2 v1 = csub(e0[k], e1[k]);
            if (!FWD) {                                    // post-twiddle (uniform/row)
                float2 w0 = g_W16384[bb0 * cp]; w0.y = -w0.y;
                float2 w1 = g_W16384[bb1 * cp]; w1.y = -w1.y;
                v0 = cmul(v0, w0); v1 = cmul(v1, w1);
            }
            g_Z[a0 + g + FA * bb0 + AB * cp] = v0;
            g_Z[a0 + g + FA * bb1 + AB * cp] = v1;
        }
    }
}

// -------- K3 stage helpers: 2048 = 8*8*8*4, XOR-swizzled smem layout SW()
__device__ __forceinline__ void k3_r8(float2 (*sm)[FA], int nrow, int t,
                                      int ls, int tmul, int inv) {
    const int s   = 1 << ls;
    const int tot = nrow << 8;      // 256 butterflies per row
    for (int q = t; q < tot; q += NTHR) {
        int row = q >> 8, qq = q & 255;
        int j = qq & (s - 1), m = qq >> ls;
        int base = (m << (ls + 3)) + j;
        float2 u[8];
#pragma unroll
        for (int k = 0; k < 8; k++) u[k] = sm[row][SW(base + (k << ls))];
        float2 w1 = g_W2048[tmul * j];          // single coalesced twiddle load
        if (!inv) {
            dft8(u, 1.f);
            twiddle_chain8(u, w1);
        } else {
            // DIT inverse: conj twiddle BEFORE inverse DFT8
            w1.y = -w1.y;
            twiddle_chain8(u, w1);
            dft8(u, -1.f);
        }
#pragma unroll
        for (int k = 0; k < 8; k++) sm[row][SW(base + (k << ls))] = u[k];
    }
    __syncthreads();
}

// radix-4 span-1 (kept for the h==0 block's unfused path)
__device__ __forceinline__ void k3_r4(float2 (*sm)[FA], int nrow, int t, float sgn) {
    const int tot = nrow << 9;      // 512 quads per row
    for (int q = t; q < tot; q += NTHR) {
        int row = q >> 9, b = (q & 511) << 2;
        float2* rowp = sm[row];
        float4 lo = *reinterpret_cast<const float4*>(&rowp[SW(b)]);
        float4 hi = *reinterpret_cast<const float4*>(&rowp[SW(b + 2)]);
        float2 u[4] = { make_float2(lo.x, lo.y), make_float2(lo.z, lo.w),
                        make_float2(hi.x, hi.y), make_float2(hi.z, hi.w) };
        dft4(u, sgn);
        *reinterpret_cast<float4*>(&rowp[SW(b)])     = make_float4(u[0].x, u[0].y, u[1].x, u[1].y);
        *reinterpret_cast<float4*>(&rowp[SW(b + 2)]) = make_float4(u[2].x, u[2].y, u[3].x, u[3].y);
    }
    __syncthreads();
}

__device__ __forceinline__ float2 herm_P(float2 z1, float2 z2) {
    // DU = (z1 + conj z2)/2 ; B = -i/2 * (z1 - conj z2) ; P = DU*B
    float2 du = make_float2(0.5f * (z1.x + z2.x), 0.5f * (z1.y - z2.y));
    float2 bv = make_float2(0.5f * (z1.y + z2.y), -0.5f * (z1.x - z2.x));
    return cmul(du, bv);
}

// -------- K3: fwd DIF over a (+twiddle), pointwise in scrambled domain, inverse DIT
// Compact grid: 8193 blocks, every block active (pair enumerated in closed form).
// Pairing identity: pos2048(2047 - f) == 2047 - pos2048(f)  (all digits complement)
// -> partner of POSITION p is 2047 - p; quad w pairs with quad 511 - w, elem e <-> 3-e.
// Fused endpoints: the span-256 FFT stages are merged with the global
// load+pre-twiddle (forward) and post-twiddle+store (inverse) — per butterfly
// the 8 touched elements are 8 fully-coalesced 256B global rows per warp.
// Middle (r4 fwd + pairing + r4 inv) fused in registers except idx==0.
// Output chunks with c' > 64 are dead downstream -> skip row1 inverse + store.
__global__ __launch_bounds__(NTHR)
void k3_core() {
    __shared__ __align__(16) float2 sm[2][FA];   // 32 KB, XOR-swizzled
    const int t   = threadIdx.x;
    const int idx = blockIdx.x;
    int b1, c1;
    if (idx < 65)       { c1 = 0;  b1 = idx; }
    else if (idx < 129) { c1 = 64; b1 = idx - 65; }
    else                { int r = idx - 129; c1 = 1 + (r >> 7); b1 = r & 127; }
    const int h1 = b1 + (c1 << LB);
    int h2;
    if (c1 > 0)      h2 = (FB - 1 - b1) + ((FC - c1) << LB);
    else if (b1 > 0) h2 = FB - b1;
    else             h2 = 0;
    const bool self = (h1 == h2);
    const int  nrow = self ? 1 : 2;
    const int  b2 = h2 & (FB - 1), c2 = h2 >> LB;
    const int  hk1 = c1 + FC * b1;             // frequency weight c' + FC*b'
    const int  hk2 = c2 + FC * b2;
    const bool keep1 = (c2 <= 64);             // row1 consumed downstream?
    const int  nrow_inv = keep1 ? nrow : 1;    // rows needing inverse transform

    // FUSED fwd stage 1 (span 256): global load + pre-twiddle W_N^{a*hk} + dft8 + STS.
    // Elements a = j + k*256; lanes have consecutive j -> 8 coalesced 256B rows/warp.
    for (int q = t; q < (nrow << 8); q += NTHR) {
        int row = q >> 8, j = q & 255;
        const int chunk = row ? h2 : h1;
        const int hk    = row ? hk2 : hk1;
        float2 u[8];
#pragma unroll
        for (int k = 0; k < 8; k++) {
            int a = j + (k << 8);
            int e = a * hk;                               // < 2^25, no mod needed
            float2 w = cmul(g_Whi[e >> 12], g_Wlo[e & 4095]);
            u[k] = cmul(g_Z[chunk * FA + a], w);
        }
        dft8(u, 1.f);
        twiddle_chain8(u, g_W2048[j]);                    // stage twiddle (tmul=1)
#pragma unroll
        for (int k = 0; k < 8; k++) sm[row][SW(j + (k << 8))] = u[k];
    }
    __syncthreads();

    // remaining forward DIF radix-8 stages
    k3_r8(sm, nrow, t, 5, 8,  0);   // sub-len 256,  span 32
    k3_r8(sm, nrow, t, 2, 64, 0);   // sub-len 32,   span 4

    if (idx == 0) {
        // h == 0: unfused path (partner f2 = (FA - f1) mod FA)
        k3_r4(sm, nrow, t, 1.f);
        for (int a1 = t; a1 <= FA / 2; a1 += NTHR) {
            if (a1 == 0 || a1 == FA / 2) {
                int p = pos2048(a1);
                float2 z = sm[0][SW(p)];
                sm[0][SW(p)] = make_float2(z.x * z.y, 0.f);   // DU=Re(z), B=Im(z)
            } else {
                int p1 = pos2048(a1), p2 = pos2048(FA - a1);
                float2 z1 = sm[0][SW(p1)];
                float2 z2 = sm[0][SW(p2)];
                float2 P  = herm_P(z1, z2);
                sm[0][SW(p1)] = P;
                sm[0][SW(p2)] = make_float2(P.x, -P.y);
            }
        }
        __syncthreads();
        k3_r4(sm, nrow, t, -1.f);
    } else {
        // fused middle: r4 fwd + Hermitian pairing + r4 inv, one register pass
        const int ntask = self ? 256 : 512;
        for (int w = t; w < ntask; w += NTHR) {
            float2* rA = sm[0];
            float2* rB = self ? sm[0] : sm[1];
            const int ba = w << 2;
            const int bb = (511 - w) << 2;
            float4 alo = *reinterpret_cast<const float4*>(&rA[SW(ba)]);
            float4 ahi = *reinterpret_cast<const float4*>(&rA[SW(ba + 2)]);
            float4 blo = *reinterpret_cast<const float4*>(&rB[SW(bb)]);
            float4 bhi = *reinterpret_cast<const float4*>(&rB[SW(bb + 2)]);
            float2 uA[4] = { make_float2(alo.x, alo.y), make_float2(alo.z, alo.w),
                             make_float2(ahi.x, ahi.y), make_float2(ahi.z, ahi.w) };
            float2 uB[4] = { make_float2(blo.x, blo.y), make_float2(blo.z, blo.w),
                             make_float2(bhi.x, bhi.y), make_float2(bhi.z, bhi.w) };
            dft4(uA, 1.f); dft4(uB, 1.f);
#pragma unroll
            for (int e = 0; e < 4; e++) {
                // partner of position ba+e is bb+(3-e) (= 2047 - (ba+e))
                float2 P = herm_P(uA[e], uB[3 - e]);
                uA[e]     = P;
                uB[3 - e] = make_float2(P.x, -P.y);
            }
            dft4(uA, -1.f);
            *reinterpret_cast<float4*>(&rA[SW(ba)])     = make_float4(uA[0].x, uA[0].y, uA[1].x, uA[1].y);
            *reinterpret_cast<float4*>(&rA[SW(ba + 2)]) = make_float4(uA[2].x, uA[2].y, uA[3].x, uA[3].y);
            if (self || keep1) {               // row1 (rB) consumed downstream?
                dft4(uB, -1.f);
                *reinterpret_cast<float4*>(&rB[SW(bb)])     = make_float4(uB[0].x, uB[0].y, uB[1].x, uB[1].y);
                *reinterpret_cast<float4*>(&rB[SW(bb + 2)]) = make_float4(uB[2].x, uB[2].y, uB[3].x, uB[3].y);
            }
        }
        __syncthreads();
    }

    // inverse DIT radix-8 stages (mirror order, conj twiddles), live rows only
    k3_r8(sm, nrow_inv, t, 2, 64, 1);
    k3_r8(sm, nrow_inv, t, 5, 8,  1);

    // FUSED last inverse stage (span 256) + post-twiddle conj(W_N^{a*hk}) + STG.
    for (int q = t; q < (nrow_inv << 8); q += NTHR) {
        int row = q >> 8, j = q & 255;
        const int chunk = row ? h2 : h1;
        const int hk    = row ? hk2 : hk1;
        float2 u[8];
#pragma unroll
        for (int k = 0; k < 8; k++) u[k] = sm[row][SW(j + (k << 8))];
        float2 w1 = g_W2048[j]; w1.y = -w1.y;             // conj stage twiddle
        twiddle_chain8(u, w1);
        dft8(u, -1.f);
#pragma unroll
        for (int k = 0; k < 8; k++) {
            int a = j + (k << 8);
            int e = a * hk;
            float2 w = cmul(g_Whi[e >> 12], g_Wlo[e & 4095]);
            w.y = -w.y;
            g_Z[chunk * FA + a] = cmul(u[k], w);
        }
    }
}

// -------- K5: inverse FFT over c' with stage-2 fused into the physics epilogue.
// Stage 1 reads DIRECTLY from global: slabs c' in [0,64] as stored, rows
// 65..127 as conj(slab 128-row) (c'-Hermitian symmetry; 2nd touch is L1-hot).
// Only even positions p (c = f128(p) < 64) are ever needed -> even half in regs.
__global__ __launch_bounds__(NTHR)
void k5_inv_epi(const float* __restrict__ up, float coefN) {
    __shared__ float2 tile[FC][GT + 1];
    __shared__ double red[NTHR];
    const int t   = threadIdx.x;
    const int ab0 = blockIdx.x * GT;

    // stage 1: global (+mirror conj) -> registers -> inverse dft8 -> smem; 2 iters unrolled
#pragma unroll
    for (int q = t; q < 512; q += NTHR) {
        int g = q & 31, j = q >> 5;
        float2 u[8];
#pragma unroll
        for (int k = 0; k < 8; k++) {
            int row = j + (k << 4);
            float2 v;
            if (row <= 64) {
                v = g_Z[ab0 + g + AB * row];
            } else {
                v = g_Z[ab0 + g + AB * (128 - row)];
                v.y = -v.y;
            }
            u[k] = v;
        }
        dft8(u, -1.f);
        float2 w1 = g_W128[j]; w1.y = -w1.y;
        twiddle_chain8(u, w1);
#pragma unroll
        for (int k = 0; k < 8; k++) tile[j + (k << 4)][g] = u[k];
    }
    __syncthreads();

    // fused stage 2 (even outputs only) + epilogue
    float acc = 0.f;
    {
        int g = t & 31, m = t >> 5;            // m in [0,8)
        int base = m << 4;
        float2 e0[8], e1[8];
#pragma unroll
        for (int k = 0; k < 8; k++) {
            e0[k] = tile[base + (k << 1)][g];
            e1[k] = tile[base + (k << 1) + 1][g];
        }
        dft8(e0, -1.f); dft8(e1, -1.f);
#pragma unroll
        for (int k = 1; k < 8; k++) {
            float2 w = g_W128[k << 3]; w.y = -w.y;   // conj W16^k
            e1[k] = cmul(e1[k], w);
        }
#pragma unroll
        for (int k = 0; k < 8; k++) {
            float convr = e0[k].x + e1[k].x;          // even output, real part
            int c = m + (k << 3);                     // f128(16m + 2k) = m + 8k  (< 64)
            int n = ab0 + g + AB * c;                 // conv index
            int mres = n + 1;                         // frac[mres] = coef*conv[mres-1]
            if (mres < MTOT) {
                float um = __ldg(up + mres);
                float ut = 0.f;
                if ((mres & 16383) != 16383) ut = __ldg(up + mres + 1) - um;  // last col: u_t=0
                float r = ut - coefN * convr;
                acc = fmaf(r, r, acc);
            }
        }
    }

    red[t] = (double)acc;
    __syncthreads();
    for (int s = NTHR / 2; s > 0; s >>= 1) { if (t < s) red[t] += red[t + s]; __syncthreads(); }
    if (t == 0) g_phys[blockIdx.x] = red[0];
}

// -------- finalize
__global__ void k_fin(const float* __restrict__ up, float* __restrict__ out) {
    __shared__ double rp[256], rd[256];
    int t = threadIdx.x;
    double sp = 0.0, sd = 0.0;
    for (int i = t; i < NBLK; i += 256) { sp += g_phys[i]; sd += g_data[i]; }
    rp[t] = sp; rd[t] = sd;
    __syncthreads();
    for (int s = 128; s > 0; s >>= 1) {
        if (t < s) { rp[t] += rp[t + s]; rd[t] += rd[t + s]; }
        __syncthreads();
    }
    if (t == 0) {
        double r0 = (double)up[1] - (double)up[0];    // m = 0 residual: u_t[0] - 0
        double phys = (rp[0] + r0 * r0) / (double)MTOT;
        double data = rd[0] / (double)MTOT;
        out[0] = (float)(data + 0.1 * phys);
        out[1] = (float)data;
        out[2] = (float)phys;
    }
}

extern "C" void kernel_launch(void* const* d_in, const int* in_sizes, int n_in,
                              void* d_out, int out_size)
{
    const float* up  = (const float*)d_in[0];  // u_pred
    const float* utr = (const float*)d_in[1];  // u_true
    (void)in_sizes; (void)n_in; (void)out_size;

    // coef = sqrt(M-1)/Gamma(1.5); fold the 1/N of the fwd+inv FFT product in here.
    double coefN = sqrt((double)(MTOT - 1)) / 0.886226925452758013649083741670572
                   / (double)NF;

    k_tw<<<128, 128>>>();
    k1_pack_fft<<<NBLK, NTHR>>>(up, utr);
    k2_fftb<1><<<NBLK, NTHR>>>();
    k3_core<<<8193, NTHR>>>();
    k2_fftb<0><<<65 * 64, NTHR>>>();           // only c' <= 64 needed (Hermitian)
    k5_inv_epi<<<NBLK, NTHR>>>(up, (float)coefN);
    k_fin<<<1, 256>>>(up, (float*)d_out);
}

// round 16
// speedup vs baseline: 5.3764x; 1.0118x over previous
#include <cuda_runtime.h>
#include <math.h>

// FFT size N = 2^25 = FA * FB * FC, position n = a + FA*b + AB*c
#define LN   25
#define NF   (1 << LN)
#define LA   11
#define FA   (1 << LA)          // 2048
#define LB   7
#define FB   (1 << LB)          // 128
#define LC   7
#define FC   (1 << LC)          // 128
#define AB   (FA * FB)          // 262144
#define GT   32                 // tile width (consecutive fast-dim elements)
#define NTHR 256

#define MTOT (1 << 24)          // problem size B*N = 2^24
#define NBLK (AB / GT)          // 8192 blocks for K1/K5

// XOR swizzle for k3 smem: flips element bits [1:4) from bits [4:7).
// Bijective, preserves 2-element (16B) alignment -> float4-safe.
#define SW(p) ((p) ^ ((((p) >> 4) & 7) << 1))

// 256 MB spectral work buffer + twiddle tables + partials (no runtime allocation)
__device__ float2 g_Z[NF];
__device__ float2 g_W16384[16384];  // W_16384^m (full)
__device__ float2 g_W2048[2048];    // W_2048^m  (full)
__device__ float2 g_W128[128];      // W_128^m   (full)
__device__ float2 g_Wlo[4096];      // W_N^j,        j < 4096
__device__ float2 g_Whi[8192];      // W_N^{4096 j}, j < 8192
__device__ double g_data[NBLK];
__device__ double g_phys[NBLK];

__device__ __forceinline__ float2 cadd(float2 a, float2 b) { return make_float2(a.x + b.x, a.y + b.y); }
__device__ __forceinline__ float2 csub(float2 a, float2 b) { return make_float2(a.x - b.x, a.y - b.y); }
__device__ __forceinline__ float2 cmul(float2 a, float2 b) {
    return make_float2(fmaf(a.x, b.x, -a.y * b.y), fmaf(a.x, b.y, a.y * b.x));
}
// multiply by -i (sgn=+1, forward) or +i (sgn=-1, inverse)
__device__ __forceinline__ float2 crot(float2 a, float sgn) { return make_float2(sgn * a.y, -sgn * a.x); }

// 8-point DFT in registers, natural-order outputs. sgn=+1 fwd, -1 inverse (unnormalized).
__device__ __forceinline__ void dft8(float2* u, float sgn) {
    const float C = 0.70710678118654752440f;
    float2 t0 = cadd(u[0], u[4]), t1 = cadd(u[1], u[5]);
    float2 t2 = cadd(u[2], u[6]), t3 = cadd(u[3], u[7]);
    float2 m4 = csub(u[0], u[4]), m5 = csub(u[1], u[5]);
    float2 m6 = csub(u[2], u[6]), m7 = csub(u[3], u[7]);
    float2 t4 = m4;
    float2 t5 = cmul(m5, make_float2(C, -sgn * C));    // W8^1
    float2 t6 = crot(m6, sgn);                         // W8^2
    float2 t7 = cmul(m7, make_float2(-C, -sgn * C));   // W8^3
    float2 s0 = cadd(t0, t2), s2 = csub(t0, t2);
    float2 s1 = cadd(t1, t3), s3 = crot(csub(t1, t3), sgn);
    float2 r0 = cadd(t4, t6), r2 = csub(t4, t6);
    float2 r1 = cadd(t5, t7), r3 = crot(csub(t5, t7), sgn);
    u[0] = cadd(s0, s1); u[4] = csub(s0, s1);
    u[2] = cadd(s2, s3); u[6] = csub(s2, s3);
    u[1] = cadd(r0, r1); u[5] = csub(r0, r1);
    u[3] = cadd(r2, r3); u[7] = csub(r2, r3);
}

// 8-point DFT with inputs 4..7 known to be zero (k1 zero-padding). In: u[0..3]; out: u[0..7].
__device__ __forceinline__ void dft8h(float2* u, float sgn) {
    const float C = 0.70710678118654752440f;
    float2 t0 = u[0], t1 = u[1], t2 = u[2], t3 = u[3];
    float2 t4 = u[0];
    float2 t5 = cmul(u[1], make_float2(C, -sgn * C));
    float2 t6 = crot(u[2], sgn);
    float2 t7 = cmul(u[3], make_float2(-C, -sgn * C));
    float2 s0 = cadd(t0, t2), s2 = csub(t0, t2);
    float2 s1 = cadd(t1, t3), s3 = crot(csub(t1, t3), sgn);
    float2 r0 = cadd(t4, t6), r2 = csub(t4, t6);
    float2 r1 = cadd(t5, t7), r3 = crot(csub(t5, t7), sgn);
    u[0] = cadd(s0, s1); u[4] = csub(s0, s1);
    u[2] = cadd(s2, s3); u[6] = csub(s2, s3);
    u[1] = cadd(r0, r1); u[5] = csub(r0, r1);
    u[3] = cadd(r2, r3); u[7] = csub(r2, r3);
}

// 4-point DFT in registers, natural order.
__device__ __forceinline__ void dft4(float2* u, float sgn) {
    float2 a0 = cadd(u[0], u[2]), b0 = csub(u[0], u[2]);
    float2 a1 = cadd(u[1], u[3]), b1 = crot(csub(u[1], u[3]), sgn);
    u[0] = cadd(a0, a1); u[2] = csub(a0, a1);
    u[1] = cadd(b0, b1); u[3] = csub(b0, b1);
}

// apply w1^k (k=1..7) to u[1..7], log-depth power tree (depth 3 vs serial 6)
__device__ __forceinline__ void twiddle_chain8(float2* u, float2 w1) {
    float2 w2 = cmul(w1, w1);
    float2 w3 = cmul(w2, w1);
    float2 w4 = cmul(w2, w2);
    float2 w5 = cmul(w4, w1);
    float2 w6 = cmul(w3, w3);
    float2 w7 = cmul(w4, w3);
    u[1] = cmul(u[1], w1); u[2] = cmul(u[2], w2); u[3] = cmul(u[3], w3);
    u[4] = cmul(u[4], w4); u[5] = cmul(u[5], w5); u[6] = cmul(u[6], w6);
    u[7] = cmul(u[7], w7);
}

// digit-reversal maps
// 128 = 8*8*2 DIF: position p -> natural frequency
__device__ __forceinline__ int f128(int p) {
    return (p >> 4) + (((p >> 1) & 7) << 3) + ((p & 1) << 6);
}
// 2048 = 8*8*8*4 DIF: natural frequency k -> scrambled position
__device__ __forceinline__ int pos2048(int k) {
    return ((k & 7) << 8) + (((k >> 3) & 7) << 5) + (((k >> 6) & 7) << 2) + (k >> 9);
}

// ---------------------------------------------------------------- twiddle init
__global__ void k_tw() {
    int idx = blockIdx.x * 128 + threadIdx.x;   // 128 blocks * 128 = 16384
    const double P2 = 6.283185307179586476925286766559;
    if (idx < 16384) { double a = -P2 * idx / 16384.0;    g_W16384[idx] = make_float2((float)cos(a), (float)sin(a)); }
    if (idx < 8192)  { double a = -P2 * idx / 8192.0;     g_Whi[idx]    = make_float2((float)cos(a), (float)sin(a)); }
    if (idx < 4096)  { double a = -P2 * idx / (double)NF; g_Wlo[idx]    = make_float2((float)cos(a), (float)sin(a)); }
    if (idx < 2048)  { double a = -P2 * idx / 2048.0;     g_W2048[idx]  = make_float2((float)cos(a), (float)sin(a)); }
    if (idx < 128)   { double a = -P2 * idx / 128.0;      g_W128[idx]   = make_float2((float)cos(a), (float)sin(a)); }
}

// ------------------------------------- K1: pack Z = du + i*b, FFT over c, data loss
// Input rows c >= 64 are structurally zero (n >= MTOT) -> half-input stage 1.
// Stage 2 writes directly to global (register->STG, coalesced per warp).
__global__ __launch_bounds__(NTHR)
void k1_pack_fft(const float* __restrict__ up, const float* __restrict__ utr) {
    __shared__ float2 tile[FC][GT + 1];
    __shared__ double red[NTHR];
    const int t   = threadIdx.x;
    const int ab0 = blockIdx.x * GT;

    // load rows c < 64 only, float4-vectorized (4 g per thread); 2 iterations unrolled
    float acc = 0.f;
#pragma unroll
    for (int i = t; i < (GT / 4) * 64; i += NTHR) {      // 512 items
        int c  = i >> 3;
        int gq = (i & 7) << 2;
        int n  = ab0 + gq + AB * c;                      // n+3 < MTOT guaranteed (c<64)
        float4 a4 = *reinterpret_cast<const float4*>(up + n);
        float4 b4 = *reinterpret_cast<const float4*>(utr + n);
        float d0 = a4.x - b4.x, d1 = a4.y - b4.y, d2 = a4.z - b4.z, d3 = a4.w - b4.w;
        acc = fmaf(d0, d0, acc); acc = fmaf(d1, d1, acc);
        acc = fmaf(d2, d2, acc); acc = fmaf(d3, d3, acc);
        float unext = (n + 4 < MTOT) ? __ldg(up + n + 4) : 0.f;
        float du0 = a4.y - a4.x, du1 = a4.z - a4.y, du2 = a4.w - a4.z, du3 = unext - a4.w;
        // EXACT replica of the reference fp32 weights (incl. cancellation noise).
        // Explicit 5-sqrt CSE: adjacent weights share endpoints.
        float s0 = __fsqrt_rn((float)n);
        float s1 = __fsqrt_rn((float)(n + 1));
        float s2 = __fsqrt_rn((float)(n + 2));
        float s3 = __fsqrt_rn((float)(n + 3));
        float s4 = __fsqrt_rn((float)(n + 4));
        float bw0 = s1 - s0, bw1 = s2 - s1, bw2 = s3 - s2, bw3 = s4 - s3;
        if (n + 3 >= MTOT - 1) {                          // only last elements of last block
            if (n + 0 >= MTOT - 1) { du0 = 0.f; bw0 = 0.f; }
            if (n + 1 >= MTOT - 1) { du1 = 0.f; bw1 = 0.f; }
            if (n + 2 >= MTOT - 1) { du2 = 0.f; bw2 = 0.f; }
            du3 = 0.f; bw3 = 0.f;
        }
        tile[c][gq + 0] = make_float2(du0, bw0);
        tile[c][gq + 1] = make_float2(du1, bw1);
        tile[c][gq + 2] = make_float2(du2, bw2);
        tile[c][gq + 3] = make_float2(du3, bw3);
    }
    __syncthreads();

    // stage 1 with zero top half: reads rows j+16k for k<4 (all < 64); 2 iters unrolled
#pragma unroll
    for (int q = t; q < 512; q += NTHR) {
        int g = q & 31, j = q >> 5;
        float2 u[8];
#pragma unroll
        for (int k = 0; k < 4; k++) u[k] = tile[j + (k << 4)][g];
        dft8h(u, 1.f);
        float2 w1 = g_W128[j];
        twiddle_chain8(u, w1);
#pragma unroll
        for (int k = 0; k < 8; k++) tile[j + (k << 4)][g] = u[k];
    }
    __syncthreads();

    // stage 2 in registers + DIRECT global store (digit-reversal in slab index)
    {
        int g = t & 31, m = t >> 5;
        int base = m << 4;
        float2 e0[8], e1[8];
#pragma unroll
        for (int k = 0; k < 8; k++) {
            e0[k] = tile[base + (k << 1)][g];
            e1[k] = tile[base + (k << 1) + 1][g];
        }
        dft8(e0, 1.f); dft8(e1, 1.f);
#pragma unroll
        for (int k = 1; k < 8; k++) e1[k] = cmul(e1[k], g_W128[k << 3]);   // W16^k
#pragma unroll
        for (int k = 0; k < 8; k++) {
            int p0 = base + (k << 1), p1 = p0 + 1;
            g_Z[ab0 + g + AB * f128(p0)] = cadd(e0[k], e1[k]);
            g_Z[ab0 + g + AB * f128(p1)] = csub(e0[k], e1[k]);
        }
    }

    red[t] = (double)acc;
    __syncthreads();
    for (int s = NTHR / 2; s > 0; s >>= 1) { if (t < s) red[t] += red[t + s]; __syncthreads(); }
    if (t == 0) g_data[blockIdx.x] = red[0];
}

// ---------------------- K2/K4: FFT over b (stride FA), twiddle W_16384^{b c'}
// Stage 1: PREFETCH all 16 global loads (both j-halves), then compute; the
// forward pre-twiddle W16384[(j+16k)c'] is a geometric chain with uniform step
// W16384[16c'] (1 coalesced load + FMA chain instead of 8 scattered LDGs).
// Stage 2 stores DIRECTLY to global; inverse post-twiddle chains with uniform
// step W16384[8c'] (f128 of even/odd positions is linear in k: m+8k / m+8k+64).
// Inverse (FWD=0) runs c' in [0,64] only (c'-Hermitian symmetry, conv real).
template<int FWD>
__global__ __launch_bounds__(NTHR)
void k2_fftb() {
    __shared__ float2 tile[FB][GT + 1];
    const int t  = threadIdx.x;
    const int cp = blockIdx.x >> 6;             // c' ; FA/GT = 64
    const int a0 = (blockIdx.x & 63) * GT;
    const float sgn = FWD ? 1.f : -1.f;
    const int g  = t & 31;
    const int j0 = t >> 5;                      // j0 in [0,8), second half j0+8

    // ---- stage 1: prefetch 16 loads, then two butterflies ----
    {
        float2 v0[8], v1[8];
#pragma unroll
        for (int k = 0; k < 8; k++) v0[k] = g_Z[a0 + g + FA * (j0 + (k << 4)) + AB * cp];
#pragma unroll
        for (int k = 0; k < 8; k++) v1[k] = g_Z[a0 + g + FA * (j0 + 8 + (k << 4)) + AB * cp];

        if (FWD) {
            // pre-twiddle chain: W16384[(j+16k)cp] = W16384[j*cp] * W16384[16cp]^k
            float2 wk = g_W16384[cp << 4];      // uniform step
            float2 w = g_W16384[j0 * cp];
            v0[0] = cmul(v0[0], w);
#pragma unroll
            for (int k = 1; k < 8; k++) { w = cmul(w, wk); v0[k] = cmul(v0[k], w); }
            w = g_W16384[(j0 + 8) * cp];
            v1[0] = cmul(v1[0], w);
#pragma unroll
            for (int k = 1; k < 8; k++) { w = cmul(w, wk); v1[k] = cmul(v1[k], w); }
        }

        dft8(v0, sgn);
        { float2 w1 = g_W128[j0]; w1.y *= sgn; twiddle_chain8(v0, w1); }
#pragma unroll
        for (int k = 0; k < 8; k++) tile[j0 + (k << 4)][g] = v0[k];

        dft8(v1, sgn);
        { float2 w1 = g_W128[j0 + 8]; w1.y *= sgn; twiddle_chain8(v1, w1); }
#pragma unroll
        for (int k = 0; k < 8; k++) tile[j0 + 8 + (k << 4)][g] = v1[k];
    }
    __syncthreads();

    // ---- stage 2: smem -> registers -> 16-pt -> DIRECT global store ----
    {
        int m = t >> 5;
        int base = m << 4;
        float2 e0[8], e1[8];
#pragma unroll
        for (int k = 0; k < 8; k++) {
            e0[k] = tile[base + (k << 1)][g];
            e1[k] = tile[base + (k << 1) + 1][g];
        }
        dft8(e0, sgn); dft8(e1, sgn);
#pragma unroll
        for (int k = 1; k < 8; k++) {
            float2 w = g_W128[k << 3]; w.y *= sgn;        // W16^k
            e1[k] = cmul(e1[k], w);
        }
        if (FWD) {
#pragma unroll
            for (int k = 0; k < 8; k++) {
                int p0 = base + (k << 1), p1 = p0 + 1;
                g_Z[a0 + g + FA * f128(p0) + AB * cp] = cadd(e0[k], e1[k]);
                g_Z[a0 + g + FA * f128(p1) + AB * cp] = csub(e0[k], e1[k]);
            }
        } else {
            // post-twiddle chain: bb0 = m+8k, bb1 = m+8k+64 -> uniform step W16384[8cp]
            float2 w8 = g_W16384[cp << 3]; w8.y = -w8.y;
            float2 wa = g_W16384[m * cp];        wa.y = -wa.y;
            float2 wb = g_W16384[(m + 64) * cp]; wb.y = -wb.y;
#pragma unroll
            for (int k = 0; k < 8; k++) {
                int bb0 = m + (k << 3), bb1 = bb0 + 64;
                float2 v0 = cmul(cadd(e0[k], e1[k]), wa);
                float2 v1 = cmul(csub(e0[k], e1[k]), wb);
                g_Z[a0 + g + FA * bb0 + AB * cp] = v0;
                g_Z[a0 + g + FA * bb1 + AB * cp] = v1;
                wa = cmul(wa, w8);
                wb = cmul(wb, w8);
            }
        }
    }
}

// -------- K3 stage helpers: 2048 = 8*8*8*4, XOR-swizzled smem layout SW()
__device__ __forceinline__ void k3_r8(float2 (*sm)[FA], int nrow, int t,
                                      int ls, int tmul, int inv) {
    const int s   = 1 << ls;
    const int tot = nrow << 8;      // 256 butterflies per row
    for (int q = t; q < tot; q += NTHR) {
        int row = q >> 8, qq = q & 255;
        int j = qq & (s - 1), m = qq >> ls;
        int base = (m << (ls + 3)) + j;
        float2 u[8];
#pragma unroll
        for (int k = 0; k < 8; k++) u[k] = sm[row][SW(base + (k << ls))];
        float2 w1 = g_W2048[tmul * j];          // single coalesced twiddle load
        if (!inv) {
            dft8(u, 1.f);
            twiddle_chain8(u, w1);
        } else {
            // DIT inverse: conj twiddle BEFORE inverse DFT8
            w1.y = -w1.y;
            twiddle_chain8(u, w1);
            dft8(u, -1.f);
        }
#pragma unroll
        for (int k = 0; k < 8; k++) sm[row][SW(base + (k << ls))] = u[k];
    }
    __syncthreads();
}

// radix-4 span-1 (kept for the h==0 block's unfused path)
__device__ __forceinline__ void k3_r4(float2 (*sm)[FA], int nrow, int t, float sgn) {
    const int tot = nrow << 9;      // 512 quads per row
    for (int q = t; q < tot; q += NTHR) {
        int row = q >> 9, b = (q & 511) << 2;
        float2* rowp = sm[row];
        float4 lo = *reinterpret_cast<const float4*>(&rowp[SW(b)]);
        float4 hi = *reinterpret_cast<const float4*>(&rowp[SW(b + 2)]);
        float2 u[4] = { make_float2(lo.x, lo.y), make_float2(lo.z, lo.w),
                        make_float2(hi.x, hi.y), make_float2(hi.z, hi.w) };
        dft4(u, sgn);
        *reinterpret_cast<float4*>(&rowp[SW(b)])     = make_float4(u[0].x, u[0].y, u[1].x, u[1].y);
        *reinterpret_cast<float4*>(&rowp[SW(b + 2)]) = make_float4(u[2].x, u[2].y, u[3].x, u[3].y);
    }
    __syncthreads();
}

__device__ __forceinline__ float2 herm_P(float2 z1, float2 z2) {
    // DU = (z1 + conj z2)/2 ; B = -i/2 * (z1 - conj z2) ; P = DU*B
    float2 du = make_float2(0.5f * (z1.x + z2.x), 0.5f * (z1.y - z2.y));
    float2 bv = make_float2(0.5f * (z1.y + z2.y), -0.5f * (z1.x - z2.x));
    return cmul(du, bv);
}

// -------- K3: fwd DIF over a (+twiddle), pointwise in scrambled domain, inverse DIT
// Compact grid: 8193 blocks, every block active (pair enumerated in closed form).
// Pairing identity: pos2048(2047 - f) == 2047 - pos2048(f)  (all digits complement)
// -> partner of POSITION p is 2047 - p; quad w pairs with quad 511 - w, elem e <-> 3-e.
// Fused endpoints: the span-256 FFT stages are merged with the global
// load+pre-twiddle (forward) and post-twiddle+store (inverse) — per butterfly
// the 8 touched elements are 8 fully-coalesced 256B global rows per warp.
// Middle (r4 fwd + pairing + r4 inv) fused in registers except idx==0.
// Output chunks with c' > 64 are dead downstream -> skip row1 inverse + store.
__global__ __launch_bounds__(NTHR)
void k3_core() {
    __shared__ __align__(16) float2 sm[2][FA];   // 32 KB, XOR-swizzled
    const int t   = threadIdx.x;
    const int idx = blockIdx.x;
    int b1, c1;
    if (idx < 65)       { c1 = 0;  b1 = idx; }
    else if (idx < 129) { c1 = 64; b1 = idx - 65; }
    else                { int r = idx - 129; c1 = 1 + (r >> 7); b1 = r & 127; }
    const int h1 = b1 + (c1 << LB);
    int h2;
    if (c1 > 0)      h2 = (FB - 1 - b1) + ((FC - c1) << LB);
    else if (b1 > 0) h2 = FB - b1;
    else             h2 = 0;
    const bool self = (h1 == h2);
    const int  nrow = self ? 1 : 2;
    const int  b2 = h2 & (FB - 1), c2 = h2 >> LB;
    const int  hk1 = c1 + FC * b1;             // frequency weight c' + FC*b'
    const int  hk2 = c2 + FC * b2;
    const bool keep1 = (c2 <= 64);             // row1 consumed downstream?
    const int  nrow_inv = keep1 ? nrow : 1;    // rows needing inverse transform

    // FUSED fwd stage 1 (span 256): global load + pre-twiddle W_N^{a*hk} + dft8 + STS.
    // Elements a = j + k*256; lanes have consecutive j -> 8 coalesced 256B rows/warp.
    for (int q = t; q < (nrow << 8); q += NTHR) {
        int row = q >> 8, j = q & 255;
        const int chunk = row ? h2 : h1;
        const int hk    = row ? hk2 : hk1;
        float2 u[8];
#pragma unroll
        for (int k = 0; k < 8; k++) {
            int a = j + (k << 8);
            int e = a * hk;                               // < 2^25, no mod needed
            float2 w = cmul(g_Whi[e >> 12], g_Wlo[e & 4095]);
            u[k] = cmul(g_Z[chunk * FA + a], w);
        }
        dft8(u, 1.f);
        twiddle_chain8(u, g_W2048[j]);                    // stage twiddle (tmul=1)
#pragma unroll
        for (int k = 0; k < 8; k++) sm[row][SW(j + (k << 8))] = u[k];
    }
    __syncthreads();

    // remaining forward DIF radix-8 stages
    k3_r8(sm, nrow, t, 5, 8,  0);   // sub-len 256,  span 32
    k3_r8(sm, nrow, t, 2, 64, 0);   // sub-len 32,   span 4

    if (idx == 0) {
        // h == 0: unfused path (partner f2 = (FA - f1) mod FA)
        k3_r4(sm, nrow, t, 1.f);
        for (int a1 = t; a1 <= FA / 2; a1 += NTHR) {
            if (a1 == 0 || a1 == FA / 2) {
                int p = pos2048(a1);
                float2 z = sm[0][SW(p)];
                sm[0][SW(p)] = make_float2(z.x * z.y, 0.f);   // DU=Re(z), B=Im(z)
            } else {
                int p1 = pos2048(a1), p2 = pos2048(FA - a1);
                float2 z1 = sm[0][SW(p1)];
                float2 z2 = sm[0][SW(p2)];
                float2 P  = herm_P(z1, z2);
                sm[0][SW(p1)] = P;
                sm[0][SW(p2)] = make_float2(P.x, -P.y);
            }
        }
        __syncthreads();
        k3_r4(sm, nrow, t, -1.f);
    } else {
        // fused middle: r4 fwd + Hermitian pairing + r4 inv, one register pass
        const int ntask = self ? 256 : 512;
        for (int w = t; w < ntask; w += NTHR) {
            float2* rA = sm[0];
            float2* rB = self ? sm[0] : sm[1];
            const int ba = w << 2;
            const int bb = (511 - w) << 2;
            float4 alo = *reinterpret_cast<const float4*>(&rA[SW(ba)]);
            float4 ahi = *reinterpret_cast<const float4*>(&rA[SW(ba + 2)]);
            float4 blo = *reinterpret_cast<const float4*>(&rB[SW(bb)]);
            float4 bhi = *reinterpret_cast<const float4*>(&rB[SW(bb + 2)]);
            float2 uA[4] = { make_float2(alo.x, alo.y), make_float2(alo.z, alo.w),
                             make_float2(ahi.x, ahi.y), make_float2(ahi.z, ahi.w) };
            float2 uB[4] = { make_float2(blo.x, blo.y), make_float2(blo.z, blo.w),
                             make_float2(bhi.x, bhi.y), make_float2(bhi.z, bhi.w) };
            dft4(uA, 1.f); dft4(uB, 1.f);
#pragma unroll
            for (int e = 0; e < 4; e++) {
                // partner of position ba+e is bb+(3-e) (= 2047 - (ba+e))
                float2 P = herm_P(uA[e], uB[3 - e]);
                uA[e]     = P;
                uB[3 - e] = make_float2(P.x, -P.y);
            }
            dft4(uA, -1.f);
            *reinterpret_cast<float4*>(&rA[SW(ba)])     = make_float4(uA[0].x, uA[0].y, uA[1].x, uA[1].y);
            *reinterpret_cast<float4*>(&rA[SW(ba + 2)]) = make_float4(uA[2].x, uA[2].y, uA[3].x, uA[3].y);
            if (self || keep1) {               // row1 (rB) consumed downstream?
                dft4(uB, -1.f);
                *reinterpret_cast<float4*>(&rB[SW(bb)])     = make_float4(uB[0].x, uB[0].y, uB[1].x, uB[1].y);
                *reinterpret_cast<float4*>(&rB[SW(bb + 2)]) = make_float4(uB[2].x, uB[2].y, uB[3].x, uB[3].y);
            }
        }
        __syncthreads();
    }

    // inverse DIT radix-8 stages (mirror order, conj twiddles), live rows only
    k3_r8(sm, nrow_inv, t, 2, 64, 1);
    k3_r8(sm, nrow_inv, t, 5, 8,  1);

    // FUSED last inverse stage (span 256) + post-twiddle conj(W_N^{a*hk}) + STG.
    for (int q = t; q < (nrow_inv << 8); q += NTHR) {
        int row = q >> 8, j = q & 255;
        const int chunk = row ? h2 : h1;
        const int hk    = row ? hk2 : hk1;
        float2 u[8];
#pragma unroll
        for (int k = 0; k < 8; k++) u[k] = sm[row][SW(j + (k << 8))];
        float2 w1 = g_W2048[j]; w1.y = -w1.y;             // conj stage twiddle
        twiddle_chain8(u, w1);
        dft8(u, -1.f);
#pragma unroll
        for (int k = 0; k < 8; k++) {
            int a = j + (k << 8);
            int e = a * hk;
            float2 w = cmul(g_Whi[e >> 12], g_Wlo[e & 4095]);
            w.y = -w.y;
            g_Z[chunk * FA + a] = cmul(u[k], w);
        }
    }
}

// -------- K5: inverse FFT over c' with stage-2 fused into the physics epilogue.
// Stage 1: PREFETCH all 16 global loads (mirror-conj for rows > 64), then two
// inverse butterflies. Only even positions p (c = f128(p) < 64) are needed.
__global__ __launch_bounds__(NTHR)
void k5_inv_epi(const float* __restrict__ up, float coefN) {
    __shared__ float2 tile[FC][GT + 1];
    __shared__ double red[NTHR];
    const int t   = threadIdx.x;
    const int ab0 = blockIdx.x * GT;
    const int g   = t & 31;
    const int j0  = t >> 5;                    // [0,8), second half j0+8

    // stage 1: prefetch 16 (with mirror conj), then two butterflies
    {
        float2 v0[8], v1[8];
#pragma unroll
        for (int k = 0; k < 8; k++) {
            int row = j0 + (k << 4);
            int src = (row <= 64) ? row : (128 - row);
            v0[k] = g_Z[ab0 + g + AB * src];
            if (row > 64) v0[k].y = -v0[k].y;
        }
#pragma unroll
        for (int k = 0; k < 8; k++) {
            int row = j0 + 8 + (k << 4);
            int src = (row <= 64) ? row : (128 - row);
            v1[k] = g_Z[ab0 + g + AB * src];
            if (row > 64) v1[k].y = -v1[k].y;
        }

        dft8(v0, -1.f);
        { float2 w1 = g_W128[j0]; w1.y = -w1.y; twiddle_chain8(v0, w1); }
#pragma unroll
        for (int k = 0; k < 8; k++) tile[j0 + (k << 4)][g] = v0[k];

        dft8(v1, -1.f);
        { float2 w1 = g_W128[j0 + 8]; w1.y = -w1.y; twiddle_chain8(v1, w1); }
#pragma unroll
        for (int k = 0; k < 8; k++) tile[j0 + 8 + (k << 4)][g] = v1[k];
    }
    __syncthreads();

    // fused stage 2 (even outputs only) + epilogue
    float acc = 0.f;
    {
        int m = t >> 5;                        // m in [0,8)
        int base = m << 4;
        float2 e0[8], e1[8];
#pragma unroll
        for (int k = 0; k < 8; k++) {
            e0[k] = tile[base + (k << 1)][g];
            e1[k] = tile[base + (k << 1) + 1][g];
        }
        dft8(e0, -1.f); dft8(e1, -1.f);
#pragma unroll
        for (int k = 1; k < 8; k++) {
            float2 w = g_W128[k << 3]; w.y = -w.y;   // conj W16^k
            e1[k] = cmul(e1[k], w);
        }
#pragma unroll
        for (int k = 0; k < 8; k++) {
            float convr = e0[k].x + e1[k].x;          // even output, real part
            int c = m + (k << 3);                     // f128(16m + 2k) = m + 8k  (< 64)
            int n = ab0 + g + AB * c;                 // conv index
            int mres = n + 1;                         // frac[mres] = coef*conv[mres-1]
            if (mres < MTOT) {
                float um = __ldg(up + mres);
                float ut = 0.f;
                if ((mres & 16383) != 16383) ut = __ldg(up + mres + 1) - um;  // last col: u_t=0
                float r = ut - coefN * convr;
                acc = fmaf(r, r, acc);
            }
        }
    }

    red[t] = (double)acc;
    __syncthreads();
    for (int s = NTHR / 2; s > 0; s >>= 1) { if (t < s) red[t] += red[t + s]; __syncthreads(); }
    if (t == 0) g_phys[blockIdx.x] = red[0];
}

// -------- finalize
__global__ void k_fin(const float* __restrict__ up, float* __restrict__ out) {
    __shared__ double rp[256], rd[256];
    int t = threadIdx.x;
    double sp = 0.0, sd = 0.0;
    for (int i = t; i < NBLK; i += 256) { sp += g_phys[i]; sd += g_data[i]; }
    rp[t] = sp; rd[t] = sd;
    __syncthreads();
    for (int s = 128; s > 0; s >>= 1) {
        if (t < s) { rp[t] += rp[t + s]; rd[t] += rd[t + s]; }
        __syncthreads();
    }
    if (t == 0) {
        double r0 = (double)up[1] - (double)up[0];    // m = 0 residual: u_t[0] - 0
        double phys = (rp[0] + r0 * r0) / (double)MTOT;
        double data = rd[0] / (double)MTOT;
        out[0] = (float)(data + 0.1 * phys);
        out[1] = (float)data;
        out[2] = (float)phys;
    }
}

extern "C" void kernel_launch(void* const* d_in, const int* in_sizes, int n_in,
                              void* d_out, int out_size)
{
    const float* up  = (const float*)d_in[0];  // u_pred
    const float* utr = (const float*)d_in[1];  // u_true
    (void)in_sizes; (void)n_in; (void)out_size;

    // coef = sqrt(M-1)/Gamma(1.5); fold the 1/N of the fwd+inv FFT product in here.
    double coefN = sqrt((double)(MTOT - 1)) / 0.886226925452758013649083741670572
                   / (double)NF;

    k_tw<<<128, 128>>>();
    k1_pack_fft<<<NBLK, NTHR>>>(up, utr);
    k2_fftb<1><<<NBLK, NTHR>>>();
    k3_core<<<8193, NTHR>>>();
    k2_fftb<0><<<65 * 64, NTHR>>>();           // only c' <= 64 needed (Hermitian)
    k5_inv_epi<<<NBLK, NTHR>>>(up, (float)coefN);
    k_fin<<<1, 256>>>(up, (float*)d_out);
}